// round 7
// baseline (speedup 1.0000x reference)
#include <cuda_runtime.h>
#include <cuda_bf16.h>
#include <math.h>
#include <stdint.h>

#define E_DIM 2048
#define B_DIM 2
#define S_DIM 2048
#define R_DIM 128
#define H_DIM 16
#define D_DIM 128
#define T_DIM (S_DIM + R_DIM)   /* 2176 */
#define KCAT (3 * E_DIM)        /* 6144 */
#define ROWW 4096               /* per-token split row: H*256 bf16 */

// ---------------- scratch -----------------------------------------------------
__device__ int8_t g_wi[3][E_DIM * E_DIM];               // ternary weights s8
__device__ int8_t g_xi[B_DIM * S_DIM * E_DIM];          // int8 activations
__device__ float g_as[B_DIM * S_DIM];                   // per-token 1/s
__device__ __nv_bfloat16 g_qs[(size_t)B_DIM * S_DIM * ROWW];
__device__ __nv_bfloat16 g_ks[(size_t)B_DIM * T_DIM * ROWW];
__device__ __nv_bfloat16 g_vs[(size_t)B_DIM * T_DIM * ROWW];
__device__ __nv_bfloat16 g_acat[(size_t)B_DIM * S_DIM * KCAT];
__device__ __nv_bfloat16 g_wcat[(size_t)E_DIM * KCAT];
__device__ float g_part[3 * 1024];
__device__ float g_scales[3];

// ---------------- prep kernels ------------------------------------------------
__global__ void absmean3(const float* __restrict__ qw, const float* __restrict__ kw,
                         const float* __restrict__ vw, float* __restrict__ part,
                         int n) {
    __shared__ float red[256];
    const float* w = (blockIdx.y == 0) ? qw : (blockIdx.y == 1) ? kw : vw;
    int chunk = n / gridDim.x;
    int base = blockIdx.x * chunk;
    float s = 0.f;
    for (int i = threadIdx.x; i < chunk; i += blockDim.x) s += fabsf(w[base + i]);
    red[threadIdx.x] = s;
    __syncthreads();
    for (int off = 128; off > 0; off >>= 1) {
        if (threadIdx.x < off) red[threadIdx.x] += red[threadIdx.x + off];
        __syncthreads();
    }
    if (threadIdx.x == 0) part[blockIdx.y * 1024 + blockIdx.x] = red[0];
}

__global__ void scale_finalize(const float* __restrict__ part,
                               float* __restrict__ scales, int nblk, float inv_n) {
    __shared__ float red[256];
    const float* p = part + blockIdx.x * nblk;
    float s = 0.f;
    for (int i = threadIdx.x; i < nblk; i += blockDim.x) s += p[i];
    red[threadIdx.x] = s;
    __syncthreads();
    for (int off = 128; off > 0; off >>= 1) {
        if (threadIdx.x < off) red[threadIdx.x] += red[threadIdx.x + off];
        __syncthreads();
    }
    if (threadIdx.x == 0) scales[blockIdx.x] = fmaxf(red[0] * inv_n, 1e-5f);
}

// ternary weights as s8 {-1,0,1}
__global__ void quantw3(const float* __restrict__ qw, const float* __restrict__ kw,
                        const float* __restrict__ vw, int8_t* __restrict__ wi,
                        const float* __restrict__ scales, int n) {
    int s = blockIdx.y;
    const float* w = (s == 0) ? qw : (s == 1) ? kw : vw;
    int8_t* o = wi + (size_t)s * n;
    float sc = scales[s];
    for (int i = blockIdx.x * blockDim.x + threadIdx.x; i < n;
         i += gridDim.x * blockDim.x) {
        float q = rintf(__fdiv_rn(w[i], sc));
        q = fminf(fmaxf(q, -1.f), 1.f);
        o[i] = (int8_t)(int)q;
    }
}

// per-token absmax int8 quant -> s8 values + 1/s
__global__ void quant_act_k(const float* __restrict__ x,
                            int8_t* __restrict__ xi,
                            float* __restrict__ as_) {
    __shared__ float red[256];
    int row = blockIdx.x;
    const float* xr = x + (size_t)row * E_DIM;
    int8_t* qr = xi + (size_t)row * E_DIM;
    float m = 0.f;
    for (int i = threadIdx.x; i < E_DIM; i += blockDim.x) m = fmaxf(m, fabsf(xr[i]));
    red[threadIdx.x] = m;
    __syncthreads();
    for (int off = 128; off > 0; off >>= 1) {
        if (threadIdx.x < off)
            red[threadIdx.x] = fmaxf(red[threadIdx.x], red[threadIdx.x + off]);
        __syncthreads();
    }
    float mx = fmaxf(red[0], 1e-5f);
    float s = __fdiv_rn(127.f, mx);
    if (threadIdx.x == 0) as_[row] = __fdiv_rn(1.f, s);
    for (int i = threadIdx.x; i < E_DIM; i += blockDim.x) {
        float q = rintf(xr[i] * s);
        q = fminf(fmaxf(q, -128.f), 127.f);
        qr[i] = (int8_t)(int)q;
    }
}

__global__ void wsplit_k(const float* __restrict__ w,
                         __nv_bfloat16* __restrict__ wc) {
    int idx = blockIdx.x * blockDim.x + threadIdx.x;
    if (idx >= E_DIM * E_DIM) return;
    int r = idx / E_DIM, c = idx % E_DIM;
    float x = w[idx];
    __nv_bfloat16 h = __float2bfloat16(x);
    __nv_bfloat16 l = __float2bfloat16(x - __bfloat162float(h));
    size_t base = (size_t)r * KCAT + c;
    wc[base] = h;
    wc[base + E_DIM] = h;
    wc[base + 2 * E_DIM] = l;
}

__device__ __forceinline__ uint32_t swz(uint32_t o) { return o ^ ((o >> 3) & 0x70); }

// ---------------- int8 IMMA NT GEMM (QKV): C = (Xq @ Wq^T)*rs*ws -> split ----
// 128x128 tile, K chunk = 128 s8 (128B SW128 rows), m16n8k32.s8, 2-stage.
struct IJobs {
    const int8_t* A[6];
    const int8_t* W[6];
    __nv_bfloat16* C[6];
    const float* rs[6];
    const float* ws[6];
};

__global__ __launch_bounds__(256, 1) void igemm_nt(IJobs jobs, int M, int N, int K) {
    extern __shared__ __align__(128) char sm_raw[];
    int z = blockIdx.z;
    const int8_t* A = jobs.A[z];
    const int8_t* W = jobs.W[z];
    const float* rs = jobs.rs[z];
    const float* ws = jobs.ws[z];

    uint32_t sbase = (uint32_t)__cvta_generic_to_shared(sm_raw);
    int tid = threadIdx.x, lane = tid & 31, warp = tid >> 5;
    int wm = warp >> 1, wn = warp & 1;
    int bm = blockIdx.y * 128, bn = blockIdx.x * 128;

    const int8_t* Ag = A + (size_t)bm * K;
    const int8_t* Wg = W + (size_t)bn * K;

    int acc[2][8][4];
#pragma unroll
    for (int mf = 0; mf < 2; mf++)
#pragma unroll
        for (int nf = 0; nf < 8; nf++)
#pragma unroll
            for (int c = 0; c < 4; c++) acc[mf][nf][c] = 0;

    float4 sa[4], sw[4];
#pragma unroll
    for (int i = 0; i < 4; i++) {
        int idx = i * 256 + tid;
        int row = idx >> 3, c = idx & 7;
        sa[i] = *(const float4*)(Ag + (size_t)row * K + c * 16);
        sw[i] = *(const float4*)(Wg + (size_t)row * K + c * 16);
    }
#pragma unroll
    for (int i = 0; i < 4; i++) {
        int idx = i * 256 + tid;
        int row = idx >> 3, c = idx & 7;
        uint32_t off = swz((uint32_t)(row * 128 + c * 16));
        *(float4*)(sm_raw + off) = sa[i];
        *(float4*)(sm_raw + 16384 + off) = sw[i];
    }
    __syncthreads();

    int KT = K >> 7;  // 128 s8 per chunk
    for (int kt = 0; kt < KT; kt++) {
        int cur = kt & 1;
        if (kt + 1 < KT) {
#pragma unroll
            for (int i = 0; i < 4; i++) {
                int idx = i * 256 + tid;
                int row = idx >> 3, c = idx & 7;
                sa[i] = *(const float4*)(Ag + (size_t)row * K + (kt + 1) * 128 + c * 16);
                sw[i] = *(const float4*)(Wg + (size_t)row * K + (kt + 1) * 128 + c * 16);
            }
        }
        uint32_t abase = sbase + cur * 32768;
        uint32_t wbase = abase + 16384;
#pragma unroll
        for (int ks = 0; ks < 4; ks++) {   // k32-step = 32 bytes
            uint32_t a[2][4];
#pragma unroll
            for (int mf = 0; mf < 2; mf++) {
                int r = wm * 32 + mf * 16 + ((lane >> 3) & 1) * 8 + (lane & 7);
                uint32_t off = swz((uint32_t)(r * 128 + ks * 32 + ((lane >> 4) & 1) * 16));
                asm volatile(
                    "ldmatrix.sync.aligned.m8n8.x4.shared.b16 {%0,%1,%2,%3}, [%4];"
                    : "=r"(a[mf][0]), "=r"(a[mf][1]), "=r"(a[mf][2]), "=r"(a[mf][3])
                    : "r"(abase + off));
            }
            uint32_t b0[8], b1[8];
#pragma unroll
            for (int q = 0; q < 4; q++) {
                int r = wn * 64 + q * 16 + ((lane >> 3) & 1) * 8 + (lane & 7);
                uint32_t off = swz((uint32_t)(r * 128 + ks * 32 + ((lane >> 4) & 1) * 16));
                uint32_t r0, r1, r2, r3;
                asm volatile(
                    "ldmatrix.sync.aligned.m8n8.x4.shared.b16 {%0,%1,%2,%3}, [%4];"
                    : "=r"(r0), "=r"(r1), "=r"(r2), "=r"(r3)
                    : "r"(wbase + off));
                b0[2 * q] = r0; b0[2 * q + 1] = r1;
                b1[2 * q] = r2; b1[2 * q + 1] = r3;
            }
#pragma unroll
            for (int mf = 0; mf < 2; mf++)
#pragma unroll
                for (int nf = 0; nf < 8; nf++)
                    asm volatile(
                        "mma.sync.aligned.m16n8k32.row.col.s32.s8.s8.s32 "
                        "{%0,%1,%2,%3},{%4,%5,%6,%7},{%8,%9},{%0,%1,%2,%3};"
                        : "+r"(acc[mf][nf][0]), "+r"(acc[mf][nf][1]),
                          "+r"(acc[mf][nf][2]), "+r"(acc[mf][nf][3])
                        : "r"(a[mf][0]), "r"(a[mf][1]), "r"(a[mf][2]), "r"(a[mf][3]),
                          "r"(b0[nf]), "r"(b1[nf]));
        }
        if (kt + 1 < KT) {
            int nxt = cur ^ 1;
#pragma unroll
            for (int i = 0; i < 4; i++) {
                int idx = i * 256 + tid;
                int row = idx >> 3, c = idx & 7;
                uint32_t off = swz((uint32_t)(row * 128 + c * 16));
                *(float4*)(sm_raw + nxt * 32768 + off) = sa[i];
                *(float4*)(sm_raw + nxt * 32768 + 16384 + off) = sw[i];
            }
        }
        __syncthreads();
    }

    // epilogue: exact s32 -> scaled split bf16 [token][h][hi|lo]
    int g = lane >> 2, t = lane & 3;
    float wsv = *ws;
    __nv_bfloat16* Ob = jobs.C[z];
#pragma unroll
    for (int mf = 0; mf < 2; mf++) {
        int row0 = bm + wm * 32 + mf * 16 + g;
        float r0s = rs[row0] * wsv;
        float r1s = rs[row0 + 8] * wsv;
#pragma unroll
        for (int nf = 0; nf < 8; nf++) {
            int col = bn + wn * 64 + nf * 8 + 2 * t;
            int hh = col >> 7, d = col & 127;
            size_t i0 = (size_t)row0 * ROWW + hh * 256 + d;
            size_t i8 = (size_t)(row0 + 8) * ROWW + hh * 256 + d;
            float v0 = (float)acc[mf][nf][0] * r0s, v1 = (float)acc[mf][nf][1] * r0s;
            float v2 = (float)acc[mf][nf][2] * r1s, v3 = (float)acc[mf][nf][3] * r1s;
            __nv_bfloat162 h0 = __floats2bfloat162_rn(v0, v1);
            __nv_bfloat162 l0 = __floats2bfloat162_rn(
                v0 - __bfloat162float(h0.x), v1 - __bfloat162float(h0.y));
            __nv_bfloat162 h8 = __floats2bfloat162_rn(v2, v3);
            __nv_bfloat162 l8 = __floats2bfloat162_rn(
                v2 - __bfloat162float(h8.x), v3 - __bfloat162float(h8.y));
            *(__nv_bfloat162*)&Ob[i0] = h0;
            *(__nv_bfloat162*)&Ob[i0 + 128] = l0;
            *(__nv_bfloat162*)&Ob[i8] = h8;
            *(__nv_bfloat162*)&Ob[i8 + 128] = l8;
        }
    }
}

// ---------------- bf16 tensor-core NT GEMM (out-proj) -------------------------
struct BJobs {
    const __nv_bfloat16* A;
    const __nv_bfloat16* W;
    float* C;
    const float* bias;
};

__global__ __launch_bounds__(256, 1) void bgemm_nt(BJobs jobs, int M, int N, int K) {
    extern __shared__ __align__(128) char sm_raw[];
    const __nv_bfloat16* A = jobs.A;
    const __nv_bfloat16* W = jobs.W;
    float* C = jobs.C;

    uint32_t sbase = (uint32_t)__cvta_generic_to_shared(sm_raw);
    int tid = threadIdx.x, lane = tid & 31, warp = tid >> 5;
    int wm = warp >> 1, wn = warp & 1;
    int bm = blockIdx.y * 128, bn = blockIdx.x * 128;

    const __nv_bfloat16* Ag = A + (size_t)bm * K;
    const __nv_bfloat16* Wg = W + (size_t)bn * K;

    float acc[2][8][4];
#pragma unroll
    for (int mf = 0; mf < 2; mf++)
#pragma unroll
        for (int nf = 0; nf < 8; nf++)
#pragma unroll
            for (int c = 0; c < 4; c++) acc[mf][nf][c] = 0.f;

    float4 sa[4], sw[4];
#pragma unroll
    for (int i = 0; i < 4; i++) {
        int idx = i * 256 + tid;
        int row = idx >> 3, c = idx & 7;
        sa[i] = *(const float4*)(Ag + (size_t)row * K + c * 8);
        sw[i] = *(const float4*)(Wg + (size_t)row * K + c * 8);
    }
#pragma unroll
    for (int i = 0; i < 4; i++) {
        int idx = i * 256 + tid;
        int row = idx >> 3, c = idx & 7;
        uint32_t off = swz((uint32_t)(row * 128 + c * 16));
        *(float4*)(sm_raw + off) = sa[i];
        *(float4*)(sm_raw + 16384 + off) = sw[i];
    }
    __syncthreads();

    int KT = K >> 6;
    for (int kt = 0; kt < KT; kt++) {
        int cur = kt & 1;
        if (kt + 1 < KT) {
#pragma unroll
            for (int i = 0; i < 4; i++) {
                int idx = i * 256 + tid;
                int row = idx >> 3, c = idx & 7;
                sa[i] = *(const float4*)(Ag + (size_t)row * K + (kt + 1) * 64 + c * 8);
                sw[i] = *(const float4*)(Wg + (size_t)row * K + (kt + 1) * 64 + c * 8);
            }
        }
        uint32_t abase = sbase + cur * 32768;
        uint32_t wbase = abase + 16384;
#pragma unroll
        for (int ks = 0; ks < 4; ks++) {
            uint32_t a[2][4];
#pragma unroll
            for (int mf = 0; mf < 2; mf++) {
                int r = wm * 32 + mf * 16 + ((lane >> 3) & 1) * 8 + (lane & 7);
                uint32_t off = swz((uint32_t)(r * 128 + ks * 32 + ((lane >> 4) & 1) * 16));
                asm volatile(
                    "ldmatrix.sync.aligned.m8n8.x4.shared.b16 {%0,%1,%2,%3}, [%4];"
                    : "=r"(a[mf][0]), "=r"(a[mf][1]), "=r"(a[mf][2]), "=r"(a[mf][3])
                    : "r"(abase + off));
            }
            uint32_t b0[8], b1[8];
#pragma unroll
            for (int q = 0; q < 4; q++) {
                int r = wn * 64 + q * 16 + ((lane >> 3) & 1) * 8 + (lane & 7);
                uint32_t off = swz((uint32_t)(r * 128 + ks * 32 + ((lane >> 4) & 1) * 16));
                uint32_t r0, r1, r2, r3;
                asm volatile(
                    "ldmatrix.sync.aligned.m8n8.x4.shared.b16 {%0,%1,%2,%3}, [%4];"
                    : "=r"(r0), "=r"(r1), "=r"(r2), "=r"(r3)
                    : "r"(wbase + off));
                b0[2 * q] = r0; b0[2 * q + 1] = r1;
                b1[2 * q] = r2; b1[2 * q + 1] = r3;
            }
#pragma unroll
            for (int mf = 0; mf < 2; mf++)
#pragma unroll
                for (int nf = 0; nf < 8; nf++)
                    asm volatile(
                        "mma.sync.aligned.m16n8k16.row.col.f32.bf16.bf16.f32 "
                        "{%0,%1,%2,%3},{%4,%5,%6,%7},{%8,%9},{%0,%1,%2,%3};"
                        : "+f"(acc[mf][nf][0]), "+f"(acc[mf][nf][1]),
                          "+f"(acc[mf][nf][2]), "+f"(acc[mf][nf][3])
                        : "r"(a[mf][0]), "r"(a[mf][1]), "r"(a[mf][2]), "r"(a[mf][3]),
                          "r"(b0[nf]), "r"(b1[nf]));
        }
        if (kt + 1 < KT) {
            int nxt = cur ^ 1;
#pragma unroll
            for (int i = 0; i < 4; i++) {
                int idx = i * 256 + tid;
                int row = idx >> 3, c = idx & 7;
                uint32_t off = swz((uint32_t)(row * 128 + c * 16));
                *(float4*)(sm_raw + nxt * 32768 + off) = sa[i];
                *(float4*)(sm_raw + nxt * 32768 + 16384 + off) = sw[i];
            }
        }
        __syncthreads();
    }

    int g = lane >> 2, t = lane & 3;
    const float* bias = jobs.bias;
#pragma unroll
    for (int mf = 0; mf < 2; mf++) {
        int row0 = bm + wm * 32 + mf * 16 + g;
#pragma unroll
        for (int nf = 0; nf < 8; nf++) {
            int col = bn + wn * 64 + nf * 8 + 2 * t;
            float b0v = bias ? bias[col] : 0.f;
            float b1v = bias ? bias[col + 1] : 0.f;
            float2 v0 = make_float2(acc[mf][nf][0] + b0v, acc[mf][nf][1] + b1v);
            float2 v1 = make_float2(acc[mf][nf][2] + b0v, acc[mf][nf][3] + b1v);
            *(float2*)&C[(size_t)row0 * N + col] = v0;
            *(float2*)&C[(size_t)(row0 + 8) * N + col] = v1;
        }
    }
}

// ---------------- fp32 NT SGEMM 128x64 (rk/rv) -> split bf16 out --------------
struct GemmJobs {
    const float* A[4];
    const float* W[4];
    __nv_bfloat16* C[4];
};

__global__ __launch_bounds__(256) void sgemm_nt64(GemmJobs jobs, int M, int N, int K) {
    __shared__ __align__(16) float As[128][20];
    __shared__ __align__(16) float Ws[64][20];
    const float* A = jobs.A[blockIdx.z];
    const float* W = jobs.W[blockIdx.z];
    __nv_bfloat16* C = jobs.C[blockIdx.z];
    int tid = threadIdx.x;
    int tx = tid & 15, ty = tid >> 4;
    int bn = blockIdx.x * 64;

    float acc[8][4];
#pragma unroll
    for (int i = 0; i < 8; i++)
#pragma unroll
        for (int j = 0; j < 4; j++) acc[i][j] = 0.f;

    for (int kt = 0; kt < K; kt += 16) {
#pragma unroll
        for (int it = 0; it < 2; it++) {
            int idx = tid + it * 256;
            int row = idx >> 2, k4 = (idx & 3) * 4;
            *(float4*)&As[row][k4] =
                *(const float4*)&A[(size_t)row * K + kt + k4];
        }
        {
            int row = tid >> 2, k4 = (tid & 3) * 4;
            *(float4*)&Ws[row][k4] =
                *(const float4*)&W[(size_t)(bn + row) * K + kt + k4];
        }
        __syncthreads();
#pragma unroll
        for (int k4 = 0; k4 < 16; k4 += 4) {
            float4 a[8], b[4];
#pragma unroll
            for (int i = 0; i < 8; i++) a[i] = *(float4*)&As[ty + 16 * i][k4];
#pragma unroll
            for (int j = 0; j < 4; j++) b[j] = *(float4*)&Ws[tx + 16 * j][k4];
#pragma unroll
            for (int i = 0; i < 8; i++)
#pragma unroll
                for (int j = 0; j < 4; j++)
                    acc[i][j] += a[i].x * b[j].x + a[i].y * b[j].y +
                                 a[i].z * b[j].z + a[i].w * b[j].w;
        }
        __syncthreads();
    }
#pragma unroll
    for (int i = 0; i < 8; i++) {
        int r = ty + 16 * i;
#pragma unroll
        for (int j = 0; j < 4; j++) {
            int n = bn + tx + 16 * j;
            int hh = n >> 7, d = n & 127;
            float v = acc[i][j];
            __nv_bfloat16 h = __float2bfloat16(v);
            __nv_bfloat16 l = __float2bfloat16(v - __bfloat162float(h));
            C[(size_t)r * ROWW + hh * 256 + d] = h;
            C[(size_t)r * ROWW + hh * 256 + d + 128] = l;
        }
    }
}

// ---------------- tensor-core flash attention (pre-split, cp.async) -----------
#define ATT_Q_OFF 0
#define ATT_K_OFF 65536
#define ATT_V_OFF 131072
#define ATT_P_OFF 196608
#define ATT_SMEM 229376

__device__ __forceinline__ uint32_t sw512o(int r, int c) {
    return (uint32_t)(r * 512 + ((((c >> 3) ^ (r & 7))) << 4) + ((c & 7) << 1));
}
__device__ __forceinline__ uint32_t sw256o(int r, int c) {
    return (uint32_t)(r * 256 + ((((c >> 3) ^ (r & 7))) << 4) + ((c & 7) << 1));
}
__device__ __forceinline__ void ldsm4(uint32_t addr, uint32_t& r0, uint32_t& r1,
                                      uint32_t& r2, uint32_t& r3) {
    asm volatile("ldmatrix.sync.aligned.m8n8.x4.shared.b16 {%0,%1,%2,%3}, [%4];"
                 : "=r"(r0), "=r"(r1), "=r"(r2), "=r"(r3) : "r"(addr));
}
__device__ __forceinline__ void ldsm4t(uint32_t addr, uint32_t& r0, uint32_t& r1,
                                       uint32_t& r2, uint32_t& r3) {
    asm volatile("ldmatrix.sync.aligned.m8n8.x4.trans.shared.b16 {%0,%1,%2,%3}, [%4];"
                 : "=r"(r0), "=r"(r1), "=r"(r2), "=r"(r3) : "r"(addr));
}
__device__ __forceinline__ void cpa16g(uint32_t dst, const void* src) {
    asm volatile("cp.async.cg.shared.global [%0], [%1], 16;" :: "r"(dst), "l"(src));
}
__device__ __forceinline__ void cp_commitg() {
    asm volatile("cp.async.commit_group;" ::: "memory");
}

__global__ __launch_bounds__(256, 1) void attn_tc(const __nv_bfloat16* __restrict__ Qs,
                                                  const __nv_bfloat16* __restrict__ Ks,
                                                  const __nv_bfloat16* __restrict__ Vs,
                                                  __nv_bfloat16* __restrict__ AOcat) {
    extern __shared__ __align__(128) char smc[];
    uint32_t sb = (uint32_t)__cvta_generic_to_shared(smc);

    int tid = threadIdx.x, lane = tid & 31, w = tid >> 5;
    int g = lane >> 2, t = lane & 3;
    int q0 = blockIdx.x * 128;
    int h = blockIdx.y, b = blockIdx.z;

    const __nv_bfloat16* Qg = Qs + ((size_t)(b * S_DIM + q0) * H_DIM + h) * 256;
    const __nv_bfloat16* Kg = Ks + ((size_t)(b * T_DIM) * H_DIM + h) * 256;
    const __nv_bfloat16* Vg = Vs + ((size_t)(b * T_DIM) * H_DIM + h) * 256;

    const int NT = T_DIM / 64;  // 34

#pragma unroll
    for (int it = 0; it < 16; it++) {
        int idx = it * 256 + tid;
        int r = idx >> 5, c = (idx & 31) * 8;
        cpa16g(sb + ATT_Q_OFF + sw512o(r, c), Qg + (size_t)r * ROWW + c);
    }
#pragma unroll
    for (int it = 0; it < 8; it++) {
        int idx = it * 256 + tid;
        int r = idx >> 5, c = (idx & 31) * 8;
        cpa16g(sb + ATT_K_OFF + sw512o(r, c), Kg + (size_t)r * ROWW + c);
    }
    cp_commitg();
#pragma unroll
    for (int it = 0; it < 8; it++) {
        int idx = it * 256 + tid;
        int r = idx >> 5, ch = idx & 31;
        uint32_t dst = (ch < 16) ? sb + ATT_V_OFF + sw256o(r, ch * 8)
                                 : sb + ATT_V_OFF + sw256o(64 + r, (ch - 16) * 8);
        cpa16g(dst, Vg + (size_t)r * ROWW + ch * 8);
    }
    cp_commitg();
#pragma unroll
    for (int it = 0; it < 8; it++) {
        int idx = it * 256 + tid;
        int r = idx >> 5, c = (idx & 31) * 8;
        cpa16g(sb + ATT_K_OFF + 32768 + sw512o(r, c),
               Kg + (size_t)(64 + r) * ROWW + c);
    }
    cp_commitg();
#pragma unroll
    for (int it = 0; it < 8; it++) {
        int idx = it * 256 + tid;
        int r = idx >> 5, ch = idx & 31;
        uint32_t dst = (ch < 16) ? sb + ATT_V_OFF + 32768 + sw256o(r, ch * 8)
                                 : sb + ATT_V_OFF + 32768 + sw256o(64 + r, (ch - 16) * 8);
        cpa16g(dst, Vg + (size_t)(64 + r) * ROWW + ch * 8);
    }
    cp_commitg();

    float o[16][4];
#pragma unroll
    for (int nf = 0; nf < 16; nf++)
#pragma unroll
        for (int c = 0; c < 4; c++) o[nf][c] = 0.f;
    float m0 = -1e30f, m8 = -1e30f, l0 = 0.f, l8 = 0.f;

    const float scl = 0.08838834764831845f;
    int rg = w * 16 + g;

    for (int i = 0; i < NT; i++) {
        asm volatile("cp.async.wait_group 2;" ::: "memory");
        __syncthreads();

        uint32_t kbuf = sb + ATT_K_OFF + (i & 1) * 32768;
        uint32_t vbuf = sb + ATT_V_OFF + (i & 1) * 32768;

        float accs[8][4];
#pragma unroll
        for (int nf = 0; nf < 8; nf++)
#pragma unroll
            for (int c = 0; c < 4; c++) accs[nf][c] = 0.f;

#pragma unroll
        for (int s = 0; s < 24; s++) {
            int aoff = (s < 8) ? s * 16 : (s < 16) ? 128 + (s - 8) * 16 : (s - 16) * 16;
            int boff = (s < 8) ? s * 16 : (s < 16) ? (s - 8) * 16 : 128 + (s - 16) * 16;
            uint32_t a0, a1, a2, a3;
            {
                int ar = w * 16 + ((lane >> 3) & 1) * 8 + (lane & 7);
                int ac = aoff + ((lane >> 4) & 1) * 8;
                ldsm4(sb + ATT_Q_OFF + sw512o(ar, ac), a0, a1, a2, a3);
            }
            uint32_t b0[8], b1[8];
#pragma unroll
            for (int nb = 0; nb < 4; nb++) {
                int br = nb * 16 + ((lane >> 3) & 1) * 8 + (lane & 7);
                int bc = boff + ((lane >> 4) & 1) * 8;
                uint32_t r0, r1, r2, r3;
                ldsm4(kbuf + sw512o(br, bc), r0, r1, r2, r3);
                b0[2 * nb] = r0; b0[2 * nb + 1] = r1;
                b1[2 * nb] = r2; b1[2 * nb + 1] = r3;
            }
#pragma unroll
            for (int nf = 0; nf < 8; nf++)
                asm volatile(
                    "mma.sync.aligned.m16n8k16.row.col.f32.bf16.bf16.f32 "
                    "{%0,%1,%2,%3},{%4,%5,%6,%7},{%8,%9},{%0,%1,%2,%3};"
                    : "+f"(accs[nf][0]), "+f"(accs[nf][1]),
                      "+f"(accs[nf][2]), "+f"(accs[nf][3])
                    : "r"(a0), "r"(a1), "r"(a2), "r"(a3),
                      "r"(b0[nf]), "r"(b1[nf]));
        }

        float mx0 = -1e30f, mx8 = -1e30f;
#pragma unroll
        for (int nf = 0; nf < 8; nf++) {
            accs[nf][0] *= scl; accs[nf][1] *= scl;
            accs[nf][2] *= scl; accs[nf][3] *= scl;
            mx0 = fmaxf(mx0, fmaxf(accs[nf][0], accs[nf][1]));
            mx8 = fmaxf(mx8, fmaxf(accs[nf][2], accs[nf][3]));
        }
        mx0 = fmaxf(mx0, __shfl_xor_sync(0xffffffffu, mx0, 1));
        mx0 = fmaxf(mx0, __shfl_xor_sync(0xffffffffu, mx0, 2));
        mx8 = fmaxf(mx8, __shfl_xor_sync(0xffffffffu, mx8, 1));
        mx8 = fmaxf(mx8, __shfl_xor_sync(0xffffffffu, mx8, 2));
        float mn0 = fmaxf(m0, mx0), mn8 = fmaxf(m8, mx8);
        float al0 = __expf(m0 - mn0), al8 = __expf(m8 - mn8);
        m0 = mn0; m8 = mn8;
        float sum0 = 0.f, sum8 = 0.f;
#pragma unroll
        for (int nf = 0; nf < 8; nf++) {
            int c = nf * 8 + 2 * t;
            float p0 = __expf(accs[nf][0] - mn0);
            float p1 = __expf(accs[nf][1] - mn0);
            sum0 += p0 + p1;
            __nv_bfloat162 ph = __floats2bfloat162_rn(p0, p1);
            __nv_bfloat162 pl = __floats2bfloat162_rn(
                p0 - __bfloat162float(ph.x), p1 - __bfloat162float(ph.y));
            *(__nv_bfloat162*)(smc + ATT_P_OFF + sw256o(rg, c)) = ph;
            *(__nv_bfloat162*)(smc + ATT_P_OFF + sw256o(rg, 64 + c)) = pl;
            float p2 = __expf(accs[nf][2] - mn8);
            float p3 = __expf(accs[nf][3] - mn8);
            sum8 += p2 + p3;
            __nv_bfloat162 qh = __floats2bfloat162_rn(p2, p3);
            __nv_bfloat162 ql = __floats2bfloat162_rn(
                p2 - __bfloat162float(qh.x), p3 - __bfloat162float(qh.y));
            *(__nv_bfloat162*)(smc + ATT_P_OFF + sw256o(rg + 8, c)) = qh;
            *(__nv_bfloat162*)(smc + ATT_P_OFF + sw256o(rg + 8, 64 + c)) = ql;
        }
        sum0 += __shfl_xor_sync(0xffffffffu, sum0, 1);
        sum0 += __shfl_xor_sync(0xffffffffu, sum0, 2);
        sum8 += __shfl_xor_sync(0xffffffffu, sum8, 1);
        sum8 += __shfl_xor_sync(0xffffffffu, sum8, 2);
        l0 = l0 * al0 + sum0;
        l8 = l8 * al8 + sum8;
#pragma unroll
        for (int nf = 0; nf < 16; nf++) {
            o[nf][0] *= al0; o[nf][1] *= al0;
            o[nf][2] *= al8; o[nf][3] *= al8;
        }
        __syncwarp();

#pragma unroll
        for (int s = 0; s < 12; s++) {
            int pcol = (s < 4) ? s * 16 : (s < 8) ? 64 + (s - 4) * 16 : (s - 8) * 16;
            int vrow = (s < 4) ? s * 16 : (s < 8) ? (s - 4) * 16 : 64 + (s - 8) * 16;
            uint32_t a0, a1, a2, a3;
            {
                int ar = w * 16 + ((lane >> 3) & 1) * 8 + (lane & 7);
                int ac = pcol + ((lane >> 4) & 1) * 8;
                ldsm4(sb + ATT_P_OFF + sw256o(ar, ac), a0, a1, a2, a3);
            }
#pragma unroll
            for (int ng = 0; ng < 8; ng++) {
                int vr = vrow + ((lane >> 3) & 1) * 8 + (lane & 7);
                int vc = ng * 16 + ((lane >> 4) & 1) * 8;
                uint32_t r0, r1, r2, r3;
                ldsm4t(vbuf + sw256o(vr, vc), r0, r1, r2, r3);
                asm volatile(
                    "mma.sync.aligned.m16n8k16.row.col.f32.bf16.bf16.f32 "
                    "{%0,%1,%2,%3},{%4,%5,%6,%7},{%8,%9},{%0,%1,%2,%3};"
                    : "+f"(o[2 * ng][0]), "+f"(o[2 * ng][1]),
                      "+f"(o[2 * ng][2]), "+f"(o[2 * ng][3])
                    : "r"(a0), "r"(a1), "r"(a2), "r"(a3), "r"(r0), "r"(r1));
                asm volatile(
                    "mma.sync.aligned.m16n8k16.row.col.f32.bf16.bf16.f32 "
                    "{%0,%1,%2,%3},{%4,%5,%6,%7},{%8,%9},{%0,%1,%2,%3};"
                    : "+f"(o[2 * ng + 1][0]), "+f"(o[2 * ng + 1][1]),
                      "+f"(o[2 * ng + 1][2]), "+f"(o[2 * ng + 1][3])
                    : "r"(a0), "r"(a1), "r"(a2), "r"(a3), "r"(r2), "r"(r3));
            }
        }
        __syncthreads();

        if (i + 2 < NT) {
            int tK = (i + 2) * 64;
            uint32_t kb2 = sb + ATT_K_OFF + (i & 1) * 32768;
#pragma unroll
            for (int it = 0; it < 8; it++) {
                int idx = it * 256 + tid;
                int r = idx >> 5, c = (idx & 31) * 8;
                cpa16g(kb2 + sw512o(r, c), Kg + (size_t)(tK + r) * ROWW + c);
            }
        }
        cp_commitg();
        if (i + 2 < NT) {
            int tV = (i + 2) * 64;
            uint32_t vb2 = sb + ATT_V_OFF + (i & 1) * 32768;
#pragma unroll
            for (int it = 0; it < 8; it++) {
                int idx = it * 256 + tid;
                int r = idx >> 5, ch = idx & 31;
                uint32_t dst = (ch < 16) ? vb2 + sw256o(r, ch * 8)
                                         : vb2 + sw256o(64 + r, (ch - 16) * 8);
                cpa16g(dst, Vg + (size_t)(tV + r) * ROWW + ch * 8);
            }
        }
        cp_commitg();
    }

    {
        float li0 = __fdiv_rn(1.f, l0);
        float li8 = __fdiv_rn(1.f, l8);
        size_t grow0 = (size_t)(b * S_DIM + q0 + rg) * KCAT + h * D_DIM;
        size_t grow8 = grow0 + (size_t)8 * KCAT;
#pragma unroll
        for (int nf = 0; nf < 16; nf++) {
            int c = nf * 8 + 2 * t;
            float f0 = o[nf][0] * li0, f1 = o[nf][1] * li0;
            float f2 = o[nf][2] * li8, f3 = o[nf][3] * li8;
            __nv_bfloat162 h0 = __floats2bfloat162_rn(f0, f1);
            __nv_bfloat162 ll0 = __floats2bfloat162_rn(f0 - __bfloat162float(h0.x),
                                                       f1 - __bfloat162float(h0.y));
            __nv_bfloat162 h8 = __floats2bfloat162_rn(f2, f3);
            __nv_bfloat162 ll8 = __floats2bfloat162_rn(f2 - __bfloat162float(h8.x),
                                                       f3 - __bfloat162float(h8.y));
            *(__nv_bfloat162*)&AOcat[grow0 + c] = h0;
            *(__nv_bfloat162*)&AOcat[grow0 + E_DIM + c] = ll0;
            *(__nv_bfloat162*)&AOcat[grow0 + 2 * E_DIM + c] = h0;
            *(__nv_bfloat162*)&AOcat[grow8 + c] = h8;
            *(__nv_bfloat162*)&AOcat[grow8 + E_DIM + c] = ll8;
            *(__nv_bfloat162*)&AOcat[grow8 + 2 * E_DIM + c] = h8;
        }
    }
}

// ---------------- launcher ----------------------------------------------------
extern "C" void kernel_launch(void* const* d_in, const int* in_sizes, int n_in,
                              void* d_out, int out_size) {
    const float* x  = (const float*)d_in[0];
    const float* rt = (const float*)d_in[1];
    const float* qw = (const float*)d_in[2];
    const float* kw = (const float*)d_in[3];
    const float* vw = (const float*)d_in[4];
    const float* ow = (const float*)d_in[5];
    const float* ob = (const float*)d_in[6];
    float* out = (float*)d_out;

    int8_t *p_wi, *p_xi;
    __nv_bfloat16 *p_qs, *p_ks, *p_vs, *p_acat, *p_wcat;
    float *p_as, *p_part, *p_scales;
    cudaGetSymbolAddress((void**)&p_wi, g_wi);
    cudaGetSymbolAddress((void**)&p_xi, g_xi);
    cudaGetSymbolAddress((void**)&p_as, g_as);
    cudaGetSymbolAddress((void**)&p_qs, g_qs);
    cudaGetSymbolAddress((void**)&p_ks, g_ks);
    cudaGetSymbolAddress((void**)&p_vs, g_vs);
    cudaGetSymbolAddress((void**)&p_acat, g_acat);
    cudaGetSymbolAddress((void**)&p_wcat, g_wcat);
    cudaGetSymbolAddress((void**)&p_part, g_part);
    cudaGetSymbolAddress((void**)&p_scales, g_scales);

    const int n = E_DIM * E_DIM;

    // 1. scales + ternary s8 weights (fused 3-way)
    absmean3<<<dim3(1024, 3), 256>>>(qw, kw, vw, p_part, n);
    scale_finalize<<<3, 256>>>(p_part, p_scales, 1024, 1.f / (float)n);
    quantw3<<<dim3(2048, 3), 256>>>(qw, kw, vw, p_wi, p_scales, n);

    // 2. activation quant (s8) + out_w split concat
    quant_act_k<<<B_DIM * S_DIM, 256>>>(x, p_xi, p_as);
    wsplit_k<<<(n + 255) / 256, 256>>>(ow, p_wcat);

    // 3. QKV projections on int8 IMMA -> split bf16 [token][h][hi|lo]
    IJobs j1 = {};
    for (int z = 0; z < 6; z++) {
        int w = z >> 1, batch = z & 1;
        j1.A[z] = p_xi + (size_t)batch * S_DIM * E_DIM;
        j1.W[z] = p_wi + (size_t)w * n;
        if (w == 0)
            j1.C[z] = p_qs + (size_t)batch * S_DIM * ROWW;
        else if (w == 1)
            j1.C[z] = p_ks + (size_t)batch * T_DIM * ROWW;
        else
            j1.C[z] = p_vs + (size_t)batch * T_DIM * ROWW;
        j1.rs[z] = p_as + (size_t)batch * S_DIM;
        j1.ws[z] = p_scales + w;
    }
    cudaFuncSetAttribute(igemm_nt, cudaFuncAttributeMaxDynamicSharedMemorySize,
                         65536);
    igemm_nt<<<dim3(16, 16, 6), 256, 65536>>>(j1, S_DIM, E_DIM, E_DIM);

    // 4. reasoning rk/rv -> split bf16 rows S..T
    GemmJobs j2 = {};
    for (int z = 0; z < 4; z++) {
        int w = z >> 1, batch = z & 1;
        j2.A[z] = rt + (size_t)batch * R_DIM * E_DIM;
        j2.W[z] = (w == 0) ? kw : vw;
        j2.C[z] = ((w == 0) ? p_ks : p_vs) +
                  ((size_t)batch * T_DIM + S_DIM) * ROWW;
    }
    sgemm_nt64<<<dim3(32, 1, 4), 256>>>(j2, R_DIM, E_DIM, E_DIM);

    // 5. pipelined tensor-core flash attention -> AO split concat
    cudaFuncSetAttribute(attn_tc, cudaFuncAttributeMaxDynamicSharedMemorySize,
                         ATT_SMEM);
    attn_tc<<<dim3(S_DIM / 128, H_DIM, B_DIM), 256, ATT_SMEM>>>(p_qs, p_ks, p_vs,
                                                                p_acat);

    // 6. output projection: split bf16 GEMM over K'=6144 + bias
    BJobs j3 = {};
    j3.A = p_acat;
    j3.W = p_wcat;
    j3.C = out;
    j3.bias = ob;
    cudaFuncSetAttribute(bgemm_nt, cudaFuncAttributeMaxDynamicSharedMemorySize,
                         65536);
    bgemm_nt<<<dim3(16, 32, 1), 256, 65536>>>(j3, B_DIM * S_DIM, E_DIM, KCAT);
}

// round 8
// speedup vs baseline: 2.1414x; 2.1414x over previous
#include <cuda_runtime.h>
#include <cuda_bf16.h>
#include <math.h>
#include <stdint.h>

#define E_DIM 2048
#define B_DIM 2
#define S_DIM 2048
#define R_DIM 128
#define H_DIM 16
#define D_DIM 128
#define T_DIM (S_DIM + R_DIM)   /* 2176 */
#define KCAT (3 * E_DIM)        /* 6144 */
#define ROWW 4096               /* per-token split row: H*256 bf16 */

// ---------------- scratch -----------------------------------------------------
__device__ __nv_bfloat16 g_wb[3][E_DIM * E_DIM];        // ternary weights bf16
__device__ __nv_bfloat16 g_xb[B_DIM * S_DIM * E_DIM];   // int8-valued acts bf16
__device__ float g_as[B_DIM * S_DIM];                   // per-token 1/s
__device__ __nv_bfloat16 g_qs[(size_t)B_DIM * S_DIM * ROWW];
__device__ __nv_bfloat16 g_ks[(size_t)B_DIM * T_DIM * ROWW];
__device__ __nv_bfloat16 g_vs[(size_t)B_DIM * T_DIM * ROWW];
__device__ __nv_bfloat16 g_acat[(size_t)B_DIM * S_DIM * KCAT];
__device__ __nv_bfloat16 g_wcat[(size_t)E_DIM * KCAT];
__device__ float g_part[3 * 1024];
__device__ float g_scales[3];

// ---------------- prep kernels (fused over 3 weights via grid.y) --------------
__global__ void absmean3(const float* __restrict__ qw, const float* __restrict__ kw,
                         const float* __restrict__ vw, float* __restrict__ part,
                         int n) {
    __shared__ float red[256];
    const float* w = (blockIdx.y == 0) ? qw : (blockIdx.y == 1) ? kw : vw;
    int chunk = n / gridDim.x;
    int base = blockIdx.x * chunk;
    float s = 0.f;
    for (int i = threadIdx.x; i < chunk; i += blockDim.x) s += fabsf(w[base + i]);
    red[threadIdx.x] = s;
    __syncthreads();
    for (int off = 128; off > 0; off >>= 1) {
        if (threadIdx.x < off) red[threadIdx.x] += red[threadIdx.x + off];
        __syncthreads();
    }
    if (threadIdx.x == 0) part[blockIdx.y * 1024 + blockIdx.x] = red[0];
}

__global__ void scale_finalize(const float* __restrict__ part,
                               float* __restrict__ scales, int nblk, float inv_n) {
    __shared__ float red[256];
    const float* p = part + blockIdx.x * nblk;
    float s = 0.f;
    for (int i = threadIdx.x; i < nblk; i += blockDim.x) s += p[i];
    red[threadIdx.x] = s;
    __syncthreads();
    for (int off = 128; off > 0; off >>= 1) {
        if (threadIdx.x < off) red[threadIdx.x] += red[threadIdx.x + off];
        __syncthreads();
    }
    if (threadIdx.x == 0) scales[blockIdx.x] = fmaxf(red[0] * inv_n, 1e-5f);
}

__global__ void quantw3(const float* __restrict__ qw, const float* __restrict__ kw,
                        const float* __restrict__ vw,
                        __nv_bfloat16* __restrict__ wb,
                        const float* __restrict__ scales, int n) {
    int s = blockIdx.y;
    const float* w = (s == 0) ? qw : (s == 1) ? kw : vw;
    __nv_bfloat16* o = wb + (size_t)s * n;
    float sc = scales[s];
    for (int i = blockIdx.x * blockDim.x + threadIdx.x; i < n;
         i += gridDim.x * blockDim.x) {
        float q = rintf(__fdiv_rn(w[i], sc));
        q = fminf(fmaxf(q, -1.f), 1.f);
        o[i] = __float2bfloat16(q);
    }
}

__global__ void quant_act_k(const float* __restrict__ x,
                            __nv_bfloat16* __restrict__ xb,
                            float* __restrict__ as_) {
    __shared__ float red[256];
    int row = blockIdx.x;
    const float* xr = x + (size_t)row * E_DIM;
    __nv_bfloat16* qr = xb + (size_t)row * E_DIM;
    float m = 0.f;
    for (int i = threadIdx.x; i < E_DIM; i += blockDim.x) m = fmaxf(m, fabsf(xr[i]));
    red[threadIdx.x] = m;
    __syncthreads();
    for (int off = 128; off > 0; off >>= 1) {
        if (threadIdx.x < off)
            red[threadIdx.x] = fmaxf(red[threadIdx.x], red[threadIdx.x + off]);
        __syncthreads();
    }
    float mx = fmaxf(red[0], 1e-5f);
    float s = __fdiv_rn(127.f, mx);
    if (threadIdx.x == 0) as_[row] = __fdiv_rn(1.f, s);
    for (int i = threadIdx.x; i < E_DIM; i += blockDim.x) {
        float q = rintf(xr[i] * s);
        q = fminf(fmaxf(q, -128.f), 127.f);
        qr[i] = __float2bfloat16(q);
    }
}

__global__ void wsplit_k(const float* __restrict__ w,
                         __nv_bfloat16* __restrict__ wc) {
    int idx = blockIdx.x * blockDim.x + threadIdx.x;
    if (idx >= E_DIM * E_DIM) return;
    int r = idx / E_DIM, c = idx % E_DIM;
    float x = w[idx];
    __nv_bfloat16 h = __float2bfloat16(x);
    __nv_bfloat16 l = __float2bfloat16(x - __bfloat162float(h));
    size_t base = (size_t)r * KCAT + c;
    wc[base] = h;
    wc[base + E_DIM] = h;
    wc[base + 2 * E_DIM] = l;
}

// ---------------- bf16 tensor-core NT GEMM -----------------------------------
struct BJobs {
    const __nv_bfloat16* A[6];
    const __nv_bfloat16* W[6];
    float* C[6];            // split: cast to bf16*
    const float* rs[6];
    const float* ws[6];
    int split[6];
    const float* bias;
};

__device__ __forceinline__ uint32_t swz(uint32_t o) { return o ^ ((o >> 3) & 0x70); }

__global__ __launch_bounds__(256, 1) void bgemm_nt(BJobs jobs, int M, int N, int K) {
    extern __shared__ __align__(128) char sm_raw[];
    int z = blockIdx.z;
    const __nv_bfloat16* A = jobs.A[z];
    const __nv_bfloat16* W = jobs.W[z];
    const float* rs = jobs.rs[z];
    const float* ws = jobs.ws[z];

    uint32_t sbase = (uint32_t)__cvta_generic_to_shared(sm_raw);
    int tid = threadIdx.x, lane = tid & 31, warp = tid >> 5;
    int wm = warp >> 1, wn = warp & 1;
    int bm = blockIdx.y * 128, bn = blockIdx.x * 128;

    const __nv_bfloat16* Ag = A + (size_t)bm * K;
    const __nv_bfloat16* Wg = W + (size_t)bn * K;

    float acc[2][8][4];
#pragma unroll
    for (int mf = 0; mf < 2; mf++)
#pragma unroll
        for (int nf = 0; nf < 8; nf++)
#pragma unroll
            for (int c = 0; c < 4; c++) acc[mf][nf][c] = 0.f;

    float4 sa[4], sw[4];
#pragma unroll
    for (int i = 0; i < 4; i++) {
        int idx = i * 256 + tid;
        int row = idx >> 3, c = idx & 7;
        sa[i] = *(const float4*)(Ag + (size_t)row * K + c * 8);
        sw[i] = *(const float4*)(Wg + (size_t)row * K + c * 8);
    }
#pragma unroll
    for (int i = 0; i < 4; i++) {
        int idx = i * 256 + tid;
        int row = idx >> 3, c = idx & 7;
        uint32_t off = swz((uint32_t)(row * 128 + c * 16));
        *(float4*)(sm_raw + off) = sa[i];
        *(float4*)(sm_raw + 16384 + off) = sw[i];
    }
    __syncthreads();

    int KT = K >> 6;
    for (int kt = 0; kt < KT; kt++) {
        int cur = kt & 1;
        if (kt + 1 < KT) {
#pragma unroll
            for (int i = 0; i < 4; i++) {
                int idx = i * 256 + tid;
                int row = idx >> 3, c = idx & 7;
                sa[i] = *(const float4*)(Ag + (size_t)row * K + (kt + 1) * 64 + c * 8);
                sw[i] = *(const float4*)(Wg + (size_t)row * K + (kt + 1) * 64 + c * 8);
            }
        }
        uint32_t abase = sbase + cur * 32768;
        uint32_t wbase = abase + 16384;
#pragma unroll
        for (int ks = 0; ks < 4; ks++) {
            uint32_t a[2][4];
#pragma unroll
            for (int mf = 0; mf < 2; mf++) {
                int r = wm * 32 + mf * 16 + ((lane >> 3) & 1) * 8 + (lane & 7);
                uint32_t off = swz((uint32_t)(r * 128 + ks * 32 + ((lane >> 4) & 1) * 16));
                asm volatile(
                    "ldmatrix.sync.aligned.m8n8.x4.shared.b16 {%0,%1,%2,%3}, [%4];"
                    : "=r"(a[mf][0]), "=r"(a[mf][1]), "=r"(a[mf][2]), "=r"(a[mf][3])
                    : "r"(abase + off));
            }
            uint32_t b0[8], b1[8];
#pragma unroll
            for (int q = 0; q < 4; q++) {
                int r = wn * 64 + q * 16 + ((lane >> 3) & 1) * 8 + (lane & 7);
                uint32_t off = swz((uint32_t)(r * 128 + ks * 32 + ((lane >> 4) & 1) * 16));
                uint32_t r0, r1, r2, r3;
                asm volatile(
                    "ldmatrix.sync.aligned.m8n8.x4.shared.b16 {%0,%1,%2,%3}, [%4];"
                    : "=r"(r0), "=r"(r1), "=r"(r2), "=r"(r3)
                    : "r"(wbase + off));
                b0[2 * q] = r0; b0[2 * q + 1] = r1;
                b1[2 * q] = r2; b1[2 * q + 1] = r3;
            }
#pragma unroll
            for (int mf = 0; mf < 2; mf++)
#pragma unroll
                for (int nf = 0; nf < 8; nf++)
                    asm volatile(
                        "mma.sync.aligned.m16n8k16.row.col.f32.bf16.bf16.f32 "
                        "{%0,%1,%2,%3},{%4,%5,%6,%7},{%8,%9},{%0,%1,%2,%3};"
                        : "+f"(acc[mf][nf][0]), "+f"(acc[mf][nf][1]),
                          "+f"(acc[mf][nf][2]), "+f"(acc[mf][nf][3])
                        : "r"(a[mf][0]), "r"(a[mf][1]), "r"(a[mf][2]), "r"(a[mf][3]),
                          "r"(b0[nf]), "r"(b1[nf]));
        }
        if (kt + 1 < KT) {
            int nxt = cur ^ 1;
#pragma unroll
            for (int i = 0; i < 4; i++) {
                int idx = i * 256 + tid;
                int row = idx >> 3, c = idx & 7;
                uint32_t off = swz((uint32_t)(row * 128 + c * 16));
                *(float4*)(sm_raw + nxt * 32768 + off) = sa[i];
                *(float4*)(sm_raw + nxt * 32768 + 16384 + off) = sw[i];
            }
        }
        __syncthreads();
    }

    int g = lane >> 2, t = lane & 3;
    float wsv = ws ? *ws : 1.f;
    if (jobs.split[z]) {
        __nv_bfloat16* Ob = (__nv_bfloat16*)jobs.C[z];
#pragma unroll
        for (int mf = 0; mf < 2; mf++) {
            int row0 = bm + wm * 32 + mf * 16 + g;
            float r0s = (rs ? rs[row0] : 1.f) * wsv;
            float r1s = (rs ? rs[row0 + 8] : 1.f) * wsv;
#pragma unroll
            for (int nf = 0; nf < 8; nf++) {
                int col = bn + wn * 64 + nf * 8 + 2 * t;
                int hh = col >> 7, d = col & 127;
                size_t i0 = (size_t)row0 * ROWW + hh * 256 + d;
                size_t i8 = (size_t)(row0 + 8) * ROWW + hh * 256 + d;
                float v0 = acc[mf][nf][0] * r0s, v1 = acc[mf][nf][1] * r0s;
                float v2 = acc[mf][nf][2] * r1s, v3 = acc[mf][nf][3] * r1s;
                __nv_bfloat162 h0 = __floats2bfloat162_rn(v0, v1);
                __nv_bfloat162 l0 = __floats2bfloat162_rn(
                    v0 - __bfloat162float(h0.x), v1 - __bfloat162float(h0.y));
                __nv_bfloat162 h8 = __floats2bfloat162_rn(v2, v3);
                __nv_bfloat162 l8 = __floats2bfloat162_rn(
                    v2 - __bfloat162float(h8.x), v3 - __bfloat162float(h8.y));
                *(__nv_bfloat162*)&Ob[i0] = h0;
                *(__nv_bfloat162*)&Ob[i0 + 128] = l0;
                *(__nv_bfloat162*)&Ob[i8] = h8;
                *(__nv_bfloat162*)&Ob[i8 + 128] = l8;
            }
        }
    } else {
        float* C = jobs.C[z];
        const float* bias = jobs.bias;
#pragma unroll
        for (int mf = 0; mf < 2; mf++) {
            int row0 = bm + wm * 32 + mf * 16 + g;
            float r0s = (rs ? rs[row0] : 1.f) * wsv;
            float r1s = (rs ? rs[row0 + 8] : 1.f) * wsv;
#pragma unroll
            for (int nf = 0; nf < 8; nf++) {
                int col = bn + wn * 64 + nf * 8 + 2 * t;
                float b0v = bias ? bias[col] : 0.f;
                float b1v = bias ? bias[col + 1] : 0.f;
                float2 v0 = make_float2(acc[mf][nf][0] * r0s + b0v,
                                        acc[mf][nf][1] * r0s + b1v);
                float2 v1 = make_float2(acc[mf][nf][2] * r1s + b0v,
                                        acc[mf][nf][3] * r1s + b1v);
                *(float2*)&C[(size_t)row0 * N + col] = v0;
                *(float2*)&C[(size_t)(row0 + 8) * N + col] = v1;
            }
        }
    }
}

// ---------------- fp32 NT SGEMM 128x64 (rk/rv) -> split bf16 out --------------
struct GemmJobs {
    const float* A[4];
    const float* W[4];
    __nv_bfloat16* C[4];
};

__global__ __launch_bounds__(256) void sgemm_nt64(GemmJobs jobs, int M, int N, int K) {
    __shared__ __align__(16) float As[128][20];
    __shared__ __align__(16) float Ws[64][20];
    const float* A = jobs.A[blockIdx.z];
    const float* W = jobs.W[blockIdx.z];
    __nv_bfloat16* C = jobs.C[blockIdx.z];
    int tid = threadIdx.x;
    int tx = tid & 15, ty = tid >> 4;
    int bn = blockIdx.x * 64;

    float acc[8][4];
#pragma unroll
    for (int i = 0; i < 8; i++)
#pragma unroll
        for (int j = 0; j < 4; j++) acc[i][j] = 0.f;

    for (int kt = 0; kt < K; kt += 16) {
#pragma unroll
        for (int it = 0; it < 2; it++) {
            int idx = tid + it * 256;
            int row = idx >> 2, k4 = (idx & 3) * 4;
            *(float4*)&As[row][k4] =
                *(const float4*)&A[(size_t)row * K + kt + k4];
        }
        {
            int row = tid >> 2, k4 = (tid & 3) * 4;
            *(float4*)&Ws[row][k4] =
                *(const float4*)&W[(size_t)(bn + row) * K + kt + k4];
        }
        __syncthreads();
#pragma unroll
        for (int k4 = 0; k4 < 16; k4 += 4) {
            float4 a[8], b[4];
#pragma unroll
            for (int i = 0; i < 8; i++) a[i] = *(float4*)&As[ty + 16 * i][k4];
#pragma unroll
            for (int j = 0; j < 4; j++) b[j] = *(float4*)&Ws[tx + 16 * j][k4];
#pragma unroll
            for (int i = 0; i < 8; i++)
#pragma unroll
                for (int j = 0; j < 4; j++)
                    acc[i][j] += a[i].x * b[j].x + a[i].y * b[j].y +
                                 a[i].z * b[j].z + a[i].w * b[j].w;
        }
        __syncthreads();
    }
#pragma unroll
    for (int i = 0; i < 8; i++) {
        int r = ty + 16 * i;
#pragma unroll
        for (int j = 0; j < 4; j++) {
            int n = bn + tx + 16 * j;
            int hh = n >> 7, d = n & 127;
            float v = acc[i][j];
            __nv_bfloat16 h = __float2bfloat16(v);
            __nv_bfloat16 l = __float2bfloat16(v - __bfloat162float(h));
            C[(size_t)r * ROWW + hh * 256 + d] = h;
            C[(size_t)r * ROWW + hh * 256 + d + 128] = l;
        }
    }
}

// ---------------- tensor-core flash attention v2 ------------------------------
// Q fragments hoisted to registers; K/V fragment reuse restructured.
#define ATT_Q_OFF 0
#define ATT_K_OFF 65536
#define ATT_V_OFF 131072
#define ATT_P_OFF 196608
#define ATT_SMEM 229376

__device__ __forceinline__ uint32_t sw512o(int r, int c) {
    return (uint32_t)(r * 512 + ((((c >> 3) ^ (r & 7))) << 4) + ((c & 7) << 1));
}
__device__ __forceinline__ uint32_t sw256o(int r, int c) {
    return (uint32_t)(r * 256 + ((((c >> 3) ^ (r & 7))) << 4) + ((c & 7) << 1));
}
__device__ __forceinline__ void ldsm4(uint32_t addr, uint32_t& r0, uint32_t& r1,
                                      uint32_t& r2, uint32_t& r3) {
    asm volatile("ldmatrix.sync.aligned.m8n8.x4.shared.b16 {%0,%1,%2,%3}, [%4];"
                 : "=r"(r0), "=r"(r1), "=r"(r2), "=r"(r3) : "r"(addr));
}
__device__ __forceinline__ void ldsm4t(uint32_t addr, uint32_t& r0, uint32_t& r1,
                                       uint32_t& r2, uint32_t& r3) {
    asm volatile("ldmatrix.sync.aligned.m8n8.x4.trans.shared.b16 {%0,%1,%2,%3}, [%4];"
                 : "=r"(r0), "=r"(r1), "=r"(r2), "=r"(r3) : "r"(addr));
}
__device__ __forceinline__ void cpa16g(uint32_t dst, const void* src) {
    asm volatile("cp.async.cg.shared.global [%0], [%1], 16;" :: "r"(dst), "l"(src));
}
__device__ __forceinline__ void cp_commitg() {
    asm volatile("cp.async.commit_group;" ::: "memory");
}
#define MMA_BF16(d, a, b0v, b1v) \
    asm volatile( \
        "mma.sync.aligned.m16n8k16.row.col.f32.bf16.bf16.f32 " \
        "{%0,%1,%2,%3},{%4,%5,%6,%7},{%8,%9},{%0,%1,%2,%3};" \
        : "+f"((d)[0]), "+f"((d)[1]), "+f"((d)[2]), "+f"((d)[3]) \
        : "r"((a)[0]), "r"((a)[1]), "r"((a)[2]), "r"((a)[3]), \
          "r"(b0v), "r"(b1v))

__global__ __launch_bounds__(256, 1) void attn_tc(const __nv_bfloat16* __restrict__ Qs,
                                                  const __nv_bfloat16* __restrict__ Ks,
                                                  const __nv_bfloat16* __restrict__ Vs,
                                                  __nv_bfloat16* __restrict__ AOcat) {
    extern __shared__ __align__(128) char smc[];
    uint32_t sb = (uint32_t)__cvta_generic_to_shared(smc);

    int tid = threadIdx.x, lane = tid & 31, w = tid >> 5;
    int g = lane >> 2, t = lane & 3;
    int q0 = blockIdx.x * 128;
    int h = blockIdx.y, b = blockIdx.z;

    const __nv_bfloat16* Qg = Qs + ((size_t)(b * S_DIM + q0) * H_DIM + h) * 256;
    const __nv_bfloat16* Kg = Ks + ((size_t)(b * T_DIM) * H_DIM + h) * 256;
    const __nv_bfloat16* Vg = Vs + ((size_t)(b * T_DIM) * H_DIM + h) * 256;

    const int NT = T_DIM / 64;  // 34

    // prologue: Q + K0 | V0 | K1 | V1 (4 commit groups)
#pragma unroll
    for (int it = 0; it < 16; it++) {
        int idx = it * 256 + tid;
        int r = idx >> 5, c = (idx & 31) * 8;
        cpa16g(sb + ATT_Q_OFF + sw512o(r, c), Qg + (size_t)r * ROWW + c);
    }
#pragma unroll
    for (int it = 0; it < 8; it++) {
        int idx = it * 256 + tid;
        int r = idx >> 5, c = (idx & 31) * 8;
        cpa16g(sb + ATT_K_OFF + sw512o(r, c), Kg + (size_t)r * ROWW + c);
    }
    cp_commitg();
#pragma unroll
    for (int it = 0; it < 8; it++) {
        int idx = it * 256 + tid;
        int r = idx >> 5, ch = idx & 31;
        uint32_t dst = (ch < 16) ? sb + ATT_V_OFF + sw256o(r, ch * 8)
                                 : sb + ATT_V_OFF + sw256o(64 + r, (ch - 16) * 8);
        cpa16g(dst, Vg + (size_t)r * ROWW + ch * 8);
    }
    cp_commitg();
#pragma unroll
    for (int it = 0; it < 8; it++) {
        int idx = it * 256 + tid;
        int r = idx >> 5, c = (idx & 31) * 8;
        cpa16g(sb + ATT_K_OFF + 32768 + sw512o(r, c),
               Kg + (size_t)(64 + r) * ROWW + c);
    }
    cp_commitg();
#pragma unroll
    for (int it = 0; it < 8; it++) {
        int idx = it * 256 + tid;
        int r = idx >> 5, ch = idx & 31;
        uint32_t dst = (ch < 16) ? sb + ATT_V_OFF + 32768 + sw256o(r, ch * 8)
                                 : sb + ATT_V_OFF + 32768 + sw256o(64 + r, (ch - 16) * 8);
        cpa16g(dst, Vg + (size_t)(64 + r) * ROWW + ch * 8);
    }
    cp_commitg();

    float o[16][4];
#pragma unroll
    for (int nf = 0; nf < 16; nf++)
#pragma unroll
        for (int c = 0; c < 4; c++) o[nf][c] = 0.f;
    float m0 = -1e30f, m8 = -1e30f, l0 = 0.f, l8 = 0.f;

    uint32_t qf[16][4];   // hoisted Q fragments: [0..7]=Qh chunks, [8..15]=Ql
    const float scl = 0.08838834764831845f;
    int rg = w * 16 + g;
    int arow_f = w * 16 + ((lane >> 3) & 1) * 8 + (lane & 7);
    int acol_f = ((lane >> 4) & 1) * 8;

    for (int i = 0; i < NT; i++) {
        asm volatile("cp.async.wait_group 2;" ::: "memory");
        __syncthreads();

        if (i == 0) {
#pragma unroll
            for (int kk = 0; kk < 16; kk++)
                ldsm4(sb + ATT_Q_OFF + sw512o(arow_f, kk * 16 + acol_f),
                      qf[kk][0], qf[kk][1], qf[kk][2], qf[kk][3]);
        }

        uint32_t kbuf = sb + ATT_K_OFF + (i & 1) * 32768;
        uint32_t vbuf = sb + ATT_V_OFF + (i & 1) * 32768;

        // ---- QK: hi k-chunks (Kh reused by Qh & Ql terms), then lo chunks ----
        float accs[8][4];
#pragma unroll
        for (int nf = 0; nf < 8; nf++)
#pragma unroll
            for (int c = 0; c < 4; c++) accs[nf][c] = 0.f;

#pragma unroll
        for (int kk = 0; kk < 8; kk++) {
            uint32_t b0[8], b1[8];
#pragma unroll
            for (int nb = 0; nb < 4; nb++) {
                int br = nb * 16 + ((lane >> 3) & 1) * 8 + (lane & 7);
                uint32_t r0, r1, r2, r3;
                ldsm4(kbuf + sw512o(br, kk * 16 + acol_f), r0, r1, r2, r3);
                b0[2 * nb] = r0; b0[2 * nb + 1] = r1;
                b1[2 * nb] = r2; b1[2 * nb + 1] = r3;
            }
#pragma unroll
            for (int nf = 0; nf < 8; nf++)
                MMA_BF16(accs[nf], qf[kk], b0[nf], b1[nf]);       // Qh@Kh
#pragma unroll
            for (int nf = 0; nf < 8; nf++)
                MMA_BF16(accs[nf], qf[8 + kk], b0[nf], b1[nf]);   // Ql@Kh
        }
#pragma unroll
        for (int kk = 0; kk < 8; kk++) {
            uint32_t b0[8], b1[8];
#pragma unroll
            for (int nb = 0; nb < 4; nb++) {
                int br = nb * 16 + ((lane >> 3) & 1) * 8 + (lane & 7);
                uint32_t r0, r1, r2, r3;
                ldsm4(kbuf + sw512o(br, 128 + kk * 16 + acol_f), r0, r1, r2, r3);
                b0[2 * nb] = r0; b0[2 * nb + 1] = r1;
                b1[2 * nb] = r2; b1[2 * nb + 1] = r3;
            }
#pragma unroll
            for (int nf = 0; nf < 8; nf++)
                MMA_BF16(accs[nf], qf[kk], b0[nf], b1[nf]);       // Qh@Kl
        }

        // ---- register-space online softmax ----
        float mx0 = -1e30f, mx8 = -1e30f;
#pragma unroll
        for (int nf = 0; nf < 8; nf++) {
            accs[nf][0] *= scl; accs[nf][1] *= scl;
            accs[nf][2] *= scl; accs[nf][3] *= scl;
            mx0 = fmaxf(mx0, fmaxf(accs[nf][0], accs[nf][1]));
            mx8 = fmaxf(mx8, fmaxf(accs[nf][2], accs[nf][3]));
        }
        mx0 = fmaxf(mx0, __shfl_xor_sync(0xffffffffu, mx0, 1));
        mx0 = fmaxf(mx0, __shfl_xor_sync(0xffffffffu, mx0, 2));
        mx8 = fmaxf(mx8, __shfl_xor_sync(0xffffffffu, mx8, 1));
        mx8 = fmaxf(mx8, __shfl_xor_sync(0xffffffffu, mx8, 2));
        float mn0 = fmaxf(m0, mx0), mn8 = fmaxf(m8, mx8);
        float al0 = __expf(m0 - mn0), al8 = __expf(m8 - mn8);
        m0 = mn0; m8 = mn8;
        float sum0 = 0.f, sum8 = 0.f;
#pragma unroll
        for (int nf = 0; nf < 8; nf++) {
            int c = nf * 8 + 2 * t;
            float p0 = __expf(accs[nf][0] - mn0);
            float p1 = __expf(accs[nf][1] - mn0);
            sum0 += p0 + p1;
            __nv_bfloat162 ph = __floats2bfloat162_rn(p0, p1);
            __nv_bfloat162 pl = __floats2bfloat162_rn(
                p0 - __bfloat162float(ph.x), p1 - __bfloat162float(ph.y));
            *(__nv_bfloat162*)(smc + ATT_P_OFF + sw256o(rg, c)) = ph;
            *(__nv_bfloat162*)(smc + ATT_P_OFF + sw256o(rg, 64 + c)) = pl;
            float p2 = __expf(accs[nf][2] - mn8);
            float p3 = __expf(accs[nf][3] - mn8);
            sum8 += p2 + p3;
            __nv_bfloat162 qh = __floats2bfloat162_rn(p2, p3);
            __nv_bfloat162 ql = __floats2bfloat162_rn(
                p2 - __bfloat162float(qh.x), p3 - __bfloat162float(qh.y));
            *(__nv_bfloat162*)(smc + ATT_P_OFF + sw256o(rg + 8, c)) = qh;
            *(__nv_bfloat162*)(smc + ATT_P_OFF + sw256o(rg + 8, 64 + c)) = ql;
        }
        sum0 += __shfl_xor_sync(0xffffffffu, sum0, 1);
        sum0 += __shfl_xor_sync(0xffffffffu, sum0, 2);
        sum8 += __shfl_xor_sync(0xffffffffu, sum8, 1);
        sum8 += __shfl_xor_sync(0xffffffffu, sum8, 2);
        l0 = l0 * al0 + sum0;
        l8 = l8 * al8 + sum8;
#pragma unroll
        for (int nf = 0; nf < 16; nf++) {
            o[nf][0] *= al0; o[nf][1] *= al0;
            o[nf][2] *= al8; o[nf][3] *= al8;
        }
        __syncwarp();

        // ---- PV: hi v-chunks (Vh reused by Ph & Pl), then lo chunks (Ph) ----
#pragma unroll
        for (int vv = 0; vv < 4; vv++) {
            uint32_t vb[8][4];
#pragma unroll
            for (int ng = 0; ng < 8; ng++) {
                int vr = vv * 16 + ((lane >> 3) & 1) * 8 + (lane & 7);
                ldsm4t(vbuf + sw256o(vr, ng * 16 + acol_f),
                       vb[ng][0], vb[ng][1], vb[ng][2], vb[ng][3]);
            }
            uint32_t ah[4], al_[4];
            ldsm4(sb + ATT_P_OFF + sw256o(arow_f, vv * 16 + acol_f),
                  ah[0], ah[1], ah[2], ah[3]);
            ldsm4(sb + ATT_P_OFF + sw256o(arow_f, 64 + vv * 16 + acol_f),
                  al_[0], al_[1], al_[2], al_[3]);
#pragma unroll
            for (int ng = 0; ng < 8; ng++) {
                MMA_BF16(o[2 * ng], ah, vb[ng][0], vb[ng][1]);
                MMA_BF16(o[2 * ng + 1], ah, vb[ng][2], vb[ng][3]);
            }
#pragma unroll
            for (int ng = 0; ng < 8; ng++) {
                MMA_BF16(o[2 * ng], al_, vb[ng][0], vb[ng][1]);
                MMA_BF16(o[2 * ng + 1], al_, vb[ng][2], vb[ng][3]);
            }
        }
#pragma unroll
        for (int vv = 0; vv < 4; vv++) {
            uint32_t vb[8][4];
#pragma unroll
            for (int ng = 0; ng < 8; ng++) {
                int vr = 64 + vv * 16 + ((lane >> 3) & 1) * 8 + (lane & 7);
                ldsm4t(vbuf + sw256o(vr, ng * 16 + acol_f),
                       vb[ng][0], vb[ng][1], vb[ng][2], vb[ng][3]);
            }
            uint32_t ah[4];
            ldsm4(sb + ATT_P_OFF + sw256o(arow_f, vv * 16 + acol_f),
                  ah[0], ah[1], ah[2], ah[3]);
#pragma unroll
            for (int ng = 0; ng < 8; ng++) {
                MMA_BF16(o[2 * ng], ah, vb[ng][0], vb[ng][1]);
                MMA_BF16(o[2 * ng + 1], ah, vb[ng][2], vb[ng][3]);
            }
        }
        __syncthreads();

        // ---- prefetch tile i+2 ----
        if (i + 2 < NT) {
            int tK = (i + 2) * 64;
            uint32_t kb2 = sb + ATT_K_OFF + (i & 1) * 32768;
#pragma unroll
            for (int it = 0; it < 8; it++) {
                int idx = it * 256 + tid;
                int r = idx >> 5, c = (idx & 31) * 8;
                cpa16g(kb2 + sw512o(r, c), Kg + (size_t)(tK + r) * ROWW + c);
            }
        }
        cp_commitg();
        if (i + 2 < NT) {
            int tV = (i + 2) * 64;
            uint32_t vb2 = sb + ATT_V_OFF + (i & 1) * 32768;
#pragma unroll
            for (int it = 0; it < 8; it++) {
                int idx = it * 256 + tid;
                int r = idx >> 5, ch = idx & 31;
                uint32_t dst = (ch < 16) ? vb2 + sw256o(r, ch * 8)
                                         : vb2 + sw256o(64 + r, (ch - 16) * 8);
                cpa16g(dst, Vg + (size_t)(tV + r) * ROWW + ch * 8);
            }
        }
        cp_commitg();
    }

    // epilogue: normalize and write hi/lo concat rows of AOcat
    {
        float li0 = __fdiv_rn(1.f, l0);
        float li8 = __fdiv_rn(1.f, l8);
        size_t grow0 = (size_t)(b * S_DIM + q0 + rg) * KCAT + h * D_DIM;
        size_t grow8 = grow0 + (size_t)8 * KCAT;
#pragma unroll
        for (int nf = 0; nf < 16; nf++) {
            int c = nf * 8 + 2 * t;
            float f0 = o[nf][0] * li0, f1 = o[nf][1] * li0;
            float f2 = o[nf][2] * li8, f3 = o[nf][3] * li8;
            __nv_bfloat162 h0 = __floats2bfloat162_rn(f0, f1);
            __nv_bfloat162 ll0 = __floats2bfloat162_rn(f0 - __bfloat162float(h0.x),
                                                       f1 - __bfloat162float(h0.y));
            __nv_bfloat162 h8 = __floats2bfloat162_rn(f2, f3);
            __nv_bfloat162 ll8 = __floats2bfloat162_rn(f2 - __bfloat162float(h8.x),
                                                       f3 - __bfloat162float(h8.y));
            *(__nv_bfloat162*)&AOcat[grow0 + c] = h0;
            *(__nv_bfloat162*)&AOcat[grow0 + E_DIM + c] = ll0;
            *(__nv_bfloat162*)&AOcat[grow0 + 2 * E_DIM + c] = h0;
            *(__nv_bfloat162*)&AOcat[grow8 + c] = h8;
            *(__nv_bfloat162*)&AOcat[grow8 + E_DIM + c] = ll8;
            *(__nv_bfloat162*)&AOcat[grow8 + 2 * E_DIM + c] = h8;
        }
    }
}

// ---------------- launcher ----------------------------------------------------
extern "C" void kernel_launch(void* const* d_in, const int* in_sizes, int n_in,
                              void* d_out, int out_size) {
    const float* x  = (const float*)d_in[0];
    const float* rt = (const float*)d_in[1];
    const float* qw = (const float*)d_in[2];
    const float* kw = (const float*)d_in[3];
    const float* vw = (const float*)d_in[4];
    const float* ow = (const float*)d_in[5];
    const float* ob = (const float*)d_in[6];
    float* out = (float*)d_out;

    __nv_bfloat16 *p_wb, *p_xb, *p_qs, *p_ks, *p_vs, *p_acat, *p_wcat;
    float *p_as, *p_part, *p_scales;
    cudaGetSymbolAddress((void**)&p_wb, g_wb);
    cudaGetSymbolAddress((void**)&p_xb, g_xb);
    cudaGetSymbolAddress((void**)&p_as, g_as);
    cudaGetSymbolAddress((void**)&p_qs, g_qs);
    cudaGetSymbolAddress((void**)&p_ks, g_ks);
    cudaGetSymbolAddress((void**)&p_vs, g_vs);
    cudaGetSymbolAddress((void**)&p_acat, g_acat);
    cudaGetSymbolAddress((void**)&p_wcat, g_wcat);
    cudaGetSymbolAddress((void**)&p_part, g_part);
    cudaGetSymbolAddress((void**)&p_scales, g_scales);

    const int n = E_DIM * E_DIM;

    // 1. scales + ternary bf16 weights (fused 3-way)
    absmean3<<<dim3(1024, 3), 256>>>(qw, kw, vw, p_part, n);
    scale_finalize<<<3, 256>>>(p_part, p_scales, 1024, 1.f / (float)n);
    quantw3<<<dim3(2048, 3), 256>>>(qw, kw, vw, p_wb, p_scales, n);

    // 2. activation quant + out_w split concat
    quant_act_k<<<B_DIM * S_DIM, 256>>>(x, p_xb, p_as);
    wsplit_k<<<(n + 255) / 256, 256>>>(ow, p_wcat);

    // 3. QKV projections (bf16 exact-integer GEMM) -> split bf16
    BJobs j1 = {};
    for (int z = 0; z < 6; z++) {
        int w = z >> 1, batch = z & 1;
        j1.A[z] = p_xb + (size_t)batch * S_DIM * E_DIM;
        j1.W[z] = p_wb + (size_t)w * n;
        if (w == 0)
            j1.C[z] = (float*)(p_qs + (size_t)batch * S_DIM * ROWW);
        else if (w == 1)
            j1.C[z] = (float*)(p_ks + (size_t)batch * T_DIM * ROWW);
        else
            j1.C[z] = (float*)(p_vs + (size_t)batch * T_DIM * ROWW);
        j1.rs[z] = p_as + (size_t)batch * S_DIM;
        j1.ws[z] = p_scales + w;
        j1.split[z] = 1;
    }
    j1.bias = nullptr;
    cudaFuncSetAttribute(bgemm_nt, cudaFuncAttributeMaxDynamicSharedMemorySize,
                         65536);
    bgemm_nt<<<dim3(16, 16, 6), 256, 65536>>>(j1, S_DIM, E_DIM, E_DIM);

    // 4. reasoning rk/rv -> split bf16 rows S..T
    GemmJobs j2 = {};
    for (int z = 0; z < 4; z++) {
        int w = z >> 1, batch = z & 1;
        j2.A[z] = rt + (size_t)batch * R_DIM * E_DIM;
        j2.W[z] = (w == 0) ? kw : vw;
        j2.C[z] = ((w == 0) ? p_ks : p_vs) +
                  ((size_t)batch * T_DIM + S_DIM) * ROWW;
    }
    sgemm_nt64<<<dim3(32, 1, 4), 256>>>(j2, R_DIM, E_DIM, E_DIM);

    // 5. pipelined tensor-core flash attention v2 -> AO split concat
    cudaFuncSetAttribute(attn_tc, cudaFuncAttributeMaxDynamicSharedMemorySize,
                         ATT_SMEM);
    attn_tc<<<dim3(S_DIM / 128, H_DIM, B_DIM), 256, ATT_SMEM>>>(p_qs, p_ks, p_vs,
                                                                p_acat);

    // 6. output projection: split bf16 GEMM over K'=6144 + bias
    BJobs j3 = {};
    j3.A[0] = p_acat;
    j3.W[0] = p_wcat;
    j3.C[0] = out;
    j3.rs[0] = nullptr;
    j3.ws[0] = nullptr;
    j3.split[0] = 0;
    j3.bias = ob;
    bgemm_nt<<<dim3(16, 32, 1), 256, 65536>>>(j3, B_DIM * S_DIM, E_DIM, KCAT);
}

// round 9
// speedup vs baseline: 2.6670x; 1.2455x over previous
#include <cuda_runtime.h>
#include <cuda_fp16.h>
#include <math.h>
#include <stdint.h>

#define E_DIM 2048
#define B_DIM 2
#define S_DIM 2048
#define R_DIM 128
#define H_DIM 16
#define D_DIM 128
#define T_DIM (S_DIM + R_DIM)   /* 2176 */
#define KA   (2 * E_DIM)        /* 4096: out-proj [AOh|AOl] */
#define QROWW 4096              /* Q split row: H*256 fp16 */
#define KVROWW 2048             /* K/V single row: H*128 fp16 */

// ---------------- scratch -----------------------------------------------------
__device__ __half g_wb[3][E_DIM * E_DIM];        // ternary weights fp16 (exact)
__device__ __half g_xb[B_DIM * S_DIM * E_DIM];   // int8-valued acts fp16 (exact)
__device__ float g_as[B_DIM * S_DIM];            // per-token 1/s
__device__ __half g_qs[(size_t)B_DIM * S_DIM * QROWW];  // Q split [h][hi|lo]
__device__ __half g_ks[(size_t)B_DIM * T_DIM * KVROWW]; // K single fp16
__device__ __half g_vs[(size_t)B_DIM * T_DIM * KVROWW]; // V single fp16
__device__ __half g_acat[(size_t)B_DIM * S_DIM * KA];   // [AOh|AOl]
__device__ __half g_wcat[(size_t)E_DIM * KA];           // [OWh|OWh]
__device__ float g_part[3 * 1024];
__device__ float g_scales[3];

// ---------------- prep kernels ------------------------------------------------
__global__ void absmean3(const float* __restrict__ qw, const float* __restrict__ kw,
                         const float* __restrict__ vw, float* __restrict__ part,
                         int n) {
    __shared__ float red[256];
    const float* w = (blockIdx.y == 0) ? qw : (blockIdx.y == 1) ? kw : vw;
    int chunk = n / gridDim.x;
    int base = blockIdx.x * chunk;
    float s = 0.f;
    for (int i = threadIdx.x; i < chunk; i += blockDim.x) s += fabsf(w[base + i]);
    red[threadIdx.x] = s;
    __syncthreads();
    for (int off = 128; off > 0; off >>= 1) {
        if (threadIdx.x < off) red[threadIdx.x] += red[threadIdx.x + off];
        __syncthreads();
    }
    if (threadIdx.x == 0) part[blockIdx.y * 1024 + blockIdx.x] = red[0];
}

__global__ void scale_finalize(const float* __restrict__ part,
                               float* __restrict__ scales, int nblk, float inv_n) {
    __shared__ float red[256];
    const float* p = part + blockIdx.x * nblk;
    float s = 0.f;
    for (int i = threadIdx.x; i < nblk; i += blockDim.x) s += p[i];
    red[threadIdx.x] = s;
    __syncthreads();
    for (int off = 128; off > 0; off >>= 1) {
        if (threadIdx.x < off) red[threadIdx.x] += red[threadIdx.x + off];
        __syncthreads();
    }
    if (threadIdx.x == 0) scales[blockIdx.x] = fmaxf(red[0] * inv_n, 1e-5f);
}

__global__ void quantw3(const float* __restrict__ qw, const float* __restrict__ kw,
                        const float* __restrict__ vw, __half* __restrict__ wb,
                        const float* __restrict__ scales, int n) {
    int s = blockIdx.y;
    const float* w = (s == 0) ? qw : (s == 1) ? kw : vw;
    __half* o = wb + (size_t)s * n;
    float sc = scales[s];
    for (int i = blockIdx.x * blockDim.x + threadIdx.x; i < n;
         i += gridDim.x * blockDim.x) {
        float q = rintf(__fdiv_rn(w[i], sc));
        q = fminf(fmaxf(q, -1.f), 1.f);
        o[i] = __float2half_rn(q);
    }
}

__global__ void quant_act_k(const float* __restrict__ x,
                            __half* __restrict__ xb,
                            float* __restrict__ as_) {
    __shared__ float red[256];
    int row = blockIdx.x;
    const float* xr = x + (size_t)row * E_DIM;
    __half* qr = xb + (size_t)row * E_DIM;
    float m = 0.f;
    for (int i = threadIdx.x; i < E_DIM; i += blockDim.x) m = fmaxf(m, fabsf(xr[i]));
    red[threadIdx.x] = m;
    __syncthreads();
    for (int off = 128; off > 0; off >>= 1) {
        if (threadIdx.x < off)
            red[threadIdx.x] = fmaxf(red[threadIdx.x], red[threadIdx.x + off]);
        __syncthreads();
    }
    float mx = fmaxf(red[0], 1e-5f);
    float s = __fdiv_rn(127.f, mx);
    if (threadIdx.x == 0) as_[row] = __fdiv_rn(1.f, s);
    for (int i = threadIdx.x; i < E_DIM; i += blockDim.x) {
        float q = rintf(xr[i] * s);
        q = fminf(fmaxf(q, -128.f), 127.f);
        qr[i] = __float2half_rn(q);   // |q|<=128 exact in fp16
    }
}

// out_w -> [OWh|OWh] fp16 (duplicated hi)
__global__ void wsplit_k(const float* __restrict__ w, __half* __restrict__ wc) {
    int idx = blockIdx.x * blockDim.x + threadIdx.x;
    if (idx >= E_DIM * E_DIM) return;
    int r = idx / E_DIM, c = idx % E_DIM;
    __half h = __float2half_rn(w[idx]);
    size_t base = (size_t)r * KA + c;
    wc[base] = h;
    wc[base + E_DIM] = h;
}

// ---------------- fp16 tensor-core NT GEMM -----------------------------------
// mode 0: fp32 out + bias; mode 1: Q split (hi+lo); mode 2: K/V single fp16
struct HJobs {
    const __half* A[6];
    const __half* W[6];
    void* C[6];
    const float* rs[6];
    const float* ws[6];
    int mode[6];
    const float* bias;
};

__device__ __forceinline__ uint32_t swz(uint32_t o) { return o ^ ((o >> 3) & 0x70); }

__global__ __launch_bounds__(256, 1) void hgemm_nt(HJobs jobs, int M, int N, int K) {
    extern __shared__ __align__(128) char sm_raw[];
    int z = blockIdx.z;
    const __half* A = jobs.A[z];
    const __half* W = jobs.W[z];
    const float* rs = jobs.rs[z];
    const float* ws = jobs.ws[z];
    int mode = jobs.mode[z];

    uint32_t sbase = (uint32_t)__cvta_generic_to_shared(sm_raw);
    int tid = threadIdx.x, lane = tid & 31, warp = tid >> 5;
    int wm = warp >> 1, wn = warp & 1;
    int bm = blockIdx.y * 128, bn = blockIdx.x * 128;

    const __half* Ag = A + (size_t)bm * K;
    const __half* Wg = W + (size_t)bn * K;

    float acc[2][8][4];
#pragma unroll
    for (int mf = 0; mf < 2; mf++)
#pragma unroll
        for (int nf = 0; nf < 8; nf++)
#pragma unroll
            for (int c = 0; c < 4; c++) acc[mf][nf][c] = 0.f;

    float4 sa[4], sw[4];
#pragma unroll
    for (int i = 0; i < 4; i++) {
        int idx = i * 256 + tid;
        int row = idx >> 3, c = idx & 7;
        sa[i] = *(const float4*)(Ag + (size_t)row * K + c * 8);
        sw[i] = *(const float4*)(Wg + (size_t)row * K + c * 8);
    }
#pragma unroll
    for (int i = 0; i < 4; i++) {
        int idx = i * 256 + tid;
        int row = idx >> 3, c = idx & 7;
        uint32_t off = swz((uint32_t)(row * 128 + c * 16));
        *(float4*)(sm_raw + off) = sa[i];
        *(float4*)(sm_raw + 16384 + off) = sw[i];
    }
    __syncthreads();

    int KT = K >> 6;
    for (int kt = 0; kt < KT; kt++) {
        int cur = kt & 1;
        if (kt + 1 < KT) {
#pragma unroll
            for (int i = 0; i < 4; i++) {
                int idx = i * 256 + tid;
                int row = idx >> 3, c = idx & 7;
                sa[i] = *(const float4*)(Ag + (size_t)row * K + (kt + 1) * 64 + c * 8);
                sw[i] = *(const float4*)(Wg + (size_t)row * K + (kt + 1) * 64 + c * 8);
            }
        }
        uint32_t abase = sbase + cur * 32768;
        uint32_t wbase = abase + 16384;
#pragma unroll
        for (int ks = 0; ks < 4; ks++) {
            uint32_t a[2][4];
#pragma unroll
            for (int mf = 0; mf < 2; mf++) {
                int r = wm * 32 + mf * 16 + ((lane >> 3) & 1) * 8 + (lane & 7);
                uint32_t off = swz((uint32_t)(r * 128 + ks * 32 + ((lane >> 4) & 1) * 16));
                asm volatile(
                    "ldmatrix.sync.aligned.m8n8.x4.shared.b16 {%0,%1,%2,%3}, [%4];"
                    : "=r"(a[mf][0]), "=r"(a[mf][1]), "=r"(a[mf][2]), "=r"(a[mf][3])
                    : "r"(abase + off));
            }
            uint32_t b0[8], b1[8];
#pragma unroll
            for (int q = 0; q < 4; q++) {
                int r = wn * 64 + q * 16 + ((lane >> 3) & 1) * 8 + (lane & 7);
                uint32_t off = swz((uint32_t)(r * 128 + ks * 32 + ((lane >> 4) & 1) * 16));
                uint32_t r0, r1, r2, r3;
                asm volatile(
                    "ldmatrix.sync.aligned.m8n8.x4.shared.b16 {%0,%1,%2,%3}, [%4];"
                    : "=r"(r0), "=r"(r1), "=r"(r2), "=r"(r3)
                    : "r"(wbase + off));
                b0[2 * q] = r0; b0[2 * q + 1] = r1;
                b1[2 * q] = r2; b1[2 * q + 1] = r3;
            }
#pragma unroll
            for (int mf = 0; mf < 2; mf++)
#pragma unroll
                for (int nf = 0; nf < 8; nf++)
                    asm volatile(
                        "mma.sync.aligned.m16n8k16.row.col.f32.f16.f16.f32 "
                        "{%0,%1,%2,%3},{%4,%5,%6,%7},{%8,%9},{%0,%1,%2,%3};"
                        : "+f"(acc[mf][nf][0]), "+f"(acc[mf][nf][1]),
                          "+f"(acc[mf][nf][2]), "+f"(acc[mf][nf][3])
                        : "r"(a[mf][0]), "r"(a[mf][1]), "r"(a[mf][2]), "r"(a[mf][3]),
                          "r"(b0[nf]), "r"(b1[nf]));
        }
        if (kt + 1 < KT) {
            int nxt = cur ^ 1;
#pragma unroll
            for (int i = 0; i < 4; i++) {
                int idx = i * 256 + tid;
                int row = idx >> 3, c = idx & 7;
                uint32_t off = swz((uint32_t)(row * 128 + c * 16));
                *(float4*)(sm_raw + nxt * 32768 + off) = sa[i];
                *(float4*)(sm_raw + nxt * 32768 + 16384 + off) = sw[i];
            }
        }
        __syncthreads();
    }

    int g = lane >> 2, t = lane & 3;
    float wsv = ws ? *ws : 1.f;
    if (mode == 1) {
        // Q: fp16 hi/lo split at [token][h*256 + d | +128]
        __half* Ob = (__half*)jobs.C[z];
#pragma unroll
        for (int mf = 0; mf < 2; mf++) {
            int row0 = bm + wm * 32 + mf * 16 + g;
            float r0s = rs[row0] * wsv;
            float r1s = rs[row0 + 8] * wsv;
#pragma unroll
            for (int nf = 0; nf < 8; nf++) {
                int col = bn + wn * 64 + nf * 8 + 2 * t;
                int hh = col >> 7, d = col & 127;
                size_t i0 = (size_t)row0 * QROWW + hh * 256 + d;
                size_t i8 = (size_t)(row0 + 8) * QROWW + hh * 256 + d;
                float v0 = acc[mf][nf][0] * r0s, v1 = acc[mf][nf][1] * r0s;
                float v2 = acc[mf][nf][2] * r1s, v3 = acc[mf][nf][3] * r1s;
                __half2 h0 = __floats2half2_rn(v0, v1);
                __half2 l0 = __floats2half2_rn(v0 - __half2float(h0.x),
                                               v1 - __half2float(h0.y));
                __half2 h8 = __floats2half2_rn(v2, v3);
                __half2 l8 = __floats2half2_rn(v2 - __half2float(h8.x),
                                               v3 - __half2float(h8.y));
                *(__half2*)&Ob[i0] = h0;
                *(__half2*)&Ob[i0 + 128] = l0;
                *(__half2*)&Ob[i8] = h8;
                *(__half2*)&Ob[i8 + 128] = l8;
            }
        }
    } else if (mode == 2) {
        // K/V: single fp16 at [token][h*128 + d]
        __half* Ob = (__half*)jobs.C[z];
#pragma unroll
        for (int mf = 0; mf < 2; mf++) {
            int row0 = bm + wm * 32 + mf * 16 + g;
            float r0s = rs[row0] * wsv;
            float r1s = rs[row0 + 8] * wsv;
#pragma unroll
            for (int nf = 0; nf < 8; nf++) {
                int col = bn + wn * 64 + nf * 8 + 2 * t;
                int hh = col >> 7, d = col & 127;
                size_t i0 = (size_t)row0 * KVROWW + hh * 128 + d;
                size_t i8 = (size_t)(row0 + 8) * KVROWW + hh * 128 + d;
                *(__half2*)&Ob[i0] = __floats2half2_rn(acc[mf][nf][0] * r0s,
                                                       acc[mf][nf][1] * r0s);
                *(__half2*)&Ob[i8] = __floats2half2_rn(acc[mf][nf][2] * r1s,
                                                       acc[mf][nf][3] * r1s);
            }
        }
    } else {
        float* C = (float*)jobs.C[z];
        const float* bias = jobs.bias;
#pragma unroll
        for (int mf = 0; mf < 2; mf++) {
            int row0 = bm + wm * 32 + mf * 16 + g;
#pragma unroll
            for (int nf = 0; nf < 8; nf++) {
                int col = bn + wn * 64 + nf * 8 + 2 * t;
                float b0v = bias ? bias[col] : 0.f;
                float b1v = bias ? bias[col + 1] : 0.f;
                float2 v0 = make_float2(acc[mf][nf][0] + b0v, acc[mf][nf][1] + b1v);
                float2 v1 = make_float2(acc[mf][nf][2] + b0v, acc[mf][nf][3] + b1v);
                *(float2*)&C[(size_t)row0 * N + col] = v0;
                *(float2*)&C[(size_t)(row0 + 8) * N + col] = v1;
            }
        }
    }
}

// ---------------- fp32 NT SGEMM 128x64 (rk/rv) -> single fp16 out -------------
struct GemmJobs {
    const float* A[4];
    const float* W[4];
    __half* C[4];
};

__global__ __launch_bounds__(256) void sgemm_nt64(GemmJobs jobs, int M, int N, int K) {
    __shared__ __align__(16) float As[128][20];
    __shared__ __align__(16) float Ws[64][20];
    const float* A = jobs.A[blockIdx.z];
    const float* W = jobs.W[blockIdx.z];
    __half* C = jobs.C[blockIdx.z];
    int tid = threadIdx.x;
    int tx = tid & 15, ty = tid >> 4;
    int bn = blockIdx.x * 64;

    float acc[8][4];
#pragma unroll
    for (int i = 0; i < 8; i++)
#pragma unroll
        for (int j = 0; j < 4; j++) acc[i][j] = 0.f;

    for (int kt = 0; kt < K; kt += 16) {
#pragma unroll
        for (int it = 0; it < 2; it++) {
            int idx = tid + it * 256;
            int row = idx >> 2, k4 = (idx & 3) * 4;
            *(float4*)&As[row][k4] =
                *(const float4*)&A[(size_t)row * K + kt + k4];
        }
        {
            int row = tid >> 2, k4 = (tid & 3) * 4;
            *(float4*)&Ws[row][k4] =
                *(const float4*)&W[(size_t)(bn + row) * K + kt + k4];
        }
        __syncthreads();
#pragma unroll
        for (int k4 = 0; k4 < 16; k4 += 4) {
            float4 a[8], b[4];
#pragma unroll
            for (int i = 0; i < 8; i++) a[i] = *(float4*)&As[ty + 16 * i][k4];
#pragma unroll
            for (int j = 0; j < 4; j++) b[j] = *(float4*)&Ws[tx + 16 * j][k4];
#pragma unroll
            for (int i = 0; i < 8; i++)
#pragma unroll
                for (int j = 0; j < 4; j++)
                    acc[i][j] += a[i].x * b[j].x + a[i].y * b[j].y +
                                 a[i].z * b[j].z + a[i].w * b[j].w;
        }
        __syncthreads();
    }
#pragma unroll
    for (int i = 0; i < 8; i++) {
        int r = ty + 16 * i;
#pragma unroll
        for (int j = 0; j < 4; j++) {
            int n = bn + tx + 16 * j;
            int hh = n >> 7, d = n & 127;
            C[(size_t)r * KVROWW + hh * 128 + d] = __float2half_rn(acc[i][j]);
        }
    }
}

// ---------------- fp16 2-term flash attention ---------------------------------
// Q split [Qh|Ql] (regs-hoisted); K,V single fp16; P split [Ph|Pl].
#define ATT_Q_OFF 0            /* [128][512B] = 64KB */
#define ATT_K_OFF 65536        /* 2 x [64][256B] = 32KB */
#define ATT_V_OFF 98304        /* 2 x [64][256B] = 32KB */
#define ATT_P_OFF 131072       /* [128][256B] = 32KB */
#define ATT_SMEM 163840

__device__ __forceinline__ uint32_t sw512o(int r, int c) {
    return (uint32_t)(r * 512 + ((((c >> 3) ^ (r & 7))) << 4) + ((c & 7) << 1));
}
__device__ __forceinline__ uint32_t sw256o(int r, int c) {
    return (uint32_t)(r * 256 + ((((c >> 3) ^ (r & 7))) << 4) + ((c & 7) << 1));
}
__device__ __forceinline__ void ldsm4(uint32_t addr, uint32_t& r0, uint32_t& r1,
                                      uint32_t& r2, uint32_t& r3) {
    asm volatile("ldmatrix.sync.aligned.m8n8.x4.shared.b16 {%0,%1,%2,%3}, [%4];"
                 : "=r"(r0), "=r"(r1), "=r"(r2), "=r"(r3) : "r"(addr));
}
__device__ __forceinline__ void ldsm4t(uint32_t addr, uint32_t& r0, uint32_t& r1,
                                       uint32_t& r2, uint32_t& r3) {
    asm volatile("ldmatrix.sync.aligned.m8n8.x4.trans.shared.b16 {%0,%1,%2,%3}, [%4];"
                 : "=r"(r0), "=r"(r1), "=r"(r2), "=r"(r3) : "r"(addr));
}
__device__ __forceinline__ void cpa16g(uint32_t dst, const void* src) {
    asm volatile("cp.async.cg.shared.global [%0], [%1], 16;" :: "r"(dst), "l"(src));
}
__device__ __forceinline__ void cp_commitg() {
    asm volatile("cp.async.commit_group;" ::: "memory");
}
#define MMA_F16(d, a, b0v, b1v) \
    asm volatile( \
        "mma.sync.aligned.m16n8k16.row.col.f32.f16.f16.f32 " \
        "{%0,%1,%2,%3},{%4,%5,%6,%7},{%8,%9},{%0,%1,%2,%3};" \
        : "+f"((d)[0]), "+f"((d)[1]), "+f"((d)[2]), "+f"((d)[3]) \
        : "r"((a)[0]), "r"((a)[1]), "r"((a)[2]), "r"((a)[3]), \
          "r"(b0v), "r"(b1v))

__global__ __launch_bounds__(256, 1) void attn_tc(const __half* __restrict__ Qs,
                                                  const __half* __restrict__ Ks,
                                                  const __half* __restrict__ Vs,
                                                  __half* __restrict__ AOcat) {
    extern __shared__ __align__(128) char smc[];
    uint32_t sb = (uint32_t)__cvta_generic_to_shared(smc);

    int tid = threadIdx.x, lane = tid & 31, w = tid >> 5;
    int g = lane >> 2, t = lane & 3;
    int q0 = blockIdx.x * 128;
    int h = blockIdx.y, b = blockIdx.z;

    const __half* Qg = Qs + (size_t)(b * S_DIM + q0) * QROWW + h * 256;
    const __half* Kg = Ks + (size_t)(b * T_DIM) * KVROWW + h * 128;
    const __half* Vg = Vs + (size_t)(b * T_DIM) * KVROWW + h * 128;

    const int NT = T_DIM / 64;  // 34

    // prologue: Q + K0 | V0 | K1 | V1
#pragma unroll
    for (int it = 0; it < 16; it++) {
        int idx = it * 256 + tid;
        int r = idx >> 5, c = (idx & 31) * 8;
        cpa16g(sb + ATT_Q_OFF + sw512o(r, c), Qg + (size_t)r * QROWW + c);
    }
#pragma unroll
    for (int it = 0; it < 4; it++) {
        int idx = it * 256 + tid;
        int r = idx >> 4, c = (idx & 15) * 8;
        cpa16g(sb + ATT_K_OFF + sw256o(r, c), Kg + (size_t)r * KVROWW + c);
    }
    cp_commitg();
#pragma unroll
    for (int it = 0; it < 4; it++) {
        int idx = it * 256 + tid;
        int r = idx >> 4, c = (idx & 15) * 8;
        cpa16g(sb + ATT_V_OFF + sw256o(r, c), Vg + (size_t)r * KVROWW + c);
    }
    cp_commitg();
#pragma unroll
    for (int it = 0; it < 4; it++) {
        int idx = it * 256 + tid;
        int r = idx >> 4, c = (idx & 15) * 8;
        cpa16g(sb + ATT_K_OFF + 16384 + sw256o(r, c),
               Kg + (size_t)(64 + r) * KVROWW + c);
    }
    cp_commitg();
#pragma unroll
    for (int it = 0; it < 4; it++) {
        int idx = it * 256 + tid;
        int r = idx >> 4, c = (idx & 15) * 8;
        cpa16g(sb + ATT_V_OFF + 16384 + sw256o(r, c),
               Vg + (size_t)(64 + r) * KVROWW + c);
    }
    cp_commitg();

    float o[16][4];
#pragma unroll
    for (int nf = 0; nf < 16; nf++)
#pragma unroll
        for (int c = 0; c < 4; c++) o[nf][c] = 0.f;
    float m0 = -1e30f, m8 = -1e30f, l0 = 0.f, l8 = 0.f;

    uint32_t qf[16][4];   // [0..7]=Qh chunks, [8..15]=Ql chunks
    const float scl = 0.08838834764831845f;
    int rg = w * 16 + g;
    int arow_f = w * 16 + ((lane >> 3) & 1) * 8 + (lane & 7);
    int acol_f = ((lane >> 4) & 1) * 8;

    for (int i = 0; i < NT; i++) {
        asm volatile("cp.async.wait_group 2;" ::: "memory");
        __syncthreads();

        if (i == 0) {
#pragma unroll
            for (int kk = 0; kk < 16; kk++)
                ldsm4(sb + ATT_Q_OFF + sw512o(arow_f, kk * 16 + acol_f),
                      qf[kk][0], qf[kk][1], qf[kk][2], qf[kk][3]);
        }

        uint32_t kbuf = sb + ATT_K_OFF + (i & 1) * 16384;
        uint32_t vbuf = sb + ATT_V_OFF + (i & 1) * 16384;

        // ---- QK: 8 chunks, Kh frag reused by Qh and Ql terms ----
        float accs[8][4];
#pragma unroll
        for (int nf = 0; nf < 8; nf++)
#pragma unroll
            for (int c = 0; c < 4; c++) accs[nf][c] = 0.f;

#pragma unroll
        for (int kk = 0; kk < 8; kk++) {
            uint32_t b0[8], b1[8];
#pragma unroll
            for (int nb = 0; nb < 4; nb++) {
                int br = nb * 16 + ((lane >> 3) & 1) * 8 + (lane & 7);
                uint32_t r0, r1, r2, r3;
                ldsm4(kbuf + sw256o(br, kk * 16 + acol_f), r0, r1, r2, r3);
                b0[2 * nb] = r0; b0[2 * nb + 1] = r1;
                b1[2 * nb] = r2; b1[2 * nb + 1] = r3;
            }
#pragma unroll
            for (int nf = 0; nf < 8; nf++)
                MMA_F16(accs[nf], qf[kk], b0[nf], b1[nf]);       // Qh@Kh
#pragma unroll
            for (int nf = 0; nf < 8; nf++)
                MMA_F16(accs[nf], qf[8 + kk], b0[nf], b1[nf]);   // Ql@Kh
        }

        // ---- register-space online softmax, P split fp16 ----
        float mx0 = -1e30f, mx8 = -1e30f;
#pragma unroll
        for (int nf = 0; nf < 8; nf++) {
            accs[nf][0] *= scl; accs[nf][1] *= scl;
            accs[nf][2] *= scl; accs[nf][3] *= scl;
            mx0 = fmaxf(mx0, fmaxf(accs[nf][0], accs[nf][1]));
            mx8 = fmaxf(mx8, fmaxf(accs[nf][2], accs[nf][3]));
        }
        mx0 = fmaxf(mx0, __shfl_xor_sync(0xffffffffu, mx0, 1));
        mx0 = fmaxf(mx0, __shfl_xor_sync(0xffffffffu, mx0, 2));
        mx8 = fmaxf(mx8, __shfl_xor_sync(0xffffffffu, mx8, 1));
        mx8 = fmaxf(mx8, __shfl_xor_sync(0xffffffffu, mx8, 2));
        float mn0 = fmaxf(m0, mx0), mn8 = fmaxf(m8, mx8);
        float al0 = __expf(m0 - mn0), al8 = __expf(m8 - mn8);
        m0 = mn0; m8 = mn8;
        float sum0 = 0.f, sum8 = 0.f;
#pragma unroll
        for (int nf = 0; nf < 8; nf++) {
            int c = nf * 8 + 2 * t;
            float p0 = __expf(accs[nf][0] - mn0);
            float p1 = __expf(accs[nf][1] - mn0);
            sum0 += p0 + p1;
            __half2 ph = __floats2half2_rn(p0, p1);
            __half2 pl = __floats2half2_rn(p0 - __half2float(ph.x),
                                           p1 - __half2float(ph.y));
            *(__half2*)(smc + ATT_P_OFF + sw256o(rg, c)) = ph;
            *(__half2*)(smc + ATT_P_OFF + sw256o(rg, 64 + c)) = pl;
            float p2 = __expf(accs[nf][2] - mn8);
            float p3 = __expf(accs[nf][3] - mn8);
            sum8 += p2 + p3;
            __half2 qh = __floats2half2_rn(p2, p3);
            __half2 ql = __floats2half2_rn(p2 - __half2float(qh.x),
                                           p3 - __half2float(qh.y));
            *(__half2*)(smc + ATT_P_OFF + sw256o(rg + 8, c)) = qh;
            *(__half2*)(smc + ATT_P_OFF + sw256o(rg + 8, 64 + c)) = ql;
        }
        sum0 += __shfl_xor_sync(0xffffffffu, sum0, 1);
        sum0 += __shfl_xor_sync(0xffffffffu, sum0, 2);
        sum8 += __shfl_xor_sync(0xffffffffu, sum8, 1);
        sum8 += __shfl_xor_sync(0xffffffffu, sum8, 2);
        l0 = l0 * al0 + sum0;
        l8 = l8 * al8 + sum8;
#pragma unroll
        for (int nf = 0; nf < 16; nf++) {
            o[nf][0] *= al0; o[nf][1] *= al0;
            o[nf][2] *= al8; o[nf][3] *= al8;
        }
        __syncwarp();

        // ---- PV: 4 v-chunks, Vh frag reused by Ph and Pl terms ----
#pragma unroll
        for (int vv = 0; vv < 4; vv++) {
            uint32_t vb[8][4];
#pragma unroll
            for (int ng = 0; ng < 8; ng++) {
                int vr = vv * 16 + ((lane >> 3) & 1) * 8 + (lane & 7);
                ldsm4t(vbuf + sw256o(vr, ng * 16 + acol_f),
                       vb[ng][0], vb[ng][1], vb[ng][2], vb[ng][3]);
            }
            uint32_t ah[4], al_[4];
            ldsm4(sb + ATT_P_OFF + sw256o(arow_f, vv * 16 + acol_f),
                  ah[0], ah[1], ah[2], ah[3]);
            ldsm4(sb + ATT_P_OFF + sw256o(arow_f, 64 + vv * 16 + acol_f),
                  al_[0], al_[1], al_[2], al_[3]);
#pragma unroll
            for (int ng = 0; ng < 8; ng++) {
                MMA_F16(o[2 * ng], ah, vb[ng][0], vb[ng][1]);
                MMA_F16(o[2 * ng + 1], ah, vb[ng][2], vb[ng][3]);
            }
#pragma unroll
            for (int ng = 0; ng < 8; ng++) {
                MMA_F16(o[2 * ng], al_, vb[ng][0], vb[ng][1]);
                MMA_F16(o[2 * ng + 1], al_, vb[ng][2], vb[ng][3]);
            }
        }
        __syncthreads();

        // ---- prefetch tile i+2 ----
        if (i + 2 < NT) {
            int tK = (i + 2) * 64;
            uint32_t kb2 = sb + ATT_K_OFF + (i & 1) * 16384;
#pragma unroll
            for (int it = 0; it < 4; it++) {
                int idx = it * 256 + tid;
                int r = idx >> 4, c = (idx & 15) * 8;
                cpa16g(kb2 + sw256o(r, c), Kg + (size_t)(tK + r) * KVROWW + c);
            }
        }
        cp_commitg();
        if (i + 2 < NT) {
            int tV = (i + 2) * 64;
            uint32_t vb2 = sb + ATT_V_OFF + (i & 1) * 16384;
#pragma unroll
            for (int it = 0; it < 4; it++) {
                int idx = it * 256 + tid;
                int r = idx >> 4, c = (idx & 15) * 8;
                cpa16g(vb2 + sw256o(r, c), Vg + (size_t)(tV + r) * KVROWW + c);
            }
        }
        cp_commitg();
    }

    // epilogue: normalize, write [AOh|AOl] fp16
    {
        float li0 = __fdiv_rn(1.f, l0);
        float li8 = __fdiv_rn(1.f, l8);
        size_t grow0 = (size_t)(b * S_DIM + q0 + rg) * KA + h * D_DIM;
        size_t grow8 = grow0 + (size_t)8 * KA;
#pragma unroll
        for (int nf = 0; nf < 16; nf++) {
            int c = nf * 8 + 2 * t;
            float f0 = o[nf][0] * li0, f1 = o[nf][1] * li0;
            float f2 = o[nf][2] * li8, f3 = o[nf][3] * li8;
            __half2 h0 = __floats2half2_rn(f0, f1);
            __half2 ll0 = __floats2half2_rn(f0 - __half2float(h0.x),
                                            f1 - __half2float(h0.y));
            __half2 h8 = __floats2half2_rn(f2, f3);
            __half2 ll8 = __floats2half2_rn(f2 - __half2float(h8.x),
                                            f3 - __half2float(h8.y));
            *(__half2*)&AOcat[grow0 + c] = h0;
            *(__half2*)&AOcat[grow0 + E_DIM + c] = ll0;
            *(__half2*)&AOcat[grow8 + c] = h8;
            *(__half2*)&AOcat[grow8 + E_DIM + c] = ll8;
        }
    }
}

// ---------------- launcher ----------------------------------------------------
extern "C" void kernel_launch(void* const* d_in, const int* in_sizes, int n_in,
                              void* d_out, int out_size) {
    const float* x  = (const float*)d_in[0];
    const float* rt = (const float*)d_in[1];
    const float* qw = (const float*)d_in[2];
    const float* kw = (const float*)d_in[3];
    const float* vw = (const float*)d_in[4];
    const float* ow = (const float*)d_in[5];
    const float* ob = (const float*)d_in[6];
    float* out = (float*)d_out;

    __half *p_wb, *p_xb, *p_qs, *p_ks, *p_vs, *p_acat, *p_wcat;
    float *p_as, *p_part, *p_scales;
    cudaGetSymbolAddress((void**)&p_wb, g_wb);
    cudaGetSymbolAddress((void**)&p_xb, g_xb);
    cudaGetSymbolAddress((void**)&p_as, g_as);
    cudaGetSymbolAddress((void**)&p_qs, g_qs);
    cudaGetSymbolAddress((void**)&p_ks, g_ks);
    cudaGetSymbolAddress((void**)&p_vs, g_vs);
    cudaGetSymbolAddress((void**)&p_acat, g_acat);
    cudaGetSymbolAddress((void**)&p_wcat, g_wcat);
    cudaGetSymbolAddress((void**)&p_part, g_part);
    cudaGetSymbolAddress((void**)&p_scales, g_scales);

    const int n = E_DIM * E_DIM;

    // 1. scales + ternary fp16 weights
    absmean3<<<dim3(1024, 3), 256>>>(qw, kw, vw, p_part, n);
    scale_finalize<<<3, 256>>>(p_part, p_scales, 1024, 1.f / (float)n);
    quantw3<<<dim3(2048, 3), 256>>>(qw, kw, vw, p_wb, p_scales, n);

    // 2. activation quant + out_w hi duplicate
    quant_act_k<<<B_DIM * S_DIM, 256>>>(x, p_xb, p_as);
    wsplit_k<<<(n + 255) / 256, 256>>>(ow, p_wcat);

    // 3. QKV projections (fp16 exact-integer GEMM)
    HJobs j1 = {};
    for (int z = 0; z < 6; z++) {
        int w = z >> 1, batch = z & 1;
        j1.A[z] = p_xb + (size_t)batch * S_DIM * E_DIM;
        j1.W[z] = p_wb + (size_t)w * n;
        if (w == 0) {
            j1.C[z] = p_qs + (size_t)batch * S_DIM * QROWW;
            j1.mode[z] = 1;
        } else if (w == 1) {
            j1.C[z] = p_ks + (size_t)batch * T_DIM * KVROWW;
            j1.mode[z] = 2;
        } else {
            j1.C[z] = p_vs + (size_t)batch * T_DIM * KVROWW;
            j1.mode[z] = 2;
        }
        j1.rs[z] = p_as + (size_t)batch * S_DIM;
        j1.ws[z] = p_scales + w;
    }
    j1.bias = nullptr;
    cudaFuncSetAttribute(hgemm_nt, cudaFuncAttributeMaxDynamicSharedMemorySize,
                         65536);
    hgemm_nt<<<dim3(16, 16, 6), 256, 65536>>>(j1, S_DIM, E_DIM, E_DIM);

    // 4. reasoning rk/rv -> single fp16 rows S..T
    GemmJobs j2 = {};
    for (int z = 0; z < 4; z++) {
        int w = z >> 1, batch = z & 1;
        j2.A[z] = rt + (size_t)batch * R_DIM * E_DIM;
        j2.W[z] = (w == 0) ? kw : vw;
        j2.C[z] = ((w == 0) ? p_ks : p_vs) +
                  ((size_t)batch * T_DIM + S_DIM) * KVROWW;
    }
    sgemm_nt64<<<dim3(32, 1, 4), 256>>>(j2, R_DIM, E_DIM, E_DIM);

    // 5. fp16 2-term flash attention -> [AOh|AOl]
    cudaFuncSetAttribute(attn_tc, cudaFuncAttributeMaxDynamicSharedMemorySize,
                         ATT_SMEM);
    attn_tc<<<dim3(S_DIM / 128, H_DIM, B_DIM), 256, ATT_SMEM>>>(p_qs, p_ks, p_vs,
                                                                p_acat);

    // 6. output projection: fp16 2-term GEMM over K'=4096 + bias
    HJobs j3 = {};
    j3.A[0] = p_acat;
    j3.W[0] = p_wcat;
    j3.C[0] = out;
    j3.rs[0] = nullptr;
    j3.ws[0] = nullptr;
    j3.mode[0] = 0;
    j3.bias = ob;
    hgemm_nt<<<dim3(16, 32, 1), 256, 65536>>>(j3, B_DIM * S_DIM, E_DIM, KA);
}

// round 10
// speedup vs baseline: 3.1171x; 1.1688x over previous
#include <cuda_runtime.h>
#include <cuda_fp16.h>
#include <math.h>
#include <stdint.h>

#define E_DIM 2048
#define B_DIM 2
#define S_DIM 2048
#define R_DIM 128
#define H_DIM 16
#define D_DIM 128
#define T_DIM (S_DIM + R_DIM)   /* 2176 */
#define QROWW 4096              /* Q split row: H*256 fp16 */
#define KVROWW 2048             /* K/V single row: H*128 fp16 */

// ---------------- scratch -----------------------------------------------------
__device__ __half g_wb[3][E_DIM * E_DIM];        // ternary weights fp16 (exact)
__device__ __half g_xb[B_DIM * S_DIM * E_DIM];   // int8-valued acts fp16 (exact)
__device__ float g_as[B_DIM * S_DIM];            // per-token 1/s
__device__ __half g_qs[(size_t)B_DIM * S_DIM * QROWW];  // Q split [h][hi|lo]
__device__ __half g_ks[(size_t)B_DIM * T_DIM * KVROWW]; // K single fp16
__device__ __half g_vs[(size_t)B_DIM * T_DIM * KVROWW]; // V single fp16
__device__ __half g_ao[(size_t)B_DIM * S_DIM * E_DIM];  // AO hi only
__device__ __half g_ow[(size_t)E_DIM * E_DIM];          // out_w fp16
__device__ float g_part[3 * 1024];
__device__ float g_scales[3];

// ---------------- prep kernels ------------------------------------------------
__global__ void absmean3(const float* __restrict__ qw, const float* __restrict__ kw,
                         const float* __restrict__ vw, float* __restrict__ part,
                         int n) {
    __shared__ float red[256];
    const float* w = (blockIdx.y == 0) ? qw : (blockIdx.y == 1) ? kw : vw;
    int chunk = n / gridDim.x;
    int base = blockIdx.x * chunk;
    float s = 0.f;
    for (int i = threadIdx.x; i < chunk; i += blockDim.x) s += fabsf(w[base + i]);
    red[threadIdx.x] = s;
    __syncthreads();
    for (int off = 128; off > 0; off >>= 1) {
        if (threadIdx.x < off) red[threadIdx.x] += red[threadIdx.x + off];
        __syncthreads();
    }
    if (threadIdx.x == 0) part[blockIdx.y * 1024 + blockIdx.x] = red[0];
}

__global__ void scale_finalize(const float* __restrict__ part,
                               float* __restrict__ scales, int nblk, float inv_n) {
    __shared__ float red[256];
    const float* p = part + blockIdx.x * nblk;
    float s = 0.f;
    for (int i = threadIdx.x; i < nblk; i += blockDim.x) s += p[i];
    red[threadIdx.x] = s;
    __syncthreads();
    for (int off = 128; off > 0; off >>= 1) {
        if (threadIdx.x < off) red[threadIdx.x] += red[threadIdx.x + off];
        __syncthreads();
    }
    if (threadIdx.x == 0) scales[blockIdx.x] = fmaxf(red[0] * inv_n, 1e-5f);
}

__global__ void quantw3(const float* __restrict__ qw, const float* __restrict__ kw,
                        const float* __restrict__ vw, __half* __restrict__ wb,
                        const float* __restrict__ scales, int n) {
    int s = blockIdx.y;
    const float* w = (s == 0) ? qw : (s == 1) ? kw : vw;
    __half* o = wb + (size_t)s * n;
    float sc = scales[s];
    for (int i = blockIdx.x * blockDim.x + threadIdx.x; i < n;
         i += gridDim.x * blockDim.x) {
        float q = rintf(__fdiv_rn(w[i], sc));
        q = fminf(fmaxf(q, -1.f), 1.f);
        o[i] = __float2half_rn(q);
    }
}

__global__ void quant_act_k(const float* __restrict__ x,
                            __half* __restrict__ xb,
                            float* __restrict__ as_) {
    __shared__ float red[256];
    int row = blockIdx.x;
    const float* xr = x + (size_t)row * E_DIM;
    __half* qr = xb + (size_t)row * E_DIM;
    float m = 0.f;
    for (int i = threadIdx.x; i < E_DIM; i += blockDim.x) m = fmaxf(m, fabsf(xr[i]));
    red[threadIdx.x] = m;
    __syncthreads();
    for (int off = 128; off > 0; off >>= 1) {
        if (threadIdx.x < off)
            red[threadIdx.x] = fmaxf(red[threadIdx.x], red[threadIdx.x + off]);
        __syncthreads();
    }
    float mx = fmaxf(red[0], 1e-5f);
    float s = __fdiv_rn(127.f, mx);
    if (threadIdx.x == 0) as_[row] = __fdiv_rn(1.f, s);
    for (int i = threadIdx.x; i < E_DIM; i += blockDim.x) {
        float q = rintf(xr[i] * s);
        q = fminf(fmaxf(q, -128.f), 127.f);
        qr[i] = __float2half_rn(q);   // |q|<=128 exact in fp16
    }
}

// out_w -> fp16
__global__ void wconv_k(const float* __restrict__ w, __half* __restrict__ wc) {
    int idx = blockIdx.x * blockDim.x + threadIdx.x;
    if (idx < E_DIM * E_DIM) wc[idx] = __float2half_rn(w[idx]);
}

// ---------------- fp16 tensor-core NT GEMM -----------------------------------
// mode 0: fp32 out + bias; mode 1: Q split (hi+lo); mode 2: K/V single fp16
struct HJobs {
    const __half* A[6];
    const __half* W[6];
    void* C[6];
    const float* rs[6];
    const float* ws[6];
    int mode[6];
    const float* bias;
};

__device__ __forceinline__ uint32_t swz(uint32_t o) { return o ^ ((o >> 3) & 0x70); }

__global__ __launch_bounds__(256, 1) void hgemm_nt(HJobs jobs, int M, int N, int K) {
    extern __shared__ __align__(128) char sm_raw[];
    int z = blockIdx.z;
    const __half* A = jobs.A[z];
    const __half* W = jobs.W[z];
    const float* rs = jobs.rs[z];
    const float* ws = jobs.ws[z];
    int mode = jobs.mode[z];

    uint32_t sbase = (uint32_t)__cvta_generic_to_shared(sm_raw);
    int tid = threadIdx.x, lane = tid & 31, warp = tid >> 5;
    int wm = warp >> 1, wn = warp & 1;
    int bm = blockIdx.y * 128, bn = blockIdx.x * 128;

    const __half* Ag = A + (size_t)bm * K;
    const __half* Wg = W + (size_t)bn * K;

    float acc[2][8][4];
#pragma unroll
    for (int mf = 0; mf < 2; mf++)
#pragma unroll
        for (int nf = 0; nf < 8; nf++)
#pragma unroll
            for (int c = 0; c < 4; c++) acc[mf][nf][c] = 0.f;

    float4 sa[4], sw[4];
#pragma unroll
    for (int i = 0; i < 4; i++) {
        int idx = i * 256 + tid;
        int row = idx >> 3, c = idx & 7;
        sa[i] = *(const float4*)(Ag + (size_t)row * K + c * 8);
        sw[i] = *(const float4*)(Wg + (size_t)row * K + c * 8);
    }
#pragma unroll
    for (int i = 0; i < 4; i++) {
        int idx = i * 256 + tid;
        int row = idx >> 3, c = idx & 7;
        uint32_t off = swz((uint32_t)(row * 128 + c * 16));
        *(float4*)(sm_raw + off) = sa[i];
        *(float4*)(sm_raw + 16384 + off) = sw[i];
    }
    __syncthreads();

    int KT = K >> 6;
    for (int kt = 0; kt < KT; kt++) {
        int cur = kt & 1;
        if (kt + 1 < KT) {
#pragma unroll
            for (int i = 0; i < 4; i++) {
                int idx = i * 256 + tid;
                int row = idx >> 3, c = idx & 7;
                sa[i] = *(const float4*)(Ag + (size_t)row * K + (kt + 1) * 64 + c * 8);
                sw[i] = *(const float4*)(Wg + (size_t)row * K + (kt + 1) * 64 + c * 8);
            }
        }
        uint32_t abase = sbase + cur * 32768;
        uint32_t wbase = abase + 16384;
#pragma unroll
        for (int ks = 0; ks < 4; ks++) {
            uint32_t a[2][4];
#pragma unroll
            for (int mf = 0; mf < 2; mf++) {
                int r = wm * 32 + mf * 16 + ((lane >> 3) & 1) * 8 + (lane & 7);
                uint32_t off = swz((uint32_t)(r * 128 + ks * 32 + ((lane >> 4) & 1) * 16));
                asm volatile(
                    "ldmatrix.sync.aligned.m8n8.x4.shared.b16 {%0,%1,%2,%3}, [%4];"
                    : "=r"(a[mf][0]), "=r"(a[mf][1]), "=r"(a[mf][2]), "=r"(a[mf][3])
                    : "r"(abase + off));
            }
            uint32_t b0[8], b1[8];
#pragma unroll
            for (int q = 0; q < 4; q++) {
                int r = wn * 64 + q * 16 + ((lane >> 3) & 1) * 8 + (lane & 7);
                uint32_t off = swz((uint32_t)(r * 128 + ks * 32 + ((lane >> 4) & 1) * 16));
                uint32_t r0, r1, r2, r3;
                asm volatile(
                    "ldmatrix.sync.aligned.m8n8.x4.shared.b16 {%0,%1,%2,%3}, [%4];"
                    : "=r"(r0), "=r"(r1), "=r"(r2), "=r"(r3)
                    : "r"(wbase + off));
                b0[2 * q] = r0; b0[2 * q + 1] = r1;
                b1[2 * q] = r2; b1[2 * q + 1] = r3;
            }
#pragma unroll
            for (int mf = 0; mf < 2; mf++)
#pragma unroll
                for (int nf = 0; nf < 8; nf++)
                    asm volatile(
                        "mma.sync.aligned.m16n8k16.row.col.f32.f16.f16.f32 "
                        "{%0,%1,%2,%3},{%4,%5,%6,%7},{%8,%9},{%0,%1,%2,%3};"
                        : "+f"(acc[mf][nf][0]), "+f"(acc[mf][nf][1]),
                          "+f"(acc[mf][nf][2]), "+f"(acc[mf][nf][3])
                        : "r"(a[mf][0]), "r"(a[mf][1]), "r"(a[mf][2]), "r"(a[mf][3]),
                          "r"(b0[nf]), "r"(b1[nf]));
        }
        if (kt + 1 < KT) {
            int nxt = cur ^ 1;
#pragma unroll
            for (int i = 0; i < 4; i++) {
                int idx = i * 256 + tid;
                int row = idx >> 3, c = idx & 7;
                uint32_t off = swz((uint32_t)(row * 128 + c * 16));
                *(float4*)(sm_raw + nxt * 32768 + off) = sa[i];
                *(float4*)(sm_raw + nxt * 32768 + 16384 + off) = sw[i];
            }
        }
        __syncthreads();
    }

    int g = lane >> 2, t = lane & 3;
    float wsv = ws ? *ws : 1.f;
    if (mode == 1) {
        __half* Ob = (__half*)jobs.C[z];
#pragma unroll
        for (int mf = 0; mf < 2; mf++) {
            int row0 = bm + wm * 32 + mf * 16 + g;
            float r0s = rs[row0] * wsv;
            float r1s = rs[row0 + 8] * wsv;
#pragma unroll
            for (int nf = 0; nf < 8; nf++) {
                int col = bn + wn * 64 + nf * 8 + 2 * t;
                int hh = col >> 7, d = col & 127;
                size_t i0 = (size_t)row0 * QROWW + hh * 256 + d;
                size_t i8 = (size_t)(row0 + 8) * QROWW + hh * 256 + d;
                float v0 = acc[mf][nf][0] * r0s, v1 = acc[mf][nf][1] * r0s;
                float v2 = acc[mf][nf][2] * r1s, v3 = acc[mf][nf][3] * r1s;
                __half2 h0 = __floats2half2_rn(v0, v1);
                __half2 l0 = __floats2half2_rn(v0 - __half2float(h0.x),
                                               v1 - __half2float(h0.y));
                __half2 h8 = __floats2half2_rn(v2, v3);
                __half2 l8 = __floats2half2_rn(v2 - __half2float(h8.x),
                                               v3 - __half2float(h8.y));
                *(__half2*)&Ob[i0] = h0;
                *(__half2*)&Ob[i0 + 128] = l0;
                *(__half2*)&Ob[i8] = h8;
                *(__half2*)&Ob[i8 + 128] = l8;
            }
        }
    } else if (mode == 2) {
        __half* Ob = (__half*)jobs.C[z];
#pragma unroll
        for (int mf = 0; mf < 2; mf++) {
            int row0 = bm + wm * 32 + mf * 16 + g;
            float r0s = rs[row0] * wsv;
            float r1s = rs[row0 + 8] * wsv;
#pragma unroll
            for (int nf = 0; nf < 8; nf++) {
                int col = bn + wn * 64 + nf * 8 + 2 * t;
                int hh = col >> 7, d = col & 127;
                size_t i0 = (size_t)row0 * KVROWW + hh * 128 + d;
                size_t i8 = (size_t)(row0 + 8) * KVROWW + hh * 128 + d;
                *(__half2*)&Ob[i0] = __floats2half2_rn(acc[mf][nf][0] * r0s,
                                                       acc[mf][nf][1] * r0s);
                *(__half2*)&Ob[i8] = __floats2half2_rn(acc[mf][nf][2] * r1s,
                                                       acc[mf][nf][3] * r1s);
            }
        }
    } else {
        float* C = (float*)jobs.C[z];
        const float* bias = jobs.bias;
#pragma unroll
        for (int mf = 0; mf < 2; mf++) {
            int row0 = bm + wm * 32 + mf * 16 + g;
#pragma unroll
            for (int nf = 0; nf < 8; nf++) {
                int col = bn + wn * 64 + nf * 8 + 2 * t;
                float b0v = bias ? bias[col] : 0.f;
                float b1v = bias ? bias[col + 1] : 0.f;
                float2 v0 = make_float2(acc[mf][nf][0] + b0v, acc[mf][nf][1] + b1v);
                float2 v1 = make_float2(acc[mf][nf][2] + b0v, acc[mf][nf][3] + b1v);
                *(float2*)&C[(size_t)row0 * N + col] = v0;
                *(float2*)&C[(size_t)(row0 + 8) * N + col] = v1;
            }
        }
    }
}

// ---------------- fp32 NT SGEMM 128x64 (rk/rv) -> single fp16 out -------------
struct GemmJobs {
    const float* A[4];
    const float* W[4];
    __half* C[4];
};

__global__ __launch_bounds__(256) void sgemm_nt64(GemmJobs jobs, int M, int N, int K) {
    __shared__ __align__(16) float As[128][20];
    __shared__ __align__(16) float Ws[64][20];
    const float* A = jobs.A[blockIdx.z];
    const float* W = jobs.W[blockIdx.z];
    __half* C = jobs.C[blockIdx.z];
    int tid = threadIdx.x;
    int tx = tid & 15, ty = tid >> 4;
    int bn = blockIdx.x * 64;

    float acc[8][4];
#pragma unroll
    for (int i = 0; i < 8; i++)
#pragma unroll
        for (int j = 0; j < 4; j++) acc[i][j] = 0.f;

    for (int kt = 0; kt < K; kt += 16) {
#pragma unroll
        for (int it = 0; it < 2; it++) {
            int idx = tid + it * 256;
            int row = idx >> 2, k4 = (idx & 3) * 4;
            *(float4*)&As[row][k4] =
                *(const float4*)&A[(size_t)row * K + kt + k4];
        }
        {
            int row = tid >> 2, k4 = (tid & 3) * 4;
            *(float4*)&Ws[row][k4] =
                *(const float4*)&W[(size_t)(bn + row) * K + kt + k4];
        }
        __syncthreads();
#pragma unroll
        for (int k4 = 0; k4 < 16; k4 += 4) {
            float4 a[8], b[4];
#pragma unroll
            for (int i = 0; i < 8; i++) a[i] = *(float4*)&As[ty + 16 * i][k4];
#pragma unroll
            for (int j = 0; j < 4; j++) b[j] = *(float4*)&Ws[tx + 16 * j][k4];
#pragma unroll
            for (int i = 0; i < 8; i++)
#pragma unroll
                for (int j = 0; j < 4; j++)
                    acc[i][j] += a[i].x * b[j].x + a[i].y * b[j].y +
                                 a[i].z * b[j].z + a[i].w * b[j].w;
        }
        __syncthreads();
    }
#pragma unroll
    for (int i = 0; i < 8; i++) {
        int r = ty + 16 * i;
#pragma unroll
        for (int j = 0; j < 4; j++) {
            int n = bn + tx + 16 * j;
            int hh = n >> 7, d = n & 127;
            C[(size_t)r * KVROWW + hh * 128 + d] = __float2half_rn(acc[i][j]);
        }
    }
}

// ---------------- fp16 flash attention (2-term QK, 1-term PV) -----------------
#define ATT_Q_OFF 0            /* [128][512B] = 64KB */
#define ATT_K_OFF 65536        /* 2 x [64][256B] = 32KB */
#define ATT_V_OFF 98304        /* 2 x [64][256B] = 32KB */
#define ATT_P_OFF 131072       /* [128][256B] = 32KB (Ph only, cols 0..127) */
#define ATT_SMEM 163840

__device__ __forceinline__ uint32_t sw512o(int r, int c) {
    return (uint32_t)(r * 512 + ((((c >> 3) ^ (r & 7))) << 4) + ((c & 7) << 1));
}
__device__ __forceinline__ uint32_t sw256o(int r, int c) {
    return (uint32_t)(r * 256 + ((((c >> 3) ^ (r & 7))) << 4) + ((c & 7) << 1));
}
__device__ __forceinline__ void ldsm4(uint32_t addr, uint32_t& r0, uint32_t& r1,
                                      uint32_t& r2, uint32_t& r3) {
    asm volatile("ldmatrix.sync.aligned.m8n8.x4.shared.b16 {%0,%1,%2,%3}, [%4];"
                 : "=r"(r0), "=r"(r1), "=r"(r2), "=r"(r3) : "r"(addr));
}
__device__ __forceinline__ void ldsm4t(uint32_t addr, uint32_t& r0, uint32_t& r1,
                                       uint32_t& r2, uint32_t& r3) {
    asm volatile("ldmatrix.sync.aligned.m8n8.x4.trans.shared.b16 {%0,%1,%2,%3}, [%4];"
                 : "=r"(r0), "=r"(r1), "=r"(r2), "=r"(r3) : "r"(addr));
}
__device__ __forceinline__ void cpa16g(uint32_t dst, const void* src) {
    asm volatile("cp.async.cg.shared.global [%0], [%1], 16;" :: "r"(dst), "l"(src));
}
__device__ __forceinline__ void cp_commitg() {
    asm volatile("cp.async.commit_group;" ::: "memory");
}
#define MMA_F16(d, a, b0v, b1v) \
    asm volatile( \
        "mma.sync.aligned.m16n8k16.row.col.f32.f16.f16.f32 " \
        "{%0,%1,%2,%3},{%4,%5,%6,%7},{%8,%9},{%0,%1,%2,%3};" \
        : "+f"((d)[0]), "+f"((d)[1]), "+f"((d)[2]), "+f"((d)[3]) \
        : "r"((a)[0]), "r"((a)[1]), "r"((a)[2]), "r"((a)[3]), \
          "r"(b0v), "r"(b1v))

__global__ __launch_bounds__(256, 1) void attn_tc(const __half* __restrict__ Qs,
                                                  const __half* __restrict__ Ks,
                                                  const __half* __restrict__ Vs,
                                                  __half* __restrict__ AO) {
    extern __shared__ __align__(128) char smc[];
    uint32_t sb = (uint32_t)__cvta_generic_to_shared(smc);

    int tid = threadIdx.x, lane = tid & 31, w = tid >> 5;
    int g = lane >> 2, t = lane & 3;
    int q0 = blockIdx.x * 128;
    int h = blockIdx.y, b = blockIdx.z;

    const __half* Qg = Qs + (size_t)(b * S_DIM + q0) * QROWW + h * 256;
    const __half* Kg = Ks + (size_t)(b * T_DIM) * KVROWW + h * 128;
    const __half* Vg = Vs + (size_t)(b * T_DIM) * KVROWW + h * 128;

    const int NT = T_DIM / 64;  // 34

    // prologue: Q + K0 | V0 | K1 | V1
#pragma unroll
    for (int it = 0; it < 16; it++) {
        int idx = it * 256 + tid;
        int r = idx >> 5, c = (idx & 31) * 8;
        cpa16g(sb + ATT_Q_OFF + sw512o(r, c), Qg + (size_t)r * QROWW + c);
    }
#pragma unroll
    for (int it = 0; it < 4; it++) {
        int idx = it * 256 + tid;
        int r = idx >> 4, c = (idx & 15) * 8;
        cpa16g(sb + ATT_K_OFF + sw256o(r, c), Kg + (size_t)r * KVROWW + c);
    }
    cp_commitg();
#pragma unroll
    for (int it = 0; it < 4; it++) {
        int idx = it * 256 + tid;
        int r = idx >> 4, c = (idx & 15) * 8;
        cpa16g(sb + ATT_V_OFF + sw256o(r, c), Vg + (size_t)r * KVROWW + c);
    }
    cp_commitg();
#pragma unroll
    for (int it = 0; it < 4; it++) {
        int idx = it * 256 + tid;
        int r = idx >> 4, c = (idx & 15) * 8;
        cpa16g(sb + ATT_K_OFF + 16384 + sw256o(r, c),
               Kg + (size_t)(64 + r) * KVROWW + c);
    }
    cp_commitg();
#pragma unroll
    for (int it = 0; it < 4; it++) {
        int idx = it * 256 + tid;
        int r = idx >> 4, c = (idx & 15) * 8;
        cpa16g(sb + ATT_V_OFF + 16384 + sw256o(r, c),
               Vg + (size_t)(64 + r) * KVROWW + c);
    }
    cp_commitg();

    float o[16][4];
#pragma unroll
    for (int nf = 0; nf < 16; nf++)
#pragma unroll
        for (int c = 0; c < 4; c++) o[nf][c] = 0.f;
    float m0 = -1e30f, m8 = -1e30f, l0 = 0.f, l8 = 0.f;

    uint32_t qf[16][4];   // [0..7]=Qh chunks, [8..15]=Ql chunks
    const float scl = 0.08838834764831845f;
    int rg = w * 16 + g;
    int arow_f = w * 16 + ((lane >> 3) & 1) * 8 + (lane & 7);
    int acol_f = ((lane >> 4) & 1) * 8;

    for (int i = 0; i < NT; i++) {
        asm volatile("cp.async.wait_group 2;" ::: "memory");
        __syncthreads();

        if (i == 0) {
#pragma unroll
            for (int kk = 0; kk < 16; kk++)
                ldsm4(sb + ATT_Q_OFF + sw512o(arow_f, kk * 16 + acol_f),
                      qf[kk][0], qf[kk][1], qf[kk][2], qf[kk][3]);
        }

        uint32_t kbuf = sb + ATT_K_OFF + (i & 1) * 16384;
        uint32_t vbuf = sb + ATT_V_OFF + (i & 1) * 16384;

        // ---- QK: 8 chunks, Kh frag reused by Qh and Ql terms ----
        float accs[8][4];
#pragma unroll
        for (int nf = 0; nf < 8; nf++)
#pragma unroll
            for (int c = 0; c < 4; c++) accs[nf][c] = 0.f;

#pragma unroll
        for (int kk = 0; kk < 8; kk++) {
            uint32_t b0[8], b1[8];
#pragma unroll
            for (int nb = 0; nb < 4; nb++) {
                int br = nb * 16 + ((lane >> 3) & 1) * 8 + (lane & 7);
                uint32_t r0, r1, r2, r3;
                ldsm4(kbuf + sw256o(br, kk * 16 + acol_f), r0, r1, r2, r3);
                b0[2 * nb] = r0; b0[2 * nb + 1] = r1;
                b1[2 * nb] = r2; b1[2 * nb + 1] = r3;
            }
#pragma unroll
            for (int nf = 0; nf < 8; nf++)
                MMA_F16(accs[nf], qf[kk], b0[nf], b1[nf]);       // Qh@Kh
#pragma unroll
            for (int nf = 0; nf < 8; nf++)
                MMA_F16(accs[nf], qf[8 + kk], b0[nf], b1[nf]);   // Ql@Kh
        }

        // ---- register-space online softmax, Ph-only fp16 ----
        float mx0 = -1e30f, mx8 = -1e30f;
#pragma unroll
        for (int nf = 0; nf < 8; nf++) {
            accs[nf][0] *= scl; accs[nf][1] *= scl;
            accs[nf][2] *= scl; accs[nf][3] *= scl;
            mx0 = fmaxf(mx0, fmaxf(accs[nf][0], accs[nf][1]));
            mx8 = fmaxf(mx8, fmaxf(accs[nf][2], accs[nf][3]));
        }
        mx0 = fmaxf(mx0, __shfl_xor_sync(0xffffffffu, mx0, 1));
        mx0 = fmaxf(mx0, __shfl_xor_sync(0xffffffffu, mx0, 2));
        mx8 = fmaxf(mx8, __shfl_xor_sync(0xffffffffu, mx8, 1));
        mx8 = fmaxf(mx8, __shfl_xor_sync(0xffffffffu, mx8, 2));
        float mn0 = fmaxf(m0, mx0), mn8 = fmaxf(m8, mx8);
        float al0 = __expf(m0 - mn0), al8 = __expf(m8 - mn8);
        m0 = mn0; m8 = mn8;
        float sum0 = 0.f, sum8 = 0.f;
#pragma unroll
        for (int nf = 0; nf < 8; nf++) {
            int c = nf * 8 + 2 * t;
            float p0 = __expf(accs[nf][0] - mn0);
            float p1 = __expf(accs[nf][1] - mn0);
            sum0 += p0 + p1;
            *(__half2*)(smc + ATT_P_OFF + sw256o(rg, c)) = __floats2half2_rn(p0, p1);
            float p2 = __expf(accs[nf][2] - mn8);
            float p3 = __expf(accs[nf][3] - mn8);
            sum8 += p2 + p3;
            *(__half2*)(smc + ATT_P_OFF + sw256o(rg + 8, c)) =
                __floats2half2_rn(p2, p3);
        }
        sum0 += __shfl_xor_sync(0xffffffffu, sum0, 1);
        sum0 += __shfl_xor_sync(0xffffffffu, sum0, 2);
        sum8 += __shfl_xor_sync(0xffffffffu, sum8, 1);
        sum8 += __shfl_xor_sync(0xffffffffu, sum8, 2);
        l0 = l0 * al0 + sum0;
        l8 = l8 * al8 + sum8;
#pragma unroll
        for (int nf = 0; nf < 16; nf++) {
            o[nf][0] *= al0; o[nf][1] *= al0;
            o[nf][2] *= al8; o[nf][3] *= al8;
        }
        __syncwarp();

        // ---- PV: 4 v-chunks, Ph only ----
#pragma unroll
        for (int vv = 0; vv < 4; vv++) {
            uint32_t vb[8][4];
#pragma unroll
            for (int ng = 0; ng < 8; ng++) {
                int vr = vv * 16 + ((lane >> 3) & 1) * 8 + (lane & 7);
                ldsm4t(vbuf + sw256o(vr, ng * 16 + acol_f),
                       vb[ng][0], vb[ng][1], vb[ng][2], vb[ng][3]);
            }
            uint32_t ah[4];
            ldsm4(sb + ATT_P_OFF + sw256o(arow_f, vv * 16 + acol_f),
                  ah[0], ah[1], ah[2], ah[3]);
#pragma unroll
            for (int ng = 0; ng < 8; ng++) {
                MMA_F16(o[2 * ng], ah, vb[ng][0], vb[ng][1]);
                MMA_F16(o[2 * ng + 1], ah, vb[ng][2], vb[ng][3]);
            }
        }
        __syncthreads();

        // ---- prefetch tile i+2 ----
        if (i + 2 < NT) {
            int tK = (i + 2) * 64;
            uint32_t kb2 = sb + ATT_K_OFF + (i & 1) * 16384;
#pragma unroll
            for (int it = 0; it < 4; it++) {
                int idx = it * 256 + tid;
                int r = idx >> 4, c = (idx & 15) * 8;
                cpa16g(kb2 + sw256o(r, c), Kg + (size_t)(tK + r) * KVROWW + c);
            }
        }
        cp_commitg();
        if (i + 2 < NT) {
            int tV = (i + 2) * 64;
            uint32_t vb2 = sb + ATT_V_OFF + (i & 1) * 16384;
#pragma unroll
            for (int it = 0; it < 4; it++) {
                int idx = it * 256 + tid;
                int r = idx >> 4, c = (idx & 15) * 8;
                cpa16g(vb2 + sw256o(r, c), Vg + (size_t)(tV + r) * KVROWW + c);
            }
        }
        cp_commitg();
    }

    // epilogue: normalize, write AO hi fp16 at [token][E]
    {
        float li0 = __fdiv_rn(1.f, l0);
        float li8 = __fdiv_rn(1.f, l8);
        size_t grow0 = (size_t)(b * S_DIM + q0 + rg) * E_DIM + h * D_DIM;
        size_t grow8 = grow0 + (size_t)8 * E_DIM;
#pragma unroll
        for (int nf = 0; nf < 16; nf++) {
            int c = nf * 8 + 2 * t;
            *(__half2*)&AO[grow0 + c] =
                __floats2half2_rn(o[nf][0] * li0, o[nf][1] * li0);
            *(__half2*)&AO[grow8 + c] =
                __floats2half2_rn(o[nf][2] * li8, o[nf][3] * li8);
        }
    }
}

// ---------------- launcher ----------------------------------------------------
extern "C" void kernel_launch(void* const* d_in, const int* in_sizes, int n_in,
                              void* d_out, int out_size) {
    const float* x  = (const float*)d_in[0];
    const float* rt = (const float*)d_in[1];
    const float* qw = (const float*)d_in[2];
    const float* kw = (const float*)d_in[3];
    const float* vw = (const float*)d_in[4];
    const float* ow = (const float*)d_in[5];
    const float* ob = (const float*)d_in[6];
    float* out = (float*)d_out;

    __half *p_wb, *p_xb, *p_qs, *p_ks, *p_vs, *p_ao, *p_ow;
    float *p_as, *p_part, *p_scales;
    cudaGetSymbolAddress((void**)&p_wb, g_wb);
    cudaGetSymbolAddress((void**)&p_xb, g_xb);
    cudaGetSymbolAddress((void**)&p_as, g_as);
    cudaGetSymbolAddress((void**)&p_qs, g_qs);
    cudaGetSymbolAddress((void**)&p_ks, g_ks);
    cudaGetSymbolAddress((void**)&p_vs, g_vs);
    cudaGetSymbolAddress((void**)&p_ao, g_ao);
    cudaGetSymbolAddress((void**)&p_ow, g_ow);
    cudaGetSymbolAddress((void**)&p_part, g_part);
    cudaGetSymbolAddress((void**)&p_scales, g_scales);

    const int n = E_DIM * E_DIM;

    // 1. scales + ternary fp16 weights
    absmean3<<<dim3(1024, 3), 256>>>(qw, kw, vw, p_part, n);
    scale_finalize<<<3, 256>>>(p_part, p_scales, 1024, 1.f / (float)n);
    quantw3<<<dim3(2048, 3), 256>>>(qw, kw, vw, p_wb, p_scales, n);

    // 2. activation quant + out_w convert
    quant_act_k<<<B_DIM * S_DIM, 256>>>(x, p_xb, p_as);
    wconv_k<<<(n + 255) / 256, 256>>>(ow, p_ow);

    // 3. QKV projections (fp16 exact-integer GEMM)
    HJobs j1 = {};
    for (int z = 0; z < 6; z++) {
        int w = z >> 1, batch = z & 1;
        j1.A[z] = p_xb + (size_t)batch * S_DIM * E_DIM;
        j1.W[z] = p_wb + (size_t)w * n;
        if (w == 0) {
            j1.C[z] = p_qs + (size_t)batch * S_DIM * QROWW;
            j1.mode[z] = 1;
        } else if (w == 1) {
            j1.C[z] = p_ks + (size_t)batch * T_DIM * KVROWW;
            j1.mode[z] = 2;
        } else {
            j1.C[z] = p_vs + (size_t)batch * T_DIM * KVROWW;
            j1.mode[z] = 2;
        }
        j1.rs[z] = p_as + (size_t)batch * S_DIM;
        j1.ws[z] = p_scales + w;
    }
    j1.bias = nullptr;
    cudaFuncSetAttribute(hgemm_nt, cudaFuncAttributeMaxDynamicSharedMemorySize,
                         65536);
    hgemm_nt<<<dim3(16, 16, 6), 256, 65536>>>(j1, S_DIM, E_DIM, E_DIM);

    // 4. reasoning rk/rv -> single fp16 rows S..T
    GemmJobs j2 = {};
    for (int z = 0; z < 4; z++) {
        int w = z >> 1, batch = z & 1;
        j2.A[z] = rt + (size_t)batch * R_DIM * E_DIM;
        j2.W[z] = (w == 0) ? kw : vw;
        j2.C[z] = ((w == 0) ? p_ks : p_vs) +
                  ((size_t)batch * T_DIM + S_DIM) * KVROWW;
    }
    sgemm_nt64<<<dim3(32, 1, 4), 256>>>(j2, R_DIM, E_DIM, E_DIM);

    // 5. fp16 flash attention (2-term QK, 1-term PV) -> AO hi
    cudaFuncSetAttribute(attn_tc, cudaFuncAttributeMaxDynamicSharedMemorySize,
                         ATT_SMEM);
    attn_tc<<<dim3(S_DIM / 128, H_DIM, B_DIM), 256, ATT_SMEM>>>(p_qs, p_ks, p_vs,
                                                                p_ao);

    // 6. output projection: single fp16 GEMM over K=2048 + bias
    HJobs j3 = {};
    j3.A[0] = p_ao;
    j3.W[0] = p_ow;
    j3.C[0] = out;
    j3.rs[0] = nullptr;
    j3.ws[0] = nullptr;
    j3.mode[0] = 0;
    j3.bias = ob;
    hgemm_nt<<<dim3(16, 32, 1), 256, 65536>>>(j3, B_DIM * S_DIM, E_DIM, E_DIM);
}

// round 11
// speedup vs baseline: 3.3654x; 1.0796x over previous
#include <cuda_runtime.h>
#include <cuda_fp16.h>
#include <math.h>
#include <stdint.h>

#define E_DIM 2048
#define B_DIM 2
#define S_DIM 2048
#define R_DIM 128
#define H_DIM 16
#define D_DIM 128
#define T_DIM (S_DIM + R_DIM)   /* 2176 */
#define KVROWW 2048             /* Q/K/V row: H*128 fp16 */

// ---------------- scratch -----------------------------------------------------
__device__ __half g_wb[3][E_DIM * E_DIM];        // ternary weights fp16 (exact)
__device__ __half g_xb[B_DIM * S_DIM * E_DIM];   // int8-valued acts fp16 (exact)
__device__ float g_as[B_DIM * S_DIM];            // per-token 1/s
__device__ __half g_qs[(size_t)B_DIM * S_DIM * KVROWW]; // Q fp16
__device__ __half g_ks[(size_t)B_DIM * T_DIM * KVROWW]; // K fp16
__device__ __half g_vs[(size_t)B_DIM * T_DIM * KVROWW]; // V fp16
__device__ __half g_ao[(size_t)B_DIM * S_DIM * E_DIM];  // AO fp16
__device__ __half g_ow[(size_t)E_DIM * E_DIM];          // out_w fp16
__device__ float g_part[3 * 1024];
__device__ float g_scales[3];

// ---------------- prep kernels ------------------------------------------------
__global__ void absmean3(const float* __restrict__ qw, const float* __restrict__ kw,
                         const float* __restrict__ vw, float* __restrict__ part,
                         int n) {
    __shared__ float red[256];
    const float* w = (blockIdx.y == 0) ? qw : (blockIdx.y == 1) ? kw : vw;
    int chunk = n / gridDim.x;
    int base = blockIdx.x * chunk;
    float s = 0.f;
    for (int i = threadIdx.x; i < chunk; i += blockDim.x) s += fabsf(w[base + i]);
    red[threadIdx.x] = s;
    __syncthreads();
    for (int off = 128; off > 0; off >>= 1) {
        if (threadIdx.x < off) red[threadIdx.x] += red[threadIdx.x + off];
        __syncthreads();
    }
    if (threadIdx.x == 0) part[blockIdx.y * 1024 + blockIdx.x] = red[0];
}

__global__ void scale_finalize(const float* __restrict__ part,
                               float* __restrict__ scales, int nblk, float inv_n) {
    __shared__ float red[256];
    const float* p = part + blockIdx.x * nblk;
    float s = 0.f;
    for (int i = threadIdx.x; i < nblk; i += blockDim.x) s += p[i];
    red[threadIdx.x] = s;
    __syncthreads();
    for (int off = 128; off > 0; off >>= 1) {
        if (threadIdx.x < off) red[threadIdx.x] += red[threadIdx.x + off];
        __syncthreads();
    }
    if (threadIdx.x == 0) scales[blockIdx.x] = fmaxf(red[0] * inv_n, 1e-5f);
}

__global__ void quantw3(const float* __restrict__ qw, const float* __restrict__ kw,
                        const float* __restrict__ vw, __half* __restrict__ wb,
                        const float* __restrict__ scales, int n) {
    int s = blockIdx.y;
    const float* w = (s == 0) ? qw : (s == 1) ? kw : vw;
    __half* o = wb + (size_t)s * n;
    float sc = scales[s];
    for (int i = blockIdx.x * blockDim.x + threadIdx.x; i < n;
         i += gridDim.x * blockDim.x) {
        float q = rintf(__fdiv_rn(w[i], sc));
        q = fminf(fmaxf(q, -1.f), 1.f);
        o[i] = __float2half_rn(q);
    }
}

__global__ void quant_act_k(const float* __restrict__ x,
                            __half* __restrict__ xb,
                            float* __restrict__ as_) {
    __shared__ float red[256];
    int row = blockIdx.x;
    const float* xr = x + (size_t)row * E_DIM;
    __half* qr = xb + (size_t)row * E_DIM;
    float m = 0.f;
    for (int i = threadIdx.x; i < E_DIM; i += blockDim.x) m = fmaxf(m, fabsf(xr[i]));
    red[threadIdx.x] = m;
    __syncthreads();
    for (int off = 128; off > 0; off >>= 1) {
        if (threadIdx.x < off)
            red[threadIdx.x] = fmaxf(red[threadIdx.x], red[threadIdx.x + off]);
        __syncthreads();
    }
    float mx = fmaxf(red[0], 1e-5f);
    float s = __fdiv_rn(127.f, mx);
    if (threadIdx.x == 0) as_[row] = __fdiv_rn(1.f, s);
    for (int i = threadIdx.x; i < E_DIM; i += blockDim.x) {
        float q = rintf(xr[i] * s);
        q = fminf(fmaxf(q, -128.f), 127.f);
        qr[i] = __float2half_rn(q);   // |q|<=128 exact in fp16
    }
}

__global__ void wconv_k(const float* __restrict__ w, __half* __restrict__ wc) {
    int idx = blockIdx.x * blockDim.x + threadIdx.x;
    if (idx < E_DIM * E_DIM) wc[idx] = __float2half_rn(w[idx]);
}

// ---------------- fp16 tensor-core NT GEMM -----------------------------------
// mode 0: fp32 out + bias; mode 2: scaled fp16 out in [token][h*128+d] layout
struct HJobs {
    const __half* A[6];
    const __half* W[6];
    void* C[6];
    const float* rs[6];
    const float* ws[6];
    int mode[6];
    const float* bias;
};

__device__ __forceinline__ uint32_t swz(uint32_t o) { return o ^ ((o >> 3) & 0x70); }

__global__ __launch_bounds__(256, 1) void hgemm_nt(HJobs jobs, int M, int N, int K) {
    extern __shared__ __align__(128) char sm_raw[];
    int z = blockIdx.z;
    const __half* A = jobs.A[z];
    const __half* W = jobs.W[z];
    const float* rs = jobs.rs[z];
    const float* ws = jobs.ws[z];
    int mode = jobs.mode[z];

    uint32_t sbase = (uint32_t)__cvta_generic_to_shared(sm_raw);
    int tid = threadIdx.x, lane = tid & 31, warp = tid >> 5;
    int wm = warp >> 1, wn = warp & 1;
    int bm = blockIdx.y * 128, bn = blockIdx.x * 128;

    const __half* Ag = A + (size_t)bm * K;
    const __half* Wg = W + (size_t)bn * K;

    float acc[2][8][4];
#pragma unroll
    for (int mf = 0; mf < 2; mf++)
#pragma unroll
        for (int nf = 0; nf < 8; nf++)
#pragma unroll
            for (int c = 0; c < 4; c++) acc[mf][nf][c] = 0.f;

    float4 sa[4], sw[4];
#pragma unroll
    for (int i = 0; i < 4; i++) {
        int idx = i * 256 + tid;
        int row = idx >> 3, c = idx & 7;
        sa[i] = *(const float4*)(Ag + (size_t)row * K + c * 8);
        sw[i] = *(const float4*)(Wg + (size_t)row * K + c * 8);
    }
#pragma unroll
    for (int i = 0; i < 4; i++) {
        int idx = i * 256 + tid;
        int row = idx >> 3, c = idx & 7;
        uint32_t off = swz((uint32_t)(row * 128 + c * 16));
        *(float4*)(sm_raw + off) = sa[i];
        *(float4*)(sm_raw + 16384 + off) = sw[i];
    }
    __syncthreads();

    int KT = K >> 6;
    for (int kt = 0; kt < KT; kt++) {
        int cur = kt & 1;
        if (kt + 1 < KT) {
#pragma unroll
            for (int i = 0; i < 4; i++) {
                int idx = i * 256 + tid;
                int row = idx >> 3, c = idx & 7;
                sa[i] = *(const float4*)(Ag + (size_t)row * K + (kt + 1) * 64 + c * 8);
                sw[i] = *(const float4*)(Wg + (size_t)row * K + (kt + 1) * 64 + c * 8);
            }
        }
        uint32_t abase = sbase + cur * 32768;
        uint32_t wbase = abase + 16384;
#pragma unroll
        for (int ks = 0; ks < 4; ks++) {
            uint32_t a[2][4];
#pragma unroll
            for (int mf = 0; mf < 2; mf++) {
                int r = wm * 32 + mf * 16 + ((lane >> 3) & 1) * 8 + (lane & 7);
                uint32_t off = swz((uint32_t)(r * 128 + ks * 32 + ((lane >> 4) & 1) * 16));
                asm volatile(
                    "ldmatrix.sync.aligned.m8n8.x4.shared.b16 {%0,%1,%2,%3}, [%4];"
                    : "=r"(a[mf][0]), "=r"(a[mf][1]), "=r"(a[mf][2]), "=r"(a[mf][3])
                    : "r"(abase + off));
            }
            uint32_t b0[8], b1[8];
#pragma unroll
            for (int q = 0; q < 4; q++) {
                int r = wn * 64 + q * 16 + ((lane >> 3) & 1) * 8 + (lane & 7);
                uint32_t off = swz((uint32_t)(r * 128 + ks * 32 + ((lane >> 4) & 1) * 16));
                uint32_t r0, r1, r2, r3;
                asm volatile(
                    "ldmatrix.sync.aligned.m8n8.x4.shared.b16 {%0,%1,%2,%3}, [%4];"
                    : "=r"(r0), "=r"(r1), "=r"(r2), "=r"(r3)
                    : "r"(wbase + off));
                b0[2 * q] = r0; b0[2 * q + 1] = r1;
                b1[2 * q] = r2; b1[2 * q + 1] = r3;
            }
#pragma unroll
            for (int mf = 0; mf < 2; mf++)
#pragma unroll
                for (int nf = 0; nf < 8; nf++)
                    asm volatile(
                        "mma.sync.aligned.m16n8k16.row.col.f32.f16.f16.f32 "
                        "{%0,%1,%2,%3},{%4,%5,%6,%7},{%8,%9},{%0,%1,%2,%3};"
                        : "+f"(acc[mf][nf][0]), "+f"(acc[mf][nf][1]),
                          "+f"(acc[mf][nf][2]), "+f"(acc[mf][nf][3])
                        : "r"(a[mf][0]), "r"(a[mf][1]), "r"(a[mf][2]), "r"(a[mf][3]),
                          "r"(b0[nf]), "r"(b1[nf]));
        }
        if (kt + 1 < KT) {
            int nxt = cur ^ 1;
#pragma unroll
            for (int i = 0; i < 4; i++) {
                int idx = i * 256 + tid;
                int row = idx >> 3, c = idx & 7;
                uint32_t off = swz((uint32_t)(row * 128 + c * 16));
                *(float4*)(sm_raw + nxt * 32768 + off) = sa[i];
                *(float4*)(sm_raw + nxt * 32768 + 16384 + off) = sw[i];
            }
        }
        __syncthreads();
    }

    int g = lane >> 2, t = lane & 3;
    float wsv = ws ? *ws : 1.f;
    if (mode == 2) {
        __half* Ob = (__half*)jobs.C[z];
#pragma unroll
        for (int mf = 0; mf < 2; mf++) {
            int row0 = bm + wm * 32 + mf * 16 + g;
            float r0s = rs[row0] * wsv;
            float r1s = rs[row0 + 8] * wsv;
#pragma unroll
            for (int nf = 0; nf < 8; nf++) {
                int col = bn + wn * 64 + nf * 8 + 2 * t;
                int hh = col >> 7, d = col & 127;
                size_t i0 = (size_t)row0 * KVROWW + hh * 128 + d;
                size_t i8 = (size_t)(row0 + 8) * KVROWW + hh * 128 + d;
                *(__half2*)&Ob[i0] = __floats2half2_rn(acc[mf][nf][0] * r0s,
                                                       acc[mf][nf][1] * r0s);
                *(__half2*)&Ob[i8] = __floats2half2_rn(acc[mf][nf][2] * r1s,
                                                       acc[mf][nf][3] * r1s);
            }
        }
    } else {
        float* C = (float*)jobs.C[z];
        const float* bias = jobs.bias;
#pragma unroll
        for (int mf = 0; mf < 2; mf++) {
            int row0 = bm + wm * 32 + mf * 16 + g;
#pragma unroll
            for (int nf = 0; nf < 8; nf++) {
                int col = bn + wn * 64 + nf * 8 + 2 * t;
                float b0v = bias ? bias[col] : 0.f;
                float b1v = bias ? bias[col + 1] : 0.f;
                float2 v0 = make_float2(acc[mf][nf][0] + b0v, acc[mf][nf][1] + b1v);
                float2 v1 = make_float2(acc[mf][nf][2] + b0v, acc[mf][nf][3] + b1v);
                *(float2*)&C[(size_t)row0 * N + col] = v0;
                *(float2*)&C[(size_t)(row0 + 8) * N + col] = v1;
            }
        }
    }
}

// ---------------- fp32 NT SGEMM 128x64 (rk/rv) -> single fp16 out -------------
struct GemmJobs {
    const float* A[4];
    const float* W[4];
    __half* C[4];
};

__global__ __launch_bounds__(256) void sgemm_nt64(GemmJobs jobs, int M, int N, int K) {
    __shared__ __align__(16) float As[128][20];
    __shared__ __align__(16) float Ws[64][20];
    const float* A = jobs.A[blockIdx.z];
    const float* W = jobs.W[blockIdx.z];
    __half* C = jobs.C[blockIdx.z];
    int tid = threadIdx.x;
    int tx = tid & 15, ty = tid >> 4;
    int bn = blockIdx.x * 64;

    float acc[8][4];
#pragma unroll
    for (int i = 0; i < 8; i++)
#pragma unroll
        for (int j = 0; j < 4; j++) acc[i][j] = 0.f;

    for (int kt = 0; kt < K; kt += 16) {
#pragma unroll
        for (int it = 0; it < 2; it++) {
            int idx = tid + it * 256;
            int row = idx >> 2, k4 = (idx & 3) * 4;
            *(float4*)&As[row][k4] =
                *(const float4*)&A[(size_t)row * K + kt + k4];
        }
        {
            int row = tid >> 2, k4 = (tid & 3) * 4;
            *(float4*)&Ws[row][k4] =
                *(const float4*)&W[(size_t)(bn + row) * K + kt + k4];
        }
        __syncthreads();
#pragma unroll
        for (int k4 = 0; k4 < 16; k4 += 4) {
            float4 a[8], b[4];
#pragma unroll
            for (int i = 0; i < 8; i++) a[i] = *(float4*)&As[ty + 16 * i][k4];
#pragma unroll
            for (int j = 0; j < 4; j++) b[j] = *(float4*)&Ws[tx + 16 * j][k4];
#pragma unroll
            for (int i = 0; i < 8; i++)
#pragma unroll
                for (int j = 0; j < 4; j++)
                    acc[i][j] += a[i].x * b[j].x + a[i].y * b[j].y +
                                 a[i].z * b[j].z + a[i].w * b[j].w;
        }
        __syncthreads();
    }
#pragma unroll
    for (int i = 0; i < 8; i++) {
        int r = ty + 16 * i;
#pragma unroll
        for (int j = 0; j < 4; j++) {
            int n = bn + tx + 16 * j;
            int hh = n >> 7, d = n & 127;
            C[(size_t)r * KVROWW + hh * 128 + d] = __float2half_rn(acc[i][j]);
        }
    }
}

// ---------------- fp16 flash attention (single-term) ---------------------------
#define ATT_Q_OFF 0            /* [128][256B] = 32KB */
#define ATT_K_OFF 32768        /* 2 x [64][256B] = 32KB */
#define ATT_V_OFF 65536        /* 2 x [64][256B] = 32KB */
#define ATT_P_OFF 98304        /* [128][256B] = 32KB */
#define ATT_SMEM 131072

__device__ __forceinline__ uint32_t sw256o(int r, int c) {
    return (uint32_t)(r * 256 + ((((c >> 3) ^ (r & 7))) << 4) + ((c & 7) << 1));
}
__device__ __forceinline__ void ldsm4(uint32_t addr, uint32_t& r0, uint32_t& r1,
                                      uint32_t& r2, uint32_t& r3) {
    asm volatile("ldmatrix.sync.aligned.m8n8.x4.shared.b16 {%0,%1,%2,%3}, [%4];"
                 : "=r"(r0), "=r"(r1), "=r"(r2), "=r"(r3) : "r"(addr));
}
__device__ __forceinline__ void ldsm4t(uint32_t addr, uint32_t& r0, uint32_t& r1,
                                       uint32_t& r2, uint32_t& r3) {
    asm volatile("ldmatrix.sync.aligned.m8n8.x4.trans.shared.b16 {%0,%1,%2,%3}, [%4];"
                 : "=r"(r0), "=r"(r1), "=r"(r2), "=r"(r3) : "r"(addr));
}
__device__ __forceinline__ void cpa16g(uint32_t dst, const void* src) {
    asm volatile("cp.async.cg.shared.global [%0], [%1], 16;" :: "r"(dst), "l"(src));
}
__device__ __forceinline__ void cp_commitg() {
    asm volatile("cp.async.commit_group;" ::: "memory");
}
#define MMA_F16(d, a, b0v, b1v) \
    asm volatile( \
        "mma.sync.aligned.m16n8k16.row.col.f32.f16.f16.f32 " \
        "{%0,%1,%2,%3},{%4,%5,%6,%7},{%8,%9},{%0,%1,%2,%3};" \
        : "+f"((d)[0]), "+f"((d)[1]), "+f"((d)[2]), "+f"((d)[3]) \
        : "r"((a)[0]), "r"((a)[1]), "r"((a)[2]), "r"((a)[3]), \
          "r"(b0v), "r"(b1v))

__global__ __launch_bounds__(256, 1) void attn_tc(const __half* __restrict__ Qs,
                                                  const __half* __restrict__ Ks,
                                                  const __half* __restrict__ Vs,
                                                  __half* __restrict__ AO) {
    extern __shared__ __align__(128) char smc[];
    uint32_t sb = (uint32_t)__cvta_generic_to_shared(smc);

    int tid = threadIdx.x, lane = tid & 31, w = tid >> 5;
    int g = lane >> 2, t = lane & 3;
    int q0 = blockIdx.x * 128;
    int h = blockIdx.y, b = blockIdx.z;

    const __half* Qg = Qs + (size_t)(b * S_DIM + q0) * KVROWW + h * 128;
    const __half* Kg = Ks + (size_t)(b * T_DIM) * KVROWW + h * 128;
    const __half* Vg = Vs + (size_t)(b * T_DIM) * KVROWW + h * 128;

    const int NT = T_DIM / 64;  // 34

    // prologue: Q + K0 | V0 | K1 | V1
#pragma unroll
    for (int it = 0; it < 8; it++) {
        int idx = it * 256 + tid;
        int r = idx >> 4, c = (idx & 15) * 8;
        cpa16g(sb + ATT_Q_OFF + sw256o(r, c), Qg + (size_t)r * KVROWW + c);
    }
#pragma unroll
    for (int it = 0; it < 4; it++) {
        int idx = it * 256 + tid;
        int r = idx >> 4, c = (idx & 15) * 8;
        cpa16g(sb + ATT_K_OFF + sw256o(r, c), Kg + (size_t)r * KVROWW + c);
    }
    cp_commitg();
#pragma unroll
    for (int it = 0; it < 4; it++) {
        int idx = it * 256 + tid;
        int r = idx >> 4, c = (idx & 15) * 8;
        cpa16g(sb + ATT_V_OFF + sw256o(r, c), Vg + (size_t)r * KVROWW + c);
    }
    cp_commitg();
#pragma unroll
    for (int it = 0; it < 4; it++) {
        int idx = it * 256 + tid;
        int r = idx >> 4, c = (idx & 15) * 8;
        cpa16g(sb + ATT_K_OFF + 16384 + sw256o(r, c),
               Kg + (size_t)(64 + r) * KVROWW + c);
    }
    cp_commitg();
#pragma unroll
    for (int it = 0; it < 4; it++) {
        int idx = it * 256 + tid;
        int r = idx >> 4, c = (idx & 15) * 8;
        cpa16g(sb + ATT_V_OFF + 16384 + sw256o(r, c),
               Vg + (size_t)(64 + r) * KVROWW + c);
    }
    cp_commitg();

    float o[16][4];
#pragma unroll
    for (int nf = 0; nf < 16; nf++)
#pragma unroll
        for (int c = 0; c < 4; c++) o[nf][c] = 0.f;
    float m0 = -1e30f, m8 = -1e30f, l0 = 0.f, l8 = 0.f;

    uint32_t qf[8][4];   // hoisted Q fragments (8 k-chunks)
    const float scl = 0.08838834764831845f;
    int rg = w * 16 + g;
    int arow_f = w * 16 + ((lane >> 3) & 1) * 8 + (lane & 7);
    int acol_f = ((lane >> 4) & 1) * 8;

    for (int i = 0; i < NT; i++) {
        asm volatile("cp.async.wait_group 2;" ::: "memory");
        __syncthreads();

        if (i == 0) {
#pragma unroll
            for (int kk = 0; kk < 8; kk++)
                ldsm4(sb + ATT_Q_OFF + sw256o(arow_f, kk * 16 + acol_f),
                      qf[kk][0], qf[kk][1], qf[kk][2], qf[kk][3]);
        }

        uint32_t kbuf = sb + ATT_K_OFF + (i & 1) * 16384;
        uint32_t vbuf = sb + ATT_V_OFF + (i & 1) * 16384;

        // ---- QK: 8 k-chunks, single term ----
        float accs[8][4];
#pragma unroll
        for (int nf = 0; nf < 8; nf++)
#pragma unroll
            for (int c = 0; c < 4; c++) accs[nf][c] = 0.f;

#pragma unroll
        for (int kk = 0; kk < 8; kk++) {
            uint32_t b0[8], b1[8];
#pragma unroll
            for (int nb = 0; nb < 4; nb++) {
                int br = nb * 16 + ((lane >> 3) & 1) * 8 + (lane & 7);
                uint32_t r0, r1, r2, r3;
                ldsm4(kbuf + sw256o(br, kk * 16 + acol_f), r0, r1, r2, r3);
                b0[2 * nb] = r0; b0[2 * nb + 1] = r1;
                b1[2 * nb] = r2; b1[2 * nb + 1] = r3;
            }
#pragma unroll
            for (int nf = 0; nf < 8; nf++)
                MMA_F16(accs[nf], qf[kk], b0[nf], b1[nf]);
        }

        // ---- register-space online softmax, Ph fp16 ----
        float mx0 = -1e30f, mx8 = -1e30f;
#pragma unroll
        for (int nf = 0; nf < 8; nf++) {
            accs[nf][0] *= scl; accs[nf][1] *= scl;
            accs[nf][2] *= scl; accs[nf][3] *= scl;
            mx0 = fmaxf(mx0, fmaxf(accs[nf][0], accs[nf][1]));
            mx8 = fmaxf(mx8, fmaxf(accs[nf][2], accs[nf][3]));
        }
        mx0 = fmaxf(mx0, __shfl_xor_sync(0xffffffffu, mx0, 1));
        mx0 = fmaxf(mx0, __shfl_xor_sync(0xffffffffu, mx0, 2));
        mx8 = fmaxf(mx8, __shfl_xor_sync(0xffffffffu, mx8, 1));
        mx8 = fmaxf(mx8, __shfl_xor_sync(0xffffffffu, mx8, 2));
        float mn0 = fmaxf(m0, mx0), mn8 = fmaxf(m8, mx8);
        float al0 = __expf(m0 - mn0), al8 = __expf(m8 - mn8);
        m0 = mn0; m8 = mn8;
        float sum0 = 0.f, sum8 = 0.f;
#pragma unroll
        for (int nf = 0; nf < 8; nf++) {
            int c = nf * 8 + 2 * t;
            float p0 = __expf(accs[nf][0] - mn0);
            float p1 = __expf(accs[nf][1] - mn0);
            sum0 += p0 + p1;
            *(__half2*)(smc + ATT_P_OFF + sw256o(rg, c)) = __floats2half2_rn(p0, p1);
            float p2 = __expf(accs[nf][2] - mn8);
            float p3 = __expf(accs[nf][3] - mn8);
            sum8 += p2 + p3;
            *(__half2*)(smc + ATT_P_OFF + sw256o(rg + 8, c)) =
                __floats2half2_rn(p2, p3);
        }
        sum0 += __shfl_xor_sync(0xffffffffu, sum0, 1);
        sum0 += __shfl_xor_sync(0xffffffffu, sum0, 2);
        sum8 += __shfl_xor_sync(0xffffffffu, sum8, 1);
        sum8 += __shfl_xor_sync(0xffffffffu, sum8, 2);
        l0 = l0 * al0 + sum0;
        l8 = l8 * al8 + sum8;
#pragma unroll
        for (int nf = 0; nf < 16; nf++) {
            o[nf][0] *= al0; o[nf][1] *= al0;
            o[nf][2] *= al8; o[nf][3] *= al8;
        }
        __syncwarp();

        // ---- PV: 4 v-chunks ----
#pragma unroll
        for (int vv = 0; vv < 4; vv++) {
            uint32_t vb[8][4];
#pragma unroll
            for (int ng = 0; ng < 8; ng++) {
                int vr = vv * 16 + ((lane >> 3) & 1) * 8 + (lane & 7);
                ldsm4t(vbuf + sw256o(vr, ng * 16 + acol_f),
                       vb[ng][0], vb[ng][1], vb[ng][2], vb[ng][3]);
            }
            uint32_t ah[4];
            ldsm4(sb + ATT_P_OFF + sw256o(arow_f, vv * 16 + acol_f),
                  ah[0], ah[1], ah[2], ah[3]);
#pragma unroll
            for (int ng = 0; ng < 8; ng++) {
                MMA_F16(o[2 * ng], ah, vb[ng][0], vb[ng][1]);
                MMA_F16(o[2 * ng + 1], ah, vb[ng][2], vb[ng][3]);
            }
        }
        __syncthreads();

        // ---- prefetch tile i+2 ----
        if (i + 2 < NT) {
            int tK = (i + 2) * 64;
            uint32_t kb2 = sb + ATT_K_OFF + (i & 1) * 16384;
#pragma unroll
            for (int it = 0; it < 4; it++) {
                int idx = it * 256 + tid;
                int r = idx >> 4, c = (idx & 15) * 8;
                cpa16g(kb2 + sw256o(r, c), Kg + (size_t)(tK + r) * KVROWW + c);
            }
        }
        cp_commitg();
        if (i + 2 < NT) {
            int tV = (i + 2) * 64;
            uint32_t vb2 = sb + ATT_V_OFF + (i & 1) * 16384;
#pragma unroll
            for (int it = 0; it < 4; it++) {
                int idx = it * 256 + tid;
                int r = idx >> 4, c = (idx & 15) * 8;
                cpa16g(vb2 + sw256o(r, c), Vg + (size_t)(tV + r) * KVROWW + c);
            }
        }
        cp_commitg();
    }

    // epilogue: normalize, write AO fp16 at [token][E]
    {
        float li0 = __fdiv_rn(1.f, l0);
        float li8 = __fdiv_rn(1.f, l8);
        size_t grow0 = (size_t)(b * S_DIM + q0 + rg) * E_DIM + h * D_DIM;
        size_t grow8 = grow0 + (size_t)8 * E_DIM;
#pragma unroll
        for (int nf = 0; nf < 16; nf++) {
            int c = nf * 8 + 2 * t;
            *(__half2*)&AO[grow0 + c] =
                __floats2half2_rn(o[nf][0] * li0, o[nf][1] * li0);
            *(__half2*)&AO[grow8 + c] =
                __floats2half2_rn(o[nf][2] * li8, o[nf][3] * li8);
        }
    }
}

// ---------------- launcher ----------------------------------------------------
extern "C" void kernel_launch(void* const* d_in, const int* in_sizes, int n_in,
                              void* d_out, int out_size) {
    const float* x  = (const float*)d_in[0];
    const float* rt = (const float*)d_in[1];
    const float* qw = (const float*)d_in[2];
    const float* kw = (const float*)d_in[3];
    const float* vw = (const float*)d_in[4];
    const float* ow = (const float*)d_in[5];
    const float* ob = (const float*)d_in[6];
    float* out = (float*)d_out;

    __half *p_wb, *p_xb, *p_qs, *p_ks, *p_vs, *p_ao, *p_ow;
    float *p_as, *p_part, *p_scales;
    cudaGetSymbolAddress((void**)&p_wb, g_wb);
    cudaGetSymbolAddress((void**)&p_xb, g_xb);
    cudaGetSymbolAddress((void**)&p_as, g_as);
    cudaGetSymbolAddress((void**)&p_qs, g_qs);
    cudaGetSymbolAddress((void**)&p_ks, g_ks);
    cudaGetSymbolAddress((void**)&p_vs, g_vs);
    cudaGetSymbolAddress((void**)&p_ao, g_ao);
    cudaGetSymbolAddress((void**)&p_ow, g_ow);
    cudaGetSymbolAddress((void**)&p_part, g_part);
    cudaGetSymbolAddress((void**)&p_scales, g_scales);

    const int n = E_DIM * E_DIM;

    // 1. scales + ternary fp16 weights
    absmean3<<<dim3(1024, 3), 256>>>(qw, kw, vw, p_part, n);
    scale_finalize<<<3, 256>>>(p_part, p_scales, 1024, 1.f / (float)n);
    quantw3<<<dim3(2048, 3), 256>>>(qw, kw, vw, p_wb, p_scales, n);

    // 2. activation quant + out_w convert
    quant_act_k<<<B_DIM * S_DIM, 256>>>(x, p_xb, p_as);
    wconv_k<<<(n + 255) / 256, 256>>>(ow, p_ow);

    // 3. QKV projections (fp16 exact-integer GEMM) -> single fp16
    HJobs j1 = {};
    for (int z = 0; z < 6; z++) {
        int w = z >> 1, batch = z & 1;
        j1.A[z] = p_xb + (size_t)batch * S_DIM * E_DIM;
        j1.W[z] = p_wb + (size_t)w * n;
        if (w == 0)
            j1.C[z] = p_qs + (size_t)batch * S_DIM * KVROWW;
        else if (w == 1)
            j1.C[z] = p_ks + (size_t)batch * T_DIM * KVROWW;
        else
            j1.C[z] = p_vs + (size_t)batch * T_DIM * KVROWW;
        j1.rs[z] = p_as + (size_t)batch * S_DIM;
        j1.ws[z] = p_scales + w;
        j1.mode[z] = 2;
    }
    j1.bias = nullptr;
    cudaFuncSetAttribute(hgemm_nt, cudaFuncAttributeMaxDynamicSharedMemorySize,
                         65536);
    hgemm_nt<<<dim3(16, 16, 6), 256, 65536>>>(j1, S_DIM, E_DIM, E_DIM);

    // 4. reasoning rk/rv -> single fp16 rows S..T
    GemmJobs j2 = {};
    for (int z = 0; z < 4; z++) {
        int w = z >> 1, batch = z & 1;
        j2.A[z] = rt + (size_t)batch * R_DIM * E_DIM;
        j2.W[z] = (w == 0) ? kw : vw;
        j2.C[z] = ((w == 0) ? p_ks : p_vs) +
                  ((size_t)batch * T_DIM + S_DIM) * KVROWW;
    }
    sgemm_nt64<<<dim3(32, 1, 4), 256>>>(j2, R_DIM, E_DIM, E_DIM);

    // 5. single-term fp16 flash attention -> AO
    cudaFuncSetAttribute(attn_tc, cudaFuncAttributeMaxDynamicSharedMemorySize,
                         ATT_SMEM);
    attn_tc<<<dim3(S_DIM / 128, H_DIM, B_DIM), 256, ATT_SMEM>>>(p_qs, p_ks, p_vs,
                                                                p_ao);

    // 6. output projection: fp16 GEMM over K=2048 + bias
    HJobs j3 = {};
    j3.A[0] = p_ao;
    j3.W[0] = p_ow;
    j3.C[0] = out;
    j3.rs[0] = nullptr;
    j3.ws[0] = nullptr;
    j3.mode[0] = 0;
    j3.bias = ob;
    hgemm_nt<<<dim3(16, 32, 1), 256, 65536>>>(j3, B_DIM * S_DIM, E_DIM, E_DIM);
}

// round 14
// speedup vs baseline: 4.4858x; 1.3329x over previous
#include <cuda_runtime.h>
#include <cuda_fp16.h>
#include <math.h>
#include <stdint.h>

#define E_DIM 2048
#define B_DIM 2
#define S_DIM 2048
#define R_DIM 128
#define H_DIM 16
#define D_DIM 128
#define T_DIM (S_DIM + R_DIM)   /* 2176 */
#define KVROWW 2048             /* Q/K/V row: H*128 fp16 */

// ---------------- scratch -----------------------------------------------------
__device__ __half g_wb[3][E_DIM * E_DIM];        // ternary weights fp16 (exact)
__device__ __half g_xb[B_DIM * S_DIM * E_DIM];   // int8-valued acts fp16 (exact)
__device__ float g_as[B_DIM * S_DIM];            // per-token 1/s
__device__ __half g_qs[(size_t)B_DIM * S_DIM * KVROWW]; // Q fp16
__device__ __half g_ks[(size_t)B_DIM * T_DIM * KVROWW]; // K fp16
__device__ __half g_vs[(size_t)B_DIM * T_DIM * KVROWW]; // V fp16
__device__ __half g_ao[(size_t)B_DIM * S_DIM * E_DIM];  // AO fp16
__device__ __half g_ow[(size_t)E_DIM * E_DIM];          // out_w fp16
__device__ __half g_kwf[(size_t)E_DIM * E_DIM];         // raw k_w fp16
__device__ __half g_vwf[(size_t)E_DIM * E_DIM];         // raw v_w fp16
__device__ __half g_rt[(size_t)B_DIM * R_DIM * E_DIM];  // reasoning tokens fp16
__device__ float g_part[3 * 1024];
__device__ float g_scales[3];

// ---------------- prep kernels ------------------------------------------------
__global__ void absmean3(const float* __restrict__ qw, const float* __restrict__ kw,
                         const float* __restrict__ vw, float* __restrict__ part,
                         int n) {
    __shared__ float red[256];
    const float* w = (blockIdx.y == 0) ? qw : (blockIdx.y == 1) ? kw : vw;
    int chunk4 = (n / gridDim.x) >> 2;      // float4 per block
    const float4* w4 = (const float4*)w + (size_t)blockIdx.x * chunk4;
    float s = 0.f;
    for (int i = threadIdx.x; i < chunk4; i += blockDim.x) {
        float4 v = w4[i];
        s += fabsf(v.x) + fabsf(v.y) + fabsf(v.z) + fabsf(v.w);
    }
    red[threadIdx.x] = s;
    __syncthreads();
    for (int off = 128; off > 0; off >>= 1) {
        if (threadIdx.x < off) red[threadIdx.x] += red[threadIdx.x + off];
        __syncthreads();
    }
    if (threadIdx.x == 0) part[blockIdx.y * 1024 + blockIdx.x] = red[0];
}

__global__ void scale_finalize(const float* __restrict__ part,
                               float* __restrict__ scales, int nblk, float inv_n) {
    __shared__ float red[256];
    const float* p = part + blockIdx.x * nblk;
    float s = 0.f;
    for (int i = threadIdx.x; i < nblk; i += blockDim.x) s += p[i];
    red[threadIdx.x] = s;
    __syncthreads();
    for (int off = 128; off > 0; off >>= 1) {
        if (threadIdx.x < off) red[threadIdx.x] += red[threadIdx.x + off];
        __syncthreads();
    }
    if (threadIdx.x == 0) scales[blockIdx.x] = fmaxf(red[0] * inv_n, 1e-5f);
}

// ternary fp16 weights: 8 elements per thread, vectorized
__global__ void quantw3(const float* __restrict__ qw, const float* __restrict__ kw,
                        const float* __restrict__ vw, __half* __restrict__ wb,
                        const float* __restrict__ scales, int n) {
    int s = blockIdx.y;
    const float* w = (s == 0) ? qw : (s == 1) ? kw : vw;
    __half* o = wb + (size_t)s * n;
    float sc = scales[s];
    int gid = blockIdx.x * blockDim.x + threadIdx.x;   // n/8 threads
    const float4* w4 = (const float4*)w;
    float4 a = w4[2 * gid], b = w4[2 * gid + 1];
    float v[8] = {a.x, a.y, a.z, a.w, b.x, b.y, b.z, b.w};
    __half h[8];
#pragma unroll
    for (int j = 0; j < 8; j++) {
        float q = rintf(__fdiv_rn(v[j], sc));
        h[j] = __float2half_rn(fminf(fmaxf(q, -1.f), 1.f));
    }
    *(float4*)&o[(size_t)gid * 8] = *(float4*)h;
}

// per-token int8 absmax quant, vectorized: each thread owns cols [tid*8, +8)
__global__ void quant_act_k(const float* __restrict__ x,
                            __half* __restrict__ xb,
                            float* __restrict__ as_) {
    __shared__ float red[256];
    int row = blockIdx.x, tid = threadIdx.x;
    const float4* xr4 = (const float4*)(x + (size_t)row * E_DIM);
    float4 a = xr4[2 * tid], b = xr4[2 * tid + 1];
    float v[8] = {a.x, a.y, a.z, a.w, b.x, b.y, b.z, b.w};
    float m = 0.f;
#pragma unroll
    for (int j = 0; j < 8; j++) m = fmaxf(m, fabsf(v[j]));
    red[tid] = m;
    __syncthreads();
    for (int off = 128; off > 0; off >>= 1) {
        if (tid < off) red[tid] = fmaxf(red[tid], red[tid + off]);
        __syncthreads();
    }
    float mx = fmaxf(red[0], 1e-5f);
    float s = __fdiv_rn(127.f, mx);
    if (tid == 0) as_[row] = __fdiv_rn(1.f, s);
    __half h[8];
#pragma unroll
    for (int j = 0; j < 8; j++) {
        float q = rintf(v[j] * s);
        h[j] = __float2half_rn(fminf(fmaxf(q, -128.f), 127.f));
    }
    *(float4*)&xb[(size_t)row * E_DIM + tid * 8] = *(float4*)h;
}

// fp32 -> fp16 convert: y=0 ow, y=1 kw, y=2 vw
__global__ void conv3(const float* __restrict__ ow, const float* __restrict__ kw,
                      const float* __restrict__ vw, __half* __restrict__ owh,
                      __half* __restrict__ kwh, __half* __restrict__ vwh) {
    int s = blockIdx.y;
    const float* src = (s == 0) ? ow : (s == 1) ? kw : vw;
    __half* dst = (s == 0) ? owh : (s == 1) ? kwh : vwh;
    int gid = blockIdx.x * blockDim.x + threadIdx.x;
    const float4* s4 = (const float4*)src;
    float4 a = s4[2 * gid], b = s4[2 * gid + 1];
    __half h[8] = {__float2half_rn(a.x), __float2half_rn(a.y),
                   __float2half_rn(a.z), __float2half_rn(a.w),
                   __float2half_rn(b.x), __float2half_rn(b.y),
                   __float2half_rn(b.z), __float2half_rn(b.w)};
    *(float4*)&dst[(size_t)gid * 8] = *(float4*)h;
}

__global__ void rtconv(const float* __restrict__ rt, __half* __restrict__ rth) {
    int gid = blockIdx.x * blockDim.x + threadIdx.x;
    const float4* s4 = (const float4*)rt;
    float4 a = s4[2 * gid], b = s4[2 * gid + 1];
    __half h[8] = {__float2half_rn(a.x), __float2half_rn(a.y),
                   __float2half_rn(a.z), __float2half_rn(a.w),
                   __float2half_rn(b.x), __float2half_rn(b.y),
                   __float2half_rn(b.z), __float2half_rn(b.w)};
    *(float4*)&rth[(size_t)gid * 8] = *(float4*)h;
}

// ---------------- fp16 tensor-core NT GEMM -----------------------------------
// mode 0: fp32 out + bias; mode 2: (optionally scaled) fp16 out [token][h*128+d]
struct HJobs {
    const __half* A[6];
    const __half* W[6];
    void* C[6];
    const float* rs[6];
    const float* ws[6];
    int mode[6];
    const float* bias;
};

__device__ __forceinline__ uint32_t swz(uint32_t o) { return o ^ ((o >> 3) & 0x70); }

__global__ __launch_bounds__(256, 1) void hgemm_nt(HJobs jobs, int M, int N, int K) {
    extern __shared__ __align__(128) char sm_raw[];
    int z = blockIdx.z;
    const __half* A = jobs.A[z];
    const __half* W = jobs.W[z];
    const float* rs = jobs.rs[z];
    const float* ws = jobs.ws[z];
    int mode = jobs.mode[z];

    uint32_t sbase = (uint32_t)__cvta_generic_to_shared(sm_raw);
    int tid = threadIdx.x, lane = tid & 31, warp = tid >> 5;
    int wm = warp >> 1, wn = warp & 1;
    int bm = blockIdx.y * 128, bn = blockIdx.x * 128;

    const __half* Ag = A + (size_t)bm * K;
    const __half* Wg = W + (size_t)bn * K;

    float acc[2][8][4];
#pragma unroll
    for (int mf = 0; mf < 2; mf++)
#pragma unroll
        for (int nf = 0; nf < 8; nf++)
#pragma unroll
            for (int c = 0; c < 4; c++) acc[mf][nf][c] = 0.f;

    float4 sa[4], sw[4];
#pragma unroll
    for (int i = 0; i < 4; i++) {
        int idx = i * 256 + tid;
        int row = idx >> 3, c = idx & 7;
        sa[i] = *(const float4*)(Ag + (size_t)row * K + c * 8);
        sw[i] = *(const float4*)(Wg + (size_t)row * K + c * 8);
    }
#pragma unroll
    for (int i = 0; i < 4; i++) {
        int idx = i * 256 + tid;
        int row = idx >> 3, c = idx & 7;
        uint32_t off = swz((uint32_t)(row * 128 + c * 16));
        *(float4*)(sm_raw + off) = sa[i];
        *(float4*)(sm_raw + 16384 + off) = sw[i];
    }
    __syncthreads();

    int KT = K >> 6;
    for (int kt = 0; kt < KT; kt++) {
        int cur = kt & 1;
        if (kt + 1 < KT) {
#pragma unroll
            for (int i = 0; i < 4; i++) {
                int idx = i * 256 + tid;
                int row = idx >> 3, c = idx & 7;
                sa[i] = *(const float4*)(Ag + (size_t)row * K + (kt + 1) * 64 + c * 8);
                sw[i] = *(const float4*)(Wg + (size_t)row * K + (kt + 1) * 64 + c * 8);
            }
        }
        uint32_t abase = sbase + cur * 32768;
        uint32_t wbase = abase + 16384;
#pragma unroll
        for (int ks = 0; ks < 4; ks++) {
            uint32_t a[2][4];
#pragma unroll
            for (int mf = 0; mf < 2; mf++) {
                int r = wm * 32 + mf * 16 + ((lane >> 3) & 1) * 8 + (lane & 7);
                uint32_t off = swz((uint32_t)(r * 128 + ks * 32 + ((lane >> 4) & 1) * 16));
                asm volatile(
                    "ldmatrix.sync.aligned.m8n8.x4.shared.b16 {%0,%1,%2,%3}, [%4];"
                    : "=r"(a[mf][0]), "=r"(a[mf][1]), "=r"(a[mf][2]), "=r"(a[mf][3])
                    : "r"(abase + off));
            }
            uint32_t b0[8], b1[8];
#pragma unroll
            for (int q = 0; q < 4; q++) {
                int r = wn * 64 + q * 16 + ((lane >> 3) & 1) * 8 + (lane & 7);
                uint32_t off = swz((uint32_t)(r * 128 + ks * 32 + ((lane >> 4) & 1) * 16));
                uint32_t r0, r1, r2, r3;
                asm volatile(
                    "ldmatrix.sync.aligned.m8n8.x4.shared.b16 {%0,%1,%2,%3}, [%4];"
                    : "=r"(r0), "=r"(r1), "=r"(r2), "=r"(r3)
                    : "r"(wbase + off));
                b0[2 * q] = r0; b0[2 * q + 1] = r1;
                b1[2 * q] = r2; b1[2 * q + 1] = r3;
            }
#pragma unroll
            for (int mf = 0; mf < 2; mf++)
#pragma unroll
                for (int nf = 0; nf < 8; nf++)
                    asm volatile(
                        "mma.sync.aligned.m16n8k16.row.col.f32.f16.f16.f32 "
                        "{%0,%1,%2,%3},{%4,%5,%6,%7},{%8,%9},{%0,%1,%2,%3};"
                        : "+f"(acc[mf][nf][0]), "+f"(acc[mf][nf][1]),
                          "+f"(acc[mf][nf][2]), "+f"(acc[mf][nf][3])
                        : "r"(a[mf][0]), "r"(a[mf][1]), "r"(a[mf][2]), "r"(a[mf][3]),
                          "r"(b0[nf]), "r"(b1[nf]));
        }
        if (kt + 1 < KT) {
            int nxt = cur ^ 1;
#pragma unroll
            for (int i = 0; i < 4; i++) {
                int idx = i * 256 + tid;
                int row = idx >> 3, c = idx & 7;
                uint32_t off = swz((uint32_t)(row * 128 + c * 16));
                *(float4*)(sm_raw + nxt * 32768 + off) = sa[i];
                *(float4*)(sm_raw + nxt * 32768 + 16384 + off) = sw[i];
            }
        }
        __syncthreads();
    }

    int g = lane >> 2, t = lane & 3;
    float wsv = ws ? *ws : 1.f;
    if (mode == 2) {
        __half* Ob = (__half*)jobs.C[z];
#pragma unroll
        for (int mf = 0; mf < 2; mf++) {
            int row0 = bm + wm * 32 + mf * 16 + g;
            float r0s = (rs ? rs[row0] : 1.f) * wsv;
            float r1s = (rs ? rs[row0 + 8] : 1.f) * wsv;
#pragma unroll
            for (int nf = 0; nf < 8; nf++) {
                int col = bn + wn * 64 + nf * 8 + 2 * t;
                int hh = col >> 7, d = col & 127;
                size_t i0 = (size_t)row0 * KVROWW + hh * 128 + d;
                size_t i8 = (size_t)(row0 + 8) * KVROWW + hh * 128 + d;
                *(__half2*)&Ob[i0] = __floats2half2_rn(acc[mf][nf][0] * r0s,
                                                       acc[mf][nf][1] * r0s);
                *(__half2*)&Ob[i8] = __floats2half2_rn(acc[mf][nf][2] * r1s,
                                                       acc[mf][nf][3] * r1s);
            }
        }
    } else {
        float* C = (float*)jobs.C[z];
        const float* bias = jobs.bias;
#pragma unroll
        for (int mf = 0; mf < 2; mf++) {
            int row0 = bm + wm * 32 + mf * 16 + g;
#pragma unroll
            for (int nf = 0; nf < 8; nf++) {
                int col = bn + wn * 64 + nf * 8 + 2 * t;
                float b0v = bias ? bias[col] : 0.f;
                float b1v = bias ? bias[col + 1] : 0.f;
                float2 v0 = make_float2(acc[mf][nf][0] + b0v, acc[mf][nf][1] + b1v);
                float2 v1 = make_float2(acc[mf][nf][2] + b0v, acc[mf][nf][3] + b1v);
                *(float2*)&C[(size_t)row0 * N + col] = v0;
                *(float2*)&C[(size_t)(row0 + 8) * N + col] = v1;
            }
        }
    }
}

// ---------------- fp16 flash attention, BK=128, P aliases Q ------------------
#define ATT_P_OFF 0            /* [128][256B] = 32KB: Q at start, P after tile 0 */
#define ATT_K_OFF 32768        /* 2 x [128][256B] = 128KB */
#define ATT_V_OFF 163840       /* 1 x [128][256B] = 64KB */
#define ATT_SMEM 229376

__device__ __forceinline__ uint32_t sw256o(int r, int c) {
    return (uint32_t)(r * 256 + ((((c >> 3) ^ (r & 7))) << 4) + ((c & 7) << 1));
}
__device__ __forceinline__ void ldsm4(uint32_t addr, uint32_t& r0, uint32_t& r1,
                                      uint32_t& r2, uint32_t& r3) {
    asm volatile("ldmatrix.sync.aligned.m8n8.x4.shared.b16 {%0,%1,%2,%3}, [%4];"
                 : "=r"(r0), "=r"(r1), "=r"(r2), "=r"(r3) : "r"(addr));
}
__device__ __forceinline__ void ldsm4t(uint32_t addr, uint32_t& r0, uint32_t& r1,
                                       uint32_t& r2, uint32_t& r3) {
    asm volatile("ldmatrix.sync.aligned.m8n8.x4.trans.shared.b16 {%0,%1,%2,%3}, [%4];"
                 : "=r"(r0), "=r"(r1), "=r"(r2), "=r"(r3) : "r"(addr));
}
__device__ __forceinline__ void cpa16g(uint32_t dst, const void* src) {
    asm volatile("cp.async.cg.shared.global [%0], [%1], 16;" :: "r"(dst), "l"(src));
}
__device__ __forceinline__ void cp_commitg() {
    asm volatile("cp.async.commit_group;" ::: "memory");
}
#define MMA_F16(d, a, b0v, b1v) \
    asm volatile( \
        "mma.sync.aligned.m16n8k16.row.col.f32.f16.f16.f32 " \
        "{%0,%1,%2,%3},{%4,%5,%6,%7},{%8,%9},{%0,%1,%2,%3};" \
        : "+f"((d)[0]), "+f"((d)[1]), "+f"((d)[2]), "+f"((d)[3]) \
        : "r"((a)[0]), "r"((a)[1]), "r"((a)[2]), "r"((a)[3]), \
          "r"(b0v), "r"(b1v))

__global__ __launch_bounds__(256, 1) void attn_tc(const __half* __restrict__ Qs,
                                                  const __half* __restrict__ Ks,
                                                  const __half* __restrict__ Vs,
                                                  __half* __restrict__ AO) {
    extern __shared__ __align__(128) char smc[];
    uint32_t sb = (uint32_t)__cvta_generic_to_shared(smc);

    int tid = threadIdx.x, lane = tid & 31, w = tid >> 5;
    int g = lane >> 2, t = lane & 3;
    int q0 = blockIdx.x * 128;
    int h = blockIdx.y, b = blockIdx.z;

    const __half* Qg = Qs + (size_t)(b * S_DIM + q0) * KVROWW + h * 128;
    const __half* Kg = Ks + (size_t)(b * T_DIM) * KVROWW + h * 128;
    const __half* Vg = Vs + (size_t)(b * T_DIM) * KVROWW + h * 128;

    const int NT = T_DIM / 128;  // 17

    // prologue: [Q + K0] | [V0] | [K1]   (3 commit groups)
#pragma unroll
    for (int it = 0; it < 8; it++) {
        int idx = it * 256 + tid;
        int r = idx >> 4, c = (idx & 15) * 8;
        cpa16g(sb + ATT_P_OFF + sw256o(r, c), Qg + (size_t)r * KVROWW + c);
    }
#pragma unroll
    for (int it = 0; it < 8; it++) {
        int idx = it * 256 + tid;
        int r = idx >> 4, c = (idx & 15) * 8;
        cpa16g(sb + ATT_K_OFF + sw256o(r, c), Kg + (size_t)r * KVROWW + c);
    }
    cp_commitg();
#pragma unroll
    for (int it = 0; it < 8; it++) {
        int idx = it * 256 + tid;
        int r = idx >> 4, c = (idx & 15) * 8;
        cpa16g(sb + ATT_V_OFF + sw256o(r, c), Vg + (size_t)r * KVROWW + c);
    }
    cp_commitg();
#pragma unroll
    for (int it = 0; it < 8; it++) {
        int idx = it * 256 + tid;
        int r = idx >> 4, c = (idx & 15) * 8;
        cpa16g(sb + ATT_K_OFF + 65536 + sw256o(r, c),
               Kg + (size_t)(128 + r) * KVROWW + c);
    }
    cp_commitg();

    float o[16][4];
#pragma unroll
    for (int nf = 0; nf < 16; nf++)
#pragma unroll
        for (int c = 0; c < 4; c++) o[nf][c] = 0.f;
    float m0 = -1e30f, m8 = -1e30f, l0 = 0.f, l8 = 0.f;

    uint32_t qf[8][4];
    const float scl = 0.08838834764831845f;
    int rg = w * 16 + g;
    int arow_f = w * 16 + ((lane >> 3) & 1) * 8 + (lane & 7);
    int acol_f = ((lane >> 4) & 1) * 8;

    for (int i = 0; i < NT; i++) {
        // K(i) (and Q at i=0) ready: 2 groups may remain pending
        asm volatile("cp.async.wait_group 2;" ::: "memory");
        __syncthreads();

        if (i == 0) {
#pragma unroll
            for (int kk = 0; kk < 8; kk++)
                ldsm4(sb + ATT_P_OFF + sw256o(arow_f, kk * 16 + acol_f),
                      qf[kk][0], qf[kk][1], qf[kk][2], qf[kk][3]);
        }

        uint32_t kbuf = sb + ATT_K_OFF + (i & 1) * 65536;

        // ---- QK: 8 k-chunks x 16 n-frags (two halves to bound registers) ----
        float accs[16][4];
#pragma unroll
        for (int nf = 0; nf < 16; nf++)
#pragma unroll
            for (int c = 0; c < 4; c++) accs[nf][c] = 0.f;

#pragma unroll
        for (int kk = 0; kk < 8; kk++) {
#pragma unroll
            for (int hf = 0; hf < 2; hf++) {
                uint32_t b0[8], b1[8];
#pragma unroll
                for (int nb = 0; nb < 4; nb++) {
                    int br = hf * 64 + nb * 16 + ((lane >> 3) & 1) * 8 + (lane & 7);
                    uint32_t r0, r1, r2, r3;
                    ldsm4(kbuf + sw256o(br, kk * 16 + acol_f), r0, r1, r2, r3);
                    b0[2 * nb] = r0; b0[2 * nb + 1] = r1;
                    b1[2 * nb] = r2; b1[2 * nb + 1] = r3;
                }
#pragma unroll
                for (int nf = 0; nf < 8; nf++)
                    MMA_F16(accs[hf * 8 + nf], qf[kk], b0[nf], b1[nf]);
            }
        }

        // ---- register-space online softmax over 16 frags, Ph fp16 ----
        float mx0 = -1e30f, mx8 = -1e30f;
#pragma unroll
        for (int nf = 0; nf < 16; nf++) {
            accs[nf][0] *= scl; accs[nf][1] *= scl;
            accs[nf][2] *= scl; accs[nf][3] *= scl;
            mx0 = fmaxf(mx0, fmaxf(accs[nf][0], accs[nf][1]));
            mx8 = fmaxf(mx8, fmaxf(accs[nf][2], accs[nf][3]));
        }
        mx0 = fmaxf(mx0, __shfl_xor_sync(0xffffffffu, mx0, 1));
        mx0 = fmaxf(mx0, __shfl_xor_sync(0xffffffffu, mx0, 2));
        mx8 = fmaxf(mx8, __shfl_xor_sync(0xffffffffu, mx8, 1));
        mx8 = fmaxf(mx8, __shfl_xor_sync(0xffffffffu, mx8, 2));
        float mn0 = fmaxf(m0, mx0), mn8 = fmaxf(m8, mx8);
        float al0 = __expf(m0 - mn0), al8 = __expf(m8 - mn8);
        m0 = mn0; m8 = mn8;
        float sum0 = 0.f, sum8 = 0.f;
#pragma unroll
        for (int nf = 0; nf < 16; nf++) {
            int c = nf * 8 + 2 * t;
            float p0 = __expf(accs[nf][0] - mn0);
            float p1 = __expf(accs[nf][1] - mn0);
            sum0 += p0 + p1;
            *(__half2*)(smc + ATT_P_OFF + sw256o(rg, c)) = __floats2half2_rn(p0, p1);
            float p2 = __expf(accs[nf][2] - mn8);
            float p3 = __expf(accs[nf][3] - mn8);
            sum8 += p2 + p3;
            *(__half2*)(smc + ATT_P_OFF + sw256o(rg + 8, c)) =
                __floats2half2_rn(p2, p3);
        }
        sum0 += __shfl_xor_sync(0xffffffffu, sum0, 1);
        sum0 += __shfl_xor_sync(0xffffffffu, sum0, 2);
        sum8 += __shfl_xor_sync(0xffffffffu, sum8, 1);
        sum8 += __shfl_xor_sync(0xffffffffu, sum8, 2);
        l0 = l0 * al0 + sum0;
        l8 = l8 * al8 + sum8;
#pragma unroll
        for (int nf = 0; nf < 16; nf++) {
            o[nf][0] *= al0; o[nf][1] *= al0;
            o[nf][2] *= al8; o[nf][3] *= al8;
        }

        // V(i) ready: 1 group (K(i+1)) may remain pending
        asm volatile("cp.async.wait_group 1;" ::: "memory");
        __syncthreads();

        // ---- PV: 8 v-chunks (k-dim 128), Ph only ----
        uint32_t vbuf = sb + ATT_V_OFF;
#pragma unroll
        for (int vv = 0; vv < 8; vv++) {
            uint32_t vb[8][4];
#pragma unroll
            for (int ng = 0; ng < 8; ng++) {
                int vr = vv * 16 + ((lane >> 3) & 1) * 8 + (lane & 7);
                ldsm4t(vbuf + sw256o(vr, ng * 16 + acol_f),
                       vb[ng][0], vb[ng][1], vb[ng][2], vb[ng][3]);
            }
            uint32_t ah[4];
            ldsm4(sb + ATT_P_OFF + sw256o(arow_f, vv * 16 + acol_f),
                  ah[0], ah[1], ah[2], ah[3]);
#pragma unroll
            for (int ng = 0; ng < 8; ng++) {
                MMA_F16(o[2 * ng], ah, vb[ng][0], vb[ng][1]);
                MMA_F16(o[2 * ng + 1], ah, vb[ng][2], vb[ng][3]);
            }
        }
        __syncthreads();

        // ---- issue V(i+1) then K(i+2) ----
        if (i + 1 < NT) {
            int tV = (i + 1) * 128;
#pragma unroll
            for (int it = 0; it < 8; it++) {
                int idx = it * 256 + tid;
                int r = idx >> 4, c = (idx & 15) * 8;
                cpa16g(sb + ATT_V_OFF + sw256o(r, c),
                       Vg + (size_t)(tV + r) * KVROWW + c);
            }
        }
        cp_commitg();
        if (i + 2 < NT) {
            int tK = (i + 2) * 128;
            uint32_t kb2 = sb + ATT_K_OFF + (i & 1) * 65536;
#pragma unroll
            for (int it = 0; it < 8; it++) {
                int idx = it * 256 + tid;
                int r = idx >> 4, c = (idx & 15) * 8;
                cpa16g(kb2 + sw256o(r, c), Kg + (size_t)(tK + r) * KVROWW + c);
            }
        }
        cp_commitg();
    }

    // epilogue
    {
        float li0 = __fdiv_rn(1.f, l0);
        float li8 = __fdiv_rn(1.f, l8);
        size_t grow0 = (size_t)(b * S_DIM + q0 + rg) * E_DIM + h * D_DIM;
        size_t grow8 = grow0 + (size_t)8 * E_DIM;
#pragma unroll
        for (int nf = 0; nf < 16; nf++) {
            int c = nf * 8 + 2 * t;
            *(__half2*)&AO[grow0 + c] =
                __floats2half2_rn(o[nf][0] * li0, o[nf][1] * li0);
            *(__half2*)&AO[grow8 + c] =
                __floats2half2_rn(o[nf][2] * li8, o[nf][3] * li8);
        }
    }
}

// ---------------- launcher ----------------------------------------------------
extern "C" void kernel_launch(void* const* d_in, const int* in_sizes, int n_in,
                              void* d_out, int out_size) {
    const float* x  = (const float*)d_in[0];
    const float* rt = (const float*)d_in[1];
    const float* qw = (const float*)d_in[2];
    const float* kw = (const float*)d_in[3];
    const float* vw = (const float*)d_in[4];
    const float* ow = (const float*)d_in[5];
    const float* ob = (const float*)d_in[6];
    float* out = (float*)d_out;

    __half *p_wb, *p_xb, *p_qs, *p_ks, *p_vs, *p_ao, *p_ow, *p_kwf, *p_vwf, *p_rt;
    float *p_as, *p_part, *p_scales;
    cudaGetSymbolAddress((void**)&p_wb, g_wb);
    cudaGetSymbolAddress((void**)&p_xb, g_xb);
    cudaGetSymbolAddress((void**)&p_as, g_as);
    cudaGetSymbolAddress((void**)&p_qs, g_qs);
    cudaGetSymbolAddress((void**)&p_ks, g_ks);
    cudaGetSymbolAddress((void**)&p_vs, g_vs);
    cudaGetSymbolAddress((void**)&p_ao, g_ao);
    cudaGetSymbolAddress((void**)&p_ow, g_ow);
    cudaGetSymbolAddress((void**)&p_kwf, g_kwf);
    cudaGetSymbolAddress((void**)&p_vwf, g_vwf);
    cudaGetSymbolAddress((void**)&p_rt, g_rt);
    cudaGetSymbolAddress((void**)&p_part, g_part);
    cudaGetSymbolAddress((void**)&p_scales, g_scales);

    const int n = E_DIM * E_DIM;

    // 1. scales + ternary fp16 weights
    absmean3<<<dim3(1024, 3), 256>>>(qw, kw, vw, p_part, n);
    scale_finalize<<<3, 256>>>(p_part, p_scales, 1024, 1.f / (float)n);
    quantw3<<<dim3(n / 8 / 256, 3), 256>>>(qw, kw, vw, p_wb, p_scales, n);

    // 2. activation quant + fp16 converts (ow/kw/vw raw, rt)
    quant_act_k<<<B_DIM * S_DIM, 256>>>(x, p_xb, p_as);
    conv3<<<dim3(n / 8 / 256, 3), 256>>>(ow, kw, vw, p_ow, p_kwf, p_vwf);
    rtconv<<<(B_DIM * R_DIM * E_DIM) / 8 / 256, 256>>>(rt, p_rt);

    // 3. QKV projections (fp16 exact-integer GEMM) -> single fp16
    HJobs j1 = {};
    for (int z = 0; z < 6; z++) {
        int w = z >> 1, batch = z & 1;
        j1.A[z] = p_xb + (size_t)batch * S_DIM * E_DIM;
        j1.W[z] = p_wb + (size_t)w * n;
        if (w == 0)
            j1.C[z] = p_qs + (size_t)batch * S_DIM * KVROWW;
        else if (w == 1)
            j1.C[z] = p_ks + (size_t)batch * T_DIM * KVROWW;
        else
            j1.C[z] = p_vs + (size_t)batch * T_DIM * KVROWW;
        j1.rs[z] = p_as + (size_t)batch * S_DIM;
        j1.ws[z] = p_scales + w;
        j1.mode[z] = 2;
    }
    j1.bias = nullptr;
    cudaFuncSetAttribute(hgemm_nt, cudaFuncAttributeMaxDynamicSharedMemorySize,
                         65536);
    hgemm_nt<<<dim3(16, 16, 6), 256, 65536>>>(j1, S_DIM, E_DIM, E_DIM);

    // 4. reasoning rk/rv on fp16 HMMA path -> rows S..T
    HJobs j2 = {};
    for (int z = 0; z < 4; z++) {
        int w = z >> 1, batch = z & 1;
        j2.A[z] = p_rt + (size_t)batch * R_DIM * E_DIM;
        j2.W[z] = (w == 0) ? p_kwf : p_vwf;
        j2.C[z] = ((w == 0) ? p_ks : p_vs) +
                  ((size_t)batch * T_DIM + S_DIM) * KVROWW;
        j2.rs[z] = nullptr;
        j2.ws[z] = nullptr;
        j2.mode[z] = 2;
    }
    j2.bias = nullptr;
    hgemm_nt<<<dim3(16, 1, 4), 256, 65536>>>(j2, R_DIM, E_DIM, E_DIM);

    // 5. fp16 flash attention (BK=128) -> AO
    cudaFuncSetAttribute(attn_tc, cudaFuncAttributeMaxDynamicSharedMemorySize,
                         ATT_SMEM);
    attn_tc<<<dim3(S_DIM / 128, H_DIM, B_DIM), 256, ATT_SMEM>>>(p_qs, p_ks, p_vs,
                                                                p_ao);

    // 6. output projection: fp16 GEMM over K=2048 + bias
    HJobs j3 = {};
    j3.A[0] = p_ao;
    j3.W[0] = p_ow;
    j3.C[0] = out;
    j3.rs[0] = nullptr;
    j3.ws[0] = nullptr;
    j3.mode[0] = 0;
    j3.bias = ob;
    hgemm_nt<<<dim3(16, 32, 1), 256, 65536>>>(j3, B_DIM * S_DIM, E_DIM, E_DIM);
}

// round 15
// speedup vs baseline: 4.7220x; 1.0526x over previous
#include <cuda_runtime.h>
#include <cuda_fp16.h>
#include <math.h>
#include <stdint.h>

#define E_DIM 2048
#define B_DIM 2
#define S_DIM 2048
#define R_DIM 128
#define H_DIM 16
#define D_DIM 128
#define T_DIM (S_DIM + R_DIM)   /* 2176 */
#define KVROWW 2048             /* Q/K/V row: H*128 fp16 */

// ---------------- scratch -----------------------------------------------------
__device__ __half g_wb[3][E_DIM * E_DIM];        // ternary weights fp16 (exact)
__device__ __half g_xb[B_DIM * S_DIM * E_DIM];   // int8-valued acts fp16 (exact)
__device__ float g_as[B_DIM * S_DIM];            // per-token 1/s
__device__ __half g_qs[(size_t)B_DIM * S_DIM * KVROWW]; // Q fp16
__device__ __half g_ks[(size_t)B_DIM * T_DIM * KVROWW]; // K fp16
__device__ __half g_vs[(size_t)B_DIM * T_DIM * KVROWW]; // V fp16
__device__ __half g_ao[(size_t)B_DIM * S_DIM * E_DIM];  // AO fp16
__device__ __half g_ow[(size_t)E_DIM * E_DIM];          // out_w fp16
__device__ __half g_kwf[(size_t)E_DIM * E_DIM];         // raw k_w fp16
__device__ __half g_vwf[(size_t)E_DIM * E_DIM];         // raw v_w fp16
__device__ __half g_rt[(size_t)B_DIM * R_DIM * E_DIM];  // reasoning tokens fp16
__device__ float g_part[3 * 1024];
__device__ float g_scales[3];

// ---------------- prep kernels ------------------------------------------------
__global__ void absmean3(const float* __restrict__ qw, const float* __restrict__ kw,
                         const float* __restrict__ vw, float* __restrict__ part,
                         int n) {
    __shared__ float red[256];
    const float* w = (blockIdx.y == 0) ? qw : (blockIdx.y == 1) ? kw : vw;
    int chunk4 = (n / gridDim.x) >> 2;
    const float4* w4 = (const float4*)w + (size_t)blockIdx.x * chunk4;
    float s = 0.f;
    for (int i = threadIdx.x; i < chunk4; i += blockDim.x) {
        float4 v = w4[i];
        s += fabsf(v.x) + fabsf(v.y) + fabsf(v.z) + fabsf(v.w);
    }
    red[threadIdx.x] = s;
    __syncthreads();
    for (int off = 128; off > 0; off >>= 1) {
        if (threadIdx.x < off) red[threadIdx.x] += red[threadIdx.x + off];
        __syncthreads();
    }
    if (threadIdx.x == 0) part[blockIdx.y * 1024 + blockIdx.x] = red[0];
}

__global__ void scale_finalize(const float* __restrict__ part,
                               float* __restrict__ scales, int nblk, float inv_n) {
    __shared__ float red[256];
    const float* p = part + blockIdx.x * nblk;
    float s = 0.f;
    for (int i = threadIdx.x; i < nblk; i += blockDim.x) s += p[i];
    red[threadIdx.x] = s;
    __syncthreads();
    for (int off = 128; off > 0; off >>= 1) {
        if (threadIdx.x < off) red[threadIdx.x] += red[threadIdx.x + off];
        __syncthreads();
    }
    if (threadIdx.x == 0) scales[blockIdx.x] = fmaxf(red[0] * inv_n, 1e-5f);
}

// fused weight prep: y=0: quant(qw)+conv(ow); y=1: quant(kw)+conv(kw);
//                    y=2: quant(vw)+conv(vw)
__global__ void wprep3(const float* __restrict__ qw, const float* __restrict__ kw,
                       const float* __restrict__ vw, const float* __restrict__ ow,
                       __half* __restrict__ wb, __half* __restrict__ owh,
                       __half* __restrict__ kwh, __half* __restrict__ vwh,
                       const float* __restrict__ scales, int n) {
    int s = blockIdx.y;
    const float* wsrc = (s == 0) ? qw : (s == 1) ? kw : vw;
    __half* qdst = wb + (size_t)s * n;
    float sc = scales[s];
    int gid = blockIdx.x * blockDim.x + threadIdx.x;   // n/8 threads
    const float4* w4 = (const float4*)wsrc;
    float4 a = w4[2 * gid], b = w4[2 * gid + 1];
    float v[8] = {a.x, a.y, a.z, a.w, b.x, b.y, b.z, b.w};
    __half hq[8];
#pragma unroll
    for (int j = 0; j < 8; j++) {
        float q = rintf(__fdiv_rn(v[j], sc));
        hq[j] = __float2half_rn(fminf(fmaxf(q, -1.f), 1.f));
    }
    *(float4*)&qdst[(size_t)gid * 8] = *(float4*)hq;

    // conv path
    __half* cdst = (s == 0) ? owh : (s == 1) ? kwh : vwh;
    if (s == 0) {
        const float4* o4 = (const float4*)ow;
        a = o4[2 * gid]; b = o4[2 * gid + 1];
        float t[8] = {a.x, a.y, a.z, a.w, b.x, b.y, b.z, b.w};
#pragma unroll
        for (int j = 0; j < 8; j++) hq[j] = __float2half_rn(t[j]);
    } else {
#pragma unroll
        for (int j = 0; j < 8; j++) hq[j] = __float2half_rn(v[j]);
    }
    *(float4*)&cdst[(size_t)gid * 8] = *(float4*)hq;
}

// per-token int8 absmax quant (blocks < B*S) + rt fp16 convert (blocks >= B*S)
__global__ void quant_act_k(const float* __restrict__ x,
                            const float* __restrict__ rt,
                            __half* __restrict__ xb,
                            __half* __restrict__ rth,
                            float* __restrict__ as_) {
    __shared__ float red[256];
    int tid = threadIdx.x;
    if (blockIdx.x >= B_DIM * S_DIM) {
        int gid = (blockIdx.x - B_DIM * S_DIM) * 256 + tid;
        const float4* s4 = (const float4*)rt;
        float4 a = s4[2 * gid], b = s4[2 * gid + 1];
        __half h[8] = {__float2half_rn(a.x), __float2half_rn(a.y),
                       __float2half_rn(a.z), __float2half_rn(a.w),
                       __float2half_rn(b.x), __float2half_rn(b.y),
                       __float2half_rn(b.z), __float2half_rn(b.w)};
        *(float4*)&rth[(size_t)gid * 8] = *(float4*)h;
        return;
    }
    int row = blockIdx.x;
    const float4* xr4 = (const float4*)(x + (size_t)row * E_DIM);
    float4 a = xr4[2 * tid], b = xr4[2 * tid + 1];
    float v[8] = {a.x, a.y, a.z, a.w, b.x, b.y, b.z, b.w};
    float m = 0.f;
#pragma unroll
    for (int j = 0; j < 8; j++) m = fmaxf(m, fabsf(v[j]));
    red[tid] = m;
    __syncthreads();
    for (int off = 128; off > 0; off >>= 1) {
        if (tid < off) red[tid] = fmaxf(red[tid], red[tid + off]);
        __syncthreads();
    }
    float mx = fmaxf(red[0], 1e-5f);
    float s = __fdiv_rn(127.f, mx);
    if (tid == 0) as_[row] = __fdiv_rn(1.f, s);
    __half h[8];
#pragma unroll
    for (int j = 0; j < 8; j++) {
        float q = rintf(v[j] * s);
        h[j] = __float2half_rn(fminf(fmaxf(q, -128.f), 127.f));
    }
    *(float4*)&xb[(size_t)row * E_DIM + tid * 8] = *(float4*)h;
}

// ---------------- fp16 tensor-core NT GEMM (up to 10 jobs, per-job M) ---------
struct HJobs {
    const __half* A[10];
    const __half* W[10];
    void* C[10];
    const float* rs[10];
    const float* ws[10];
    int mode[10];
    int Mz[10];
    const float* bias;
};

__device__ __forceinline__ uint32_t swz(uint32_t o) { return o ^ ((o >> 3) & 0x70); }

__global__ __launch_bounds__(256, 1) void hgemm_nt(HJobs jobs, int M, int N, int K) {
    extern __shared__ __align__(128) char sm_raw[];
    int z = blockIdx.z;
    if ((int)blockIdx.y * 128 >= jobs.Mz[z]) return;
    const __half* A = jobs.A[z];
    const __half* W = jobs.W[z];
    const float* rs = jobs.rs[z];
    const float* ws = jobs.ws[z];
    int mode = jobs.mode[z];

    uint32_t sbase = (uint32_t)__cvta_generic_to_shared(sm_raw);
    int tid = threadIdx.x, lane = tid & 31, warp = tid >> 5;
    int wm = warp >> 1, wn = warp & 1;
    int bm = blockIdx.y * 128, bn = blockIdx.x * 128;

    const __half* Ag = A + (size_t)bm * K;
    const __half* Wg = W + (size_t)bn * K;

    float acc[2][8][4];
#pragma unroll
    for (int mf = 0; mf < 2; mf++)
#pragma unroll
        for (int nf = 0; nf < 8; nf++)
#pragma unroll
            for (int c = 0; c < 4; c++) acc[mf][nf][c] = 0.f;

    float4 sa[4], sw[4];
#pragma unroll
    for (int i = 0; i < 4; i++) {
        int idx = i * 256 + tid;
        int row = idx >> 3, c = idx & 7;
        sa[i] = *(const float4*)(Ag + (size_t)row * K + c * 8);
        sw[i] = *(const float4*)(Wg + (size_t)row * K + c * 8);
    }
#pragma unroll
    for (int i = 0; i < 4; i++) {
        int idx = i * 256 + tid;
        int row = idx >> 3, c = idx & 7;
        uint32_t off = swz((uint32_t)(row * 128 + c * 16));
        *(float4*)(sm_raw + off) = sa[i];
        *(float4*)(sm_raw + 16384 + off) = sw[i];
    }
    __syncthreads();

    int KT = K >> 6;
    for (int kt = 0; kt < KT; kt++) {
        int cur = kt & 1;
        if (kt + 1 < KT) {
#pragma unroll
            for (int i = 0; i < 4; i++) {
                int idx = i * 256 + tid;
                int row = idx >> 3, c = idx & 7;
                sa[i] = *(const float4*)(Ag + (size_t)row * K + (kt + 1) * 64 + c * 8);
                sw[i] = *(const float4*)(Wg + (size_t)row * K + (kt + 1) * 64 + c * 8);
            }
        }
        uint32_t abase = sbase + cur * 32768;
        uint32_t wbase = abase + 16384;
#pragma unroll
        for (int ks = 0; ks < 4; ks++) {
            uint32_t a[2][4];
#pragma unroll
            for (int mf = 0; mf < 2; mf++) {
                int r = wm * 32 + mf * 16 + ((lane >> 3) & 1) * 8 + (lane & 7);
                uint32_t off = swz((uint32_t)(r * 128 + ks * 32 + ((lane >> 4) & 1) * 16));
                asm volatile(
                    "ldmatrix.sync.aligned.m8n8.x4.shared.b16 {%0,%1,%2,%3}, [%4];"
                    : "=r"(a[mf][0]), "=r"(a[mf][1]), "=r"(a[mf][2]), "=r"(a[mf][3])
                    : "r"(abase + off));
            }
            uint32_t b0[8], b1[8];
#pragma unroll
            for (int q = 0; q < 4; q++) {
                int r = wn * 64 + q * 16 + ((lane >> 3) & 1) * 8 + (lane & 7);
                uint32_t off = swz((uint32_t)(r * 128 + ks * 32 + ((lane >> 4) & 1) * 16));
                uint32_t r0, r1, r2, r3;
                asm volatile(
                    "ldmatrix.sync.aligned.m8n8.x4.shared.b16 {%0,%1,%2,%3}, [%4];"
                    : "=r"(r0), "=r"(r1), "=r"(r2), "=r"(r3)
                    : "r"(wbase + off));
                b0[2 * q] = r0; b0[2 * q + 1] = r1;
                b1[2 * q] = r2; b1[2 * q + 1] = r3;
            }
#pragma unroll
            for (int mf = 0; mf < 2; mf++)
#pragma unroll
                for (int nf = 0; nf < 8; nf++)
                    asm volatile(
                        "mma.sync.aligned.m16n8k16.row.col.f32.f16.f16.f32 "
                        "{%0,%1,%2,%3},{%4,%5,%6,%7},{%8,%9},{%0,%1,%2,%3};"
                        : "+f"(acc[mf][nf][0]), "+f"(acc[mf][nf][1]),
                          "+f"(acc[mf][nf][2]), "+f"(acc[mf][nf][3])
                        : "r"(a[mf][0]), "r"(a[mf][1]), "r"(a[mf][2]), "r"(a[mf][3]),
                          "r"(b0[nf]), "r"(b1[nf]));
        }
        if (kt + 1 < KT) {
            int nxt = cur ^ 1;
#pragma unroll
            for (int i = 0; i < 4; i++) {
                int idx = i * 256 + tid;
                int row = idx >> 3, c = idx & 7;
                uint32_t off = swz((uint32_t)(row * 128 + c * 16));
                *(float4*)(sm_raw + nxt * 32768 + off) = sa[i];
                *(float4*)(sm_raw + nxt * 32768 + 16384 + off) = sw[i];
            }
        }
        __syncthreads();
    }

    int g = lane >> 2, t = lane & 3;
    float wsv = ws ? *ws : 1.f;
    if (mode == 2) {
        __half* Ob = (__half*)jobs.C[z];
#pragma unroll
        for (int mf = 0; mf < 2; mf++) {
            int row0 = bm + wm * 32 + mf * 16 + g;
            float r0s = (rs ? rs[row0] : 1.f) * wsv;
            float r1s = (rs ? rs[row0 + 8] : 1.f) * wsv;
#pragma unroll
            for (int nf = 0; nf < 8; nf++) {
                int col = bn + wn * 64 + nf * 8 + 2 * t;
                int hh = col >> 7, d = col & 127;
                size_t i0 = (size_t)row0 * KVROWW + hh * 128 + d;
                size_t i8 = (size_t)(row0 + 8) * KVROWW + hh * 128 + d;
                *(__half2*)&Ob[i0] = __floats2half2_rn(acc[mf][nf][0] * r0s,
                                                       acc[mf][nf][1] * r0s);
                *(__half2*)&Ob[i8] = __floats2half2_rn(acc[mf][nf][2] * r1s,
                                                       acc[mf][nf][3] * r1s);
            }
        }
    } else {
        float* C = (float*)jobs.C[z];
        const float* bias = jobs.bias;
#pragma unroll
        for (int mf = 0; mf < 2; mf++) {
            int row0 = bm + wm * 32 + mf * 16 + g;
#pragma unroll
            for (int nf = 0; nf < 8; nf++) {
                int col = bn + wn * 64 + nf * 8 + 2 * t;
                float b0v = bias ? bias[col] : 0.f;
                float b1v = bias ? bias[col + 1] : 0.f;
                float2 v0 = make_float2(acc[mf][nf][0] + b0v, acc[mf][nf][1] + b1v);
                float2 v1 = make_float2(acc[mf][nf][2] + b0v, acc[mf][nf][3] + b1v);
                *(float2*)&C[(size_t)row0 * N + col] = v0;
                *(float2*)&C[(size_t)(row0 + 8) * N + col] = v1;
            }
        }
    }
}

// ---------------- fp16 flash attention, BK=128, P aliases Q ------------------
#define ATT_P_OFF 0            /* [128][256B] = 32KB: Q at start, P after tile 0 */
#define ATT_K_OFF 32768        /* 2 x [128][256B] = 128KB */
#define ATT_V_OFF 163840       /* 1 x [128][256B] = 64KB */
#define ATT_SMEM 229376

__device__ __forceinline__ uint32_t sw256o(int r, int c) {
    return (uint32_t)(r * 256 + ((((c >> 3) ^ (r & 7))) << 4) + ((c & 7) << 1));
}
__device__ __forceinline__ void ldsm4(uint32_t addr, uint32_t& r0, uint32_t& r1,
                                      uint32_t& r2, uint32_t& r3) {
    asm volatile("ldmatrix.sync.aligned.m8n8.x4.shared.b16 {%0,%1,%2,%3}, [%4];"
                 : "=r"(r0), "=r"(r1), "=r"(r2), "=r"(r3) : "r"(addr));
}
__device__ __forceinline__ void ldsm4t(uint32_t addr, uint32_t& r0, uint32_t& r1,
                                       uint32_t& r2, uint32_t& r3) {
    asm volatile("ldmatrix.sync.aligned.m8n8.x4.trans.shared.b16 {%0,%1,%2,%3}, [%4];"
                 : "=r"(r0), "=r"(r1), "=r"(r2), "=r"(r3) : "r"(addr));
}
__device__ __forceinline__ void cpa16g(uint32_t dst, const void* src) {
    asm volatile("cp.async.cg.shared.global [%0], [%1], 16;" :: "r"(dst), "l"(src));
}
__device__ __forceinline__ void cp_commitg() {
    asm volatile("cp.async.commit_group;" ::: "memory");
}
#define MMA_F16(d, a, b0v, b1v) \
    asm volatile( \
        "mma.sync.aligned.m16n8k16.row.col.f32.f16.f16.f32 " \
        "{%0,%1,%2,%3},{%4,%5,%6,%7},{%8,%9},{%0,%1,%2,%3};" \
        : "+f"((d)[0]), "+f"((d)[1]), "+f"((d)[2]), "+f"((d)[3]) \
        : "r"((a)[0]), "r"((a)[1]), "r"((a)[2]), "r"((a)[3]), \
          "r"(b0v), "r"(b1v))

__global__ __launch_bounds__(256, 1) void attn_tc(const __half* __restrict__ Qs,
                                                  const __half* __restrict__ Ks,
                                                  const __half* __restrict__ Vs,
                                                  __half* __restrict__ AO) {
    extern __shared__ __align__(128) char smc[];
    uint32_t sb = (uint32_t)__cvta_generic_to_shared(smc);

    int tid = threadIdx.x, lane = tid & 31, w = tid >> 5;
    int g = lane >> 2, t = lane & 3;
    int q0 = blockIdx.x * 128;
    int h = blockIdx.y, b = blockIdx.z;

    const __half* Qg = Qs + (size_t)(b * S_DIM + q0) * KVROWW + h * 128;
    const __half* Kg = Ks + (size_t)(b * T_DIM) * KVROWW + h * 128;
    const __half* Vg = Vs + (size_t)(b * T_DIM) * KVROWW + h * 128;

    const int NT = T_DIM / 128;  // 17

#pragma unroll
    for (int it = 0; it < 8; it++) {
        int idx = it * 256 + tid;
        int r = idx >> 4, c = (idx & 15) * 8;
        cpa16g(sb + ATT_P_OFF + sw256o(r, c), Qg + (size_t)r * KVROWW + c);
    }
#pragma unroll
    for (int it = 0; it < 8; it++) {
        int idx = it * 256 + tid;
        int r = idx >> 4, c = (idx & 15) * 8;
        cpa16g(sb + ATT_K_OFF + sw256o(r, c), Kg + (size_t)r * KVROWW + c);
    }
    cp_commitg();
#pragma unroll
    for (int it = 0; it < 8; it++) {
        int idx = it * 256 + tid;
        int r = idx >> 4, c = (idx & 15) * 8;
        cpa16g(sb + ATT_V_OFF + sw256o(r, c), Vg + (size_t)r * KVROWW + c);
    }
    cp_commitg();
#pragma unroll
    for (int it = 0; it < 8; it++) {
        int idx = it * 256 + tid;
        int r = idx >> 4, c = (idx & 15) * 8;
        cpa16g(sb + ATT_K_OFF + 65536 + sw256o(r, c),
               Kg + (size_t)(128 + r) * KVROWW + c);
    }
    cp_commitg();

    float o[16][4];
#pragma unroll
    for (int nf = 0; nf < 16; nf++)
#pragma unroll
        for (int c = 0; c < 4; c++) o[nf][c] = 0.f;
    float m0 = -1e30f, m8 = -1e30f, l0 = 0.f, l8 = 0.f;

    uint32_t qf[8][4];
    const float scl = 0.08838834764831845f;
    int rg = w * 16 + g;
    int arow_f = w * 16 + ((lane >> 3) & 1) * 8 + (lane & 7);
    int acol_f = ((lane >> 4) & 1) * 8;

    for (int i = 0; i < NT; i++) {
        asm volatile("cp.async.wait_group 2;" ::: "memory");
        __syncthreads();

        if (i == 0) {
#pragma unroll
            for (int kk = 0; kk < 8; kk++)
                ldsm4(sb + ATT_P_OFF + sw256o(arow_f, kk * 16 + acol_f),
                      qf[kk][0], qf[kk][1], qf[kk][2], qf[kk][3]);
        }

        uint32_t kbuf = sb + ATT_K_OFF + (i & 1) * 65536;

        float accs[16][4];
#pragma unroll
        for (int nf = 0; nf < 16; nf++)
#pragma unroll
            for (int c = 0; c < 4; c++) accs[nf][c] = 0.f;

#pragma unroll
        for (int kk = 0; kk < 8; kk++) {
#pragma unroll
            for (int hf = 0; hf < 2; hf++) {
                uint32_t b0[8], b1[8];
#pragma unroll
                for (int nb = 0; nb < 4; nb++) {
                    int br = hf * 64 + nb * 16 + ((lane >> 3) & 1) * 8 + (lane & 7);
                    uint32_t r0, r1, r2, r3;
                    ldsm4(kbuf + sw256o(br, kk * 16 + acol_f), r0, r1, r2, r3);
                    b0[2 * nb] = r0; b0[2 * nb + 1] = r1;
                    b1[2 * nb] = r2; b1[2 * nb + 1] = r3;
                }
#pragma unroll
                for (int nf = 0; nf < 8; nf++)
                    MMA_F16(accs[hf * 8 + nf], qf[kk], b0[nf], b1[nf]);
            }
        }

        float mx0 = -1e30f, mx8 = -1e30f;
#pragma unroll
        for (int nf = 0; nf < 16; nf++) {
            accs[nf][0] *= scl; accs[nf][1] *= scl;
            accs[nf][2] *= scl; accs[nf][3] *= scl;
            mx0 = fmaxf(mx0, fmaxf(accs[nf][0], accs[nf][1]));
            mx8 = fmaxf(mx8, fmaxf(accs[nf][2], accs[nf][3]));
        }
        mx0 = fmaxf(mx0, __shfl_xor_sync(0xffffffffu, mx0, 1));
        mx0 = fmaxf(mx0, __shfl_xor_sync(0xffffffffu, mx0, 2));
        mx8 = fmaxf(mx8, __shfl_xor_sync(0xffffffffu, mx8, 1));
        mx8 = fmaxf(mx8, __shfl_xor_sync(0xffffffffu, mx8, 2));
        float mn0 = fmaxf(m0, mx0), mn8 = fmaxf(m8, mx8);
        float al0 = __expf(m0 - mn0), al8 = __expf(m8 - mn8);
        m0 = mn0; m8 = mn8;
        float sum0 = 0.f, sum8 = 0.f;
#pragma unroll
        for (int nf = 0; nf < 16; nf++) {
            int c = nf * 8 + 2 * t;
            float p0 = __expf(accs[nf][0] - mn0);
            float p1 = __expf(accs[nf][1] - mn0);
            sum0 += p0 + p1;
            *(__half2*)(smc + ATT_P_OFF + sw256o(rg, c)) = __floats2half2_rn(p0, p1);
            float p2 = __expf(accs[nf][2] - mn8);
            float p3 = __expf(accs[nf][3] - mn8);
            sum8 += p2 + p3;
            *(__half2*)(smc + ATT_P_OFF + sw256o(rg + 8, c)) =
                __floats2half2_rn(p2, p3);
        }
        sum0 += __shfl_xor_sync(0xffffffffu, sum0, 1);
        sum0 += __shfl_xor_sync(0xffffffffu, sum0, 2);
        sum8 += __shfl_xor_sync(0xffffffffu, sum8, 1);
        sum8 += __shfl_xor_sync(0xffffffffu, sum8, 2);
        l0 = l0 * al0 + sum0;
        l8 = l8 * al8 + sum8;
#pragma unroll
        for (int nf = 0; nf < 16; nf++) {
            o[nf][0] *= al0; o[nf][1] *= al0;
            o[nf][2] *= al8; o[nf][3] *= al8;
        }

        asm volatile("cp.async.wait_group 1;" ::: "memory");
        __syncthreads();

        uint32_t vbuf = sb + ATT_V_OFF;
#pragma unroll
        for (int vv = 0; vv < 8; vv++) {
            uint32_t vb[8][4];
#pragma unroll
            for (int ng = 0; ng < 8; ng++) {
                int vr = vv * 16 + ((lane >> 3) & 1) * 8 + (lane & 7);
                ldsm4t(vbuf + sw256o(vr, ng * 16 + acol_f),
                       vb[ng][0], vb[ng][1], vb[ng][2], vb[ng][3]);
            }
            uint32_t ah[4];
            ldsm4(sb + ATT_P_OFF + sw256o(arow_f, vv * 16 + acol_f),
                  ah[0], ah[1], ah[2], ah[3]);
#pragma unroll
            for (int ng = 0; ng < 8; ng++) {
                MMA_F16(o[2 * ng], ah, vb[ng][0], vb[ng][1]);
                MMA_F16(o[2 * ng + 1], ah, vb[ng][2], vb[ng][3]);
            }
        }
        __syncthreads();

        if (i + 1 < NT) {
            int tV = (i + 1) * 128;
#pragma unroll
            for (int it = 0; it < 8; it++) {
                int idx = it * 256 + tid;
                int r = idx >> 4, c = (idx & 15) * 8;
                cpa16g(sb + ATT_V_OFF + sw256o(r, c),
                       Vg + (size_t)(tV + r) * KVROWW + c);
            }
        }
        cp_commitg();
        if (i + 2 < NT) {
            int tK = (i + 2) * 128;
            uint32_t kb2 = sb + ATT_K_OFF + (i & 1) * 65536;
#pragma unroll
            for (int it = 0; it < 8; it++) {
                int idx = it * 256 + tid;
                int r = idx >> 4, c = (idx & 15) * 8;
                cpa16g(kb2 + sw256o(r, c), Kg + (size_t)(tK + r) * KVROWW + c);
            }
        }
        cp_commitg();
    }

    {
        float li0 = __fdiv_rn(1.f, l0);
        float li8 = __fdiv_rn(1.f, l8);
        size_t grow0 = (size_t)(b * S_DIM + q0 + rg) * E_DIM + h * D_DIM;
        size_t grow8 = grow0 + (size_t)8 * E_DIM;
#pragma unroll
        for (int nf = 0; nf < 16; nf++) {
            int c = nf * 8 + 2 * t;
            *(__half2*)&AO[grow0 + c] =
                __floats2half2_rn(o[nf][0] * li0, o[nf][1] * li0);
            *(__half2*)&AO[grow8 + c] =
                __floats2half2_rn(o[nf][2] * li8, o[nf][3] * li8);
        }
    }
}

// ---------------- launcher ----------------------------------------------------
extern "C" void kernel_launch(void* const* d_in, const int* in_sizes, int n_in,
                              void* d_out, int out_size) {
    const float* x  = (const float*)d_in[0];
    const float* rt = (const float*)d_in[1];
    const float* qw = (const float*)d_in[2];
    const float* kw = (const float*)d_in[3];
    const float* vw = (const float*)d_in[4];
    const float* ow = (const float*)d_in[5];
    const float* ob = (const float*)d_in[6];
    float* out = (float*)d_out;

    __half *p_wb, *p_xb, *p_qs, *p_ks, *p_vs, *p_ao, *p_ow, *p_kwf, *p_vwf, *p_rt;
    float *p_as, *p_part, *p_scales;
    cudaGetSymbolAddress((void**)&p_wb, g_wb);
    cudaGetSymbolAddress((void**)&p_xb, g_xb);
    cudaGetSymbolAddress((void**)&p_as, g_as);
    cudaGetSymbolAddress((void**)&p_qs, g_qs);
    cudaGetSymbolAddress((void**)&p_ks, g_ks);
    cudaGetSymbolAddress((void**)&p_vs, g_vs);
    cudaGetSymbolAddress((void**)&p_ao, g_ao);
    cudaGetSymbolAddress((void**)&p_ow, g_ow);
    cudaGetSymbolAddress((void**)&p_kwf, g_kwf);
    cudaGetSymbolAddress((void**)&p_vwf, g_vwf);
    cudaGetSymbolAddress((void**)&p_rt, g_rt);
    cudaGetSymbolAddress((void**)&p_part, g_part);
    cudaGetSymbolAddress((void**)&p_scales, g_scales);

    const int n = E_DIM * E_DIM;

    // 1. scales + fused weight prep (ternary fp16 + raw fp16 converts)
    absmean3<<<dim3(1024, 3), 256>>>(qw, kw, vw, p_part, n);
    scale_finalize<<<3, 256>>>(p_part, p_scales, 1024, 1.f / (float)n);
    wprep3<<<dim3(n / 8 / 256, 3), 256>>>(qw, kw, vw, ow, p_wb, p_ow, p_kwf,
                                          p_vwf, p_scales, n);

    // 2. activation quant + rt convert (fused via grid extension)
    quant_act_k<<<B_DIM * S_DIM + (B_DIM * R_DIM * E_DIM) / 8 / 256, 256>>>(
        x, rt, p_xb, p_rt, p_as);

    // 3+4. QKV projections + rk/rv in ONE launch (rk/rv fills QKV tail)
    HJobs j1 = {};
    for (int z = 0; z < 6; z++) {
        int w = z >> 1, batch = z & 1;
        j1.A[z] = p_xb + (size_t)batch * S_DIM * E_DIM;
        j1.W[z] = p_wb + (size_t)w * n;
        if (w == 0)
            j1.C[z] = p_qs + (size_t)batch * S_DIM * KVROWW;
        else if (w == 1)
            j1.C[z] = p_ks + (size_t)batch * T_DIM * KVROWW;
        else
            j1.C[z] = p_vs + (size_t)batch * T_DIM * KVROWW;
        j1.rs[z] = p_as + (size_t)batch * S_DIM;
        j1.ws[z] = p_scales + w;
        j1.mode[z] = 2;
        j1.Mz[z] = S_DIM;
    }
    for (int z = 6; z < 10; z++) {
        int w = (z - 6) >> 1, batch = (z - 6) & 1;
        j1.A[z] = p_rt + (size_t)batch * R_DIM * E_DIM;
        j1.W[z] = (w == 0) ? p_kwf : p_vwf;
        j1.C[z] = ((w == 0) ? p_ks : p_vs) +
                  ((size_t)batch * T_DIM + S_DIM) * KVROWW;
        j1.rs[z] = nullptr;
        j1.ws[z] = nullptr;
        j1.mode[z] = 2;
        j1.Mz[z] = R_DIM;
    }
    j1.bias = nullptr;
    cudaFuncSetAttribute(hgemm_nt, cudaFuncAttributeMaxDynamicSharedMemorySize,
                         65536);
    hgemm_nt<<<dim3(16, 16, 10), 256, 65536>>>(j1, S_DIM, E_DIM, E_DIM);

    // 5. fp16 flash attention (BK=128) -> AO
    cudaFuncSetAttribute(attn_tc, cudaFuncAttributeMaxDynamicSharedMemorySize,
                         ATT_SMEM);
    attn_tc<<<dim3(S_DIM / 128, H_DIM, B_DIM), 256, ATT_SMEM>>>(p_qs, p_ks, p_vs,
                                                                p_ao);

    // 6. output projection: fp16 GEMM over K=2048 + bias
    HJobs j3 = {};
    j3.A[0] = p_ao;
    j3.W[0] = p_ow;
    j3.C[0] = out;
    j3.rs[0] = nullptr;
    j3.ws[0] = nullptr;
    j3.mode[0] = 0;
    j3.Mz[0] = B_DIM * S_DIM;
    j3.bias = ob;
    hgemm_nt<<<dim3(16, 32, 1), 256, 65536>>>(j3, B_DIM * S_DIM, E_DIM, E_DIM);
}

// round 16
// speedup vs baseline: 4.8911x; 1.0358x over previous
#include <cuda_runtime.h>
#include <cuda_fp16.h>
#include <math.h>
#include <stdint.h>

#define E_DIM 2048
#define B_DIM 2
#define S_DIM 2048
#define R_DIM 128
#define H_DIM 16
#define D_DIM 128
#define T_DIM (S_DIM + R_DIM)   /* 2176 */
#define KVROWW 2048             /* Q/K/V row: H*128 fp16 */

// ---------------- scratch -----------------------------------------------------
__device__ __half g_wb[3][E_DIM * E_DIM];        // ternary weights fp16 (exact)
__device__ __half g_xb[B_DIM * S_DIM * E_DIM];   // int8-valued acts fp16 (exact)
__device__ float g_as[B_DIM * S_DIM];            // per-token 1/s
__device__ __half g_qs[(size_t)B_DIM * S_DIM * KVROWW]; // Q fp16
__device__ __half g_ks[(size_t)B_DIM * T_DIM * KVROWW]; // K fp16
__device__ __half g_vs[(size_t)B_DIM * T_DIM * KVROWW]; // V fp16
__device__ __half g_ao[(size_t)B_DIM * S_DIM * E_DIM];  // AO fp16
__device__ __half g_ow[(size_t)E_DIM * E_DIM];          // out_w fp16
__device__ __half g_kwf[(size_t)E_DIM * E_DIM];         // raw k_w fp16
__device__ __half g_vwf[(size_t)E_DIM * E_DIM];         // raw v_w fp16
__device__ __half g_rt[(size_t)B_DIM * R_DIM * E_DIM];  // reasoning tokens fp16
__device__ float g_part[3 * 1024];
__device__ float g_scales[3];

// ---------------- prep kernels ------------------------------------------------
__global__ void absmean3(const float* __restrict__ qw, const float* __restrict__ kw,
                         const float* __restrict__ vw, float* __restrict__ part,
                         int n) {
    __shared__ float red[256];
    const float* w = (blockIdx.y == 0) ? qw : (blockIdx.y == 1) ? kw : vw;
    int chunk4 = (n / gridDim.x) >> 2;
    const float4* w4 = (const float4*)w + (size_t)blockIdx.x * chunk4;
    float s = 0.f;
    for (int i = threadIdx.x; i < chunk4; i += blockDim.x) {
        float4 v = w4[i];
        s += fabsf(v.x) + fabsf(v.y) + fabsf(v.z) + fabsf(v.w);
    }
    red[threadIdx.x] = s;
    __syncthreads();
    for (int off = 128; off > 0; off >>= 1) {
        if (threadIdx.x < off) red[threadIdx.x] += red[threadIdx.x + off];
        __syncthreads();
    }
    if (threadIdx.x == 0) part[blockIdx.y * 1024 + blockIdx.x] = red[0];
}

__global__ void scale_finalize(const float* __restrict__ part,
                               float* __restrict__ scales, int nblk, float inv_n) {
    __shared__ float red[256];
    const float* p = part + blockIdx.x * nblk;
    float s = 0.f;
    for (int i = threadIdx.x; i < nblk; i += blockDim.x) s += p[i];
    red[threadIdx.x] = s;
    __syncthreads();
    for (int off = 128; off > 0; off >>= 1) {
        if (threadIdx.x < off) red[threadIdx.x] += red[threadIdx.x + off];
        __syncthreads();
    }
    if (threadIdx.x == 0) scales[blockIdx.x] = fmaxf(red[0] * inv_n, 1e-5f);
}

// fused weight prep: y=0: quant(qw)+conv(ow); y=1: quant(kw)+conv(kw);
//                    y=2: quant(vw)+conv(vw)
__global__ void wprep3(const float* __restrict__ qw, const float* __restrict__ kw,
                       const float* __restrict__ vw, const float* __restrict__ ow,
                       __half* __restrict__ wb, __half* __restrict__ owh,
                       __half* __restrict__ kwh, __half* __restrict__ vwh,
                       const float* __restrict__ scales, int n) {
    int s = blockIdx.y;
    const float* wsrc = (s == 0) ? qw : (s == 1) ? kw : vw;
    __half* qdst = wb + (size_t)s * n;
    float sc = scales[s];
    int gid = blockIdx.x * blockDim.x + threadIdx.x;
    const float4* w4 = (const float4*)wsrc;
    float4 a = w4[2 * gid], b = w4[2 * gid + 1];
    float v[8] = {a.x, a.y, a.z, a.w, b.x, b.y, b.z, b.w};
    __half hq[8];
#pragma unroll
    for (int j = 0; j < 8; j++) {
        float q = rintf(__fdiv_rn(v[j], sc));
        hq[j] = __float2half_rn(fminf(fmaxf(q, -1.f), 1.f));
    }
    *(float4*)&qdst[(size_t)gid * 8] = *(float4*)hq;

    __half* cdst = (s == 0) ? owh : (s == 1) ? kwh : vwh;
    if (s == 0) {
        const float4* o4 = (const float4*)ow;
        a = o4[2 * gid]; b = o4[2 * gid + 1];
        float t[8] = {a.x, a.y, a.z, a.w, b.x, b.y, b.z, b.w};
#pragma unroll
        for (int j = 0; j < 8; j++) hq[j] = __float2half_rn(t[j]);
    } else {
#pragma unroll
        for (int j = 0; j < 8; j++) hq[j] = __float2half_rn(v[j]);
    }
    *(float4*)&cdst[(size_t)gid * 8] = *(float4*)hq;
}

// per-token int8 absmax quant (blocks < B*S) + rt fp16 convert (blocks >= B*S)
__global__ void quant_act_k(const float* __restrict__ x,
                            const float* __restrict__ rt,
                            __half* __restrict__ xb,
                            __half* __restrict__ rth,
                            float* __restrict__ as_) {
    __shared__ float red[256];
    int tid = threadIdx.x;
    if (blockIdx.x >= B_DIM * S_DIM) {
        int gid = (blockIdx.x - B_DIM * S_DIM) * 256 + tid;
        const float4* s4 = (const float4*)rt;
        float4 a = s4[2 * gid], b = s4[2 * gid + 1];
        __half h[8] = {__float2half_rn(a.x), __float2half_rn(a.y),
                       __float2half_rn(a.z), __float2half_rn(a.w),
                       __float2half_rn(b.x), __float2half_rn(b.y),
                       __float2half_rn(b.z), __float2half_rn(b.w)};
        *(float4*)&rth[(size_t)gid * 8] = *(float4*)h;
        return;
    }
    int row = blockIdx.x;
    const float4* xr4 = (const float4*)(x + (size_t)row * E_DIM);
    float4 a = xr4[2 * tid], b = xr4[2 * tid + 1];
    float v[8] = {a.x, a.y, a.z, a.w, b.x, b.y, b.z, b.w};
    float m = 0.f;
#pragma unroll
    for (int j = 0; j < 8; j++) m = fmaxf(m, fabsf(v[j]));
    red[tid] = m;
    __syncthreads();
    for (int off = 128; off > 0; off >>= 1) {
        if (tid < off) red[tid] = fmaxf(red[tid], red[tid + off]);
        __syncthreads();
    }
    float mx = fmaxf(red[0], 1e-5f);
    float s = __fdiv_rn(127.f, mx);
    if (tid == 0) as_[row] = __fdiv_rn(1.f, s);
    __half h[8];
#pragma unroll
    for (int j = 0; j < 8; j++) {
        float q = rintf(v[j] * s);
        h[j] = __float2half_rn(fminf(fmaxf(q, -128.f), 127.f));
    }
    *(float4*)&xb[(size_t)row * E_DIM + tid * 8] = *(float4*)h;
}

// ---------------- fp16 tensor-core NT GEMM (up to 10 jobs, per-job M) ---------
struct HJobs {
    const __half* A[10];
    const __half* W[10];
    void* C[10];
    const float* rs[10];
    const float* ws[10];
    int mode[10];
    int Mz[10];
    const float* bias;
};

__device__ __forceinline__ uint32_t swz(uint32_t o) { return o ^ ((o >> 3) & 0x70); }

__global__ __launch_bounds__(256, 1) void hgemm_nt(HJobs jobs, int M, int N, int K) {
    extern __shared__ __align__(128) char sm_raw[];
    int z = blockIdx.z;
    if ((int)blockIdx.y * 128 >= jobs.Mz[z]) return;
    const __half* A = jobs.A[z];
    const __half* W = jobs.W[z];
    const float* rs = jobs.rs[z];
    const float* ws = jobs.ws[z];
    int mode = jobs.mode[z];

    uint32_t sbase = (uint32_t)__cvta_generic_to_shared(sm_raw);
    int tid = threadIdx.x, lane = tid & 31, warp = tid >> 5;
    int wm = warp >> 1, wn = warp & 1;
    int bm = blockIdx.y * 128, bn = blockIdx.x * 128;

    const __half* Ag = A + (size_t)bm * K;
    const __half* Wg = W + (size_t)bn * K;

    float acc[2][8][4];
#pragma unroll
    for (int mf = 0; mf < 2; mf++)
#pragma unroll
        for (int nf = 0; nf < 8; nf++)
#pragma unroll
            for (int c = 0; c < 4; c++) acc[mf][nf][c] = 0.f;

    float4 sa[4], sw[4];
#pragma unroll
    for (int i = 0; i < 4; i++) {
        int idx = i * 256 + tid;
        int row = idx >> 3, c = idx & 7;
        sa[i] = *(const float4*)(Ag + (size_t)row * K + c * 8);
        sw[i] = *(const float4*)(Wg + (size_t)row * K + c * 8);
    }
#pragma unroll
    for (int i = 0; i < 4; i++) {
        int idx = i * 256 + tid;
        int row = idx >> 3, c = idx & 7;
        uint32_t off = swz((uint32_t)(row * 128 + c * 16));
        *(float4*)(sm_raw + off) = sa[i];
        *(float4*)(sm_raw + 16384 + off) = sw[i];
    }
    __syncthreads();

    int KT = K >> 6;
    for (int kt = 0; kt < KT; kt++) {
        int cur = kt & 1;
        if (kt + 1 < KT) {
#pragma unroll
            for (int i = 0; i < 4; i++) {
                int idx = i * 256 + tid;
                int row = idx >> 3, c = idx & 7;
                sa[i] = *(const float4*)(Ag + (size_t)row * K + (kt + 1) * 64 + c * 8);
                sw[i] = *(const float4*)(Wg + (size_t)row * K + (kt + 1) * 64 + c * 8);
            }
        }
        uint32_t abase = sbase + cur * 32768;
        uint32_t wbase = abase + 16384;
#pragma unroll
        for (int ks = 0; ks < 4; ks++) {
            uint32_t a[2][4];
#pragma unroll
            for (int mf = 0; mf < 2; mf++) {
                int r = wm * 32 + mf * 16 + ((lane >> 3) & 1) * 8 + (lane & 7);
                uint32_t off = swz((uint32_t)(r * 128 + ks * 32 + ((lane >> 4) & 1) * 16));
                asm volatile(
                    "ldmatrix.sync.aligned.m8n8.x4.shared.b16 {%0,%1,%2,%3}, [%4];"
                    : "=r"(a[mf][0]), "=r"(a[mf][1]), "=r"(a[mf][2]), "=r"(a[mf][3])
                    : "r"(abase + off));
            }
            uint32_t b0[8], b1[8];
#pragma unroll
            for (int q = 0; q < 4; q++) {
                int r = wn * 64 + q * 16 + ((lane >> 3) & 1) * 8 + (lane & 7);
                uint32_t off = swz((uint32_t)(r * 128 + ks * 32 + ((lane >> 4) & 1) * 16));
                uint32_t r0, r1, r2, r3;
                asm volatile(
                    "ldmatrix.sync.aligned.m8n8.x4.shared.b16 {%0,%1,%2,%3}, [%4];"
                    : "=r"(r0), "=r"(r1), "=r"(r2), "=r"(r3)
                    : "r"(wbase + off));
                b0[2 * q] = r0; b0[2 * q + 1] = r1;
                b1[2 * q] = r2; b1[2 * q + 1] = r3;
            }
#pragma unroll
            for (int mf = 0; mf < 2; mf++)
#pragma unroll
                for (int nf = 0; nf < 8; nf++)
                    asm volatile(
                        "mma.sync.aligned.m16n8k16.row.col.f32.f16.f16.f32 "
                        "{%0,%1,%2,%3},{%4,%5,%6,%7},{%8,%9},{%0,%1,%2,%3};"
                        : "+f"(acc[mf][nf][0]), "+f"(acc[mf][nf][1]),
                          "+f"(acc[mf][nf][2]), "+f"(acc[mf][nf][3])
                        : "r"(a[mf][0]), "r"(a[mf][1]), "r"(a[mf][2]), "r"(a[mf][3]),
                          "r"(b0[nf]), "r"(b1[nf]));
        }
        if (kt + 1 < KT) {
            int nxt = cur ^ 1;
#pragma unroll
            for (int i = 0; i < 4; i++) {
                int idx = i * 256 + tid;
                int row = idx >> 3, c = idx & 7;
                uint32_t off = swz((uint32_t)(row * 128 + c * 16));
                *(float4*)(sm_raw + nxt * 32768 + off) = sa[i];
                *(float4*)(sm_raw + nxt * 32768 + 16384 + off) = sw[i];
            }
        }
        __syncthreads();
    }

    int g = lane >> 2, t = lane & 3;
    float wsv = ws ? *ws : 1.f;
    if (mode == 2) {
        __half* Ob = (__half*)jobs.C[z];
#pragma unroll
        for (int mf = 0; mf < 2; mf++) {
            int row0 = bm + wm * 32 + mf * 16 + g;
            float r0s = (rs ? rs[row0] : 1.f) * wsv;
            float r1s = (rs ? rs[row0 + 8] : 1.f) * wsv;
#pragma unroll
            for (int nf = 0; nf < 8; nf++) {
                int col = bn + wn * 64 + nf * 8 + 2 * t;
                int hh = col >> 7, d = col & 127;
                size_t i0 = (size_t)row0 * KVROWW + hh * 128 + d;
                size_t i8 = (size_t)(row0 + 8) * KVROWW + hh * 128 + d;
                *(__half2*)&Ob[i0] = __floats2half2_rn(acc[mf][nf][0] * r0s,
                                                       acc[mf][nf][1] * r0s);
                *(__half2*)&Ob[i8] = __floats2half2_rn(acc[mf][nf][2] * r1s,
                                                       acc[mf][nf][3] * r1s);
            }
        }
    } else {
        float* C = (float*)jobs.C[z];
        const float* bias = jobs.bias;
#pragma unroll
        for (int mf = 0; mf < 2; mf++) {
            int row0 = bm + wm * 32 + mf * 16 + g;
#pragma unroll
            for (int nf = 0; nf < 8; nf++) {
                int col = bn + wn * 64 + nf * 8 + 2 * t;
                float b0v = bias ? bias[col] : 0.f;
                float b1v = bias ? bias[col + 1] : 0.f;
                float2 v0 = make_float2(acc[mf][nf][0] + b0v, acc[mf][nf][1] + b1v);
                float2 v1 = make_float2(acc[mf][nf][2] + b0v, acc[mf][nf][3] + b1v);
                *(float2*)&C[(size_t)row0 * N + col] = v0;
                *(float2*)&C[(size_t)(row0 + 8) * N + col] = v1;
            }
        }
    }
}

// ---------------- fp16 flash attention, BQ=64, BK=128, 128 threads ------------
// 4 warps, warp w owns q-rows [16w,16w+16). P aliases Q. 112KB smem -> 2 CTA/SM.
#define ATT_P_OFF 0            /* [64][256B] = 16KB: Q, then P */
#define ATT_K_OFF 16384        /* 2 x [128][256B] = 64KB */
#define ATT_V_OFF 81920        /* 1 x [128][256B] = 32KB */
#define ATT_SMEM 114688

__device__ __forceinline__ uint32_t sw256o(int r, int c) {
    return (uint32_t)(r * 256 + ((((c >> 3) ^ (r & 7))) << 4) + ((c & 7) << 1));
}
__device__ __forceinline__ void ldsm4(uint32_t addr, uint32_t& r0, uint32_t& r1,
                                      uint32_t& r2, uint32_t& r3) {
    asm volatile("ldmatrix.sync.aligned.m8n8.x4.shared.b16 {%0,%1,%2,%3}, [%4];"
                 : "=r"(r0), "=r"(r1), "=r"(r2), "=r"(r3) : "r"(addr));
}
__device__ __forceinline__ void ldsm4t(uint32_t addr, uint32_t& r0, uint32_t& r1,
                                       uint32_t& r2, uint32_t& r3) {
    asm volatile("ldmatrix.sync.aligned.m8n8.x4.trans.shared.b16 {%0,%1,%2,%3}, [%4];"
                 : "=r"(r0), "=r"(r1), "=r"(r2), "=r"(r3) : "r"(addr));
}
__device__ __forceinline__ void cpa16g(uint32_t dst, const void* src) {
    asm volatile("cp.async.cg.shared.global [%0], [%1], 16;" :: "r"(dst), "l"(src));
}
__device__ __forceinline__ void cp_commitg() {
    asm volatile("cp.async.commit_group;" ::: "memory");
}
#define MMA_F16(d, a, b0v, b1v) \
    asm volatile( \
        "mma.sync.aligned.m16n8k16.row.col.f32.f16.f16.f32 " \
        "{%0,%1,%2,%3},{%4,%5,%6,%7},{%8,%9},{%0,%1,%2,%3};" \
        : "+f"((d)[0]), "+f"((d)[1]), "+f"((d)[2]), "+f"((d)[3]) \
        : "r"((a)[0]), "r"((a)[1]), "r"((a)[2]), "r"((a)[3]), \
          "r"(b0v), "r"(b1v))

__global__ __launch_bounds__(128, 1) void attn_tc(const __half* __restrict__ Qs,
                                                  const __half* __restrict__ Ks,
                                                  const __half* __restrict__ Vs,
                                                  __half* __restrict__ AO) {
    extern __shared__ __align__(128) char smc[];
    uint32_t sb = (uint32_t)__cvta_generic_to_shared(smc);

    int tid = threadIdx.x, lane = tid & 31, w = tid >> 5;   // w in [0,4)
    int g = lane >> 2, t = lane & 3;
    int q0 = blockIdx.x * 64;
    int h = blockIdx.y, b = blockIdx.z;

    const __half* Qg = Qs + (size_t)(b * S_DIM + q0) * KVROWW + h * 128;
    const __half* Kg = Ks + (size_t)(b * T_DIM) * KVROWW + h * 128;
    const __half* Vg = Vs + (size_t)(b * T_DIM) * KVROWW + h * 128;

    const int NT = T_DIM / 128;  // 17

    // prologue: [Q + K0] | [V0] | [K1]  (3 commit groups)
#pragma unroll
    for (int it = 0; it < 8; it++) {          // Q: 64 rows = 1024 float4
        int idx = it * 128 + tid;
        int r = idx >> 4, c = (idx & 15) * 8;
        cpa16g(sb + ATT_P_OFF + sw256o(r, c), Qg + (size_t)r * KVROWW + c);
    }
#pragma unroll
    for (int it = 0; it < 16; it++) {         // K0: 128 rows = 2048 float4
        int idx = it * 128 + tid;
        int r = idx >> 4, c = (idx & 15) * 8;
        cpa16g(sb + ATT_K_OFF + sw256o(r, c), Kg + (size_t)r * KVROWW + c);
    }
    cp_commitg();
#pragma unroll
    for (int it = 0; it < 16; it++) {         // V0
        int idx = it * 128 + tid;
        int r = idx >> 4, c = (idx & 15) * 8;
        cpa16g(sb + ATT_V_OFF + sw256o(r, c), Vg + (size_t)r * KVROWW + c);
    }
    cp_commitg();
#pragma unroll
    for (int it = 0; it < 16; it++) {         // K1
        int idx = it * 128 + tid;
        int r = idx >> 4, c = (idx & 15) * 8;
        cpa16g(sb + ATT_K_OFF + 32768 + sw256o(r, c),
               Kg + (size_t)(128 + r) * KVROWW + c);
    }
    cp_commitg();

    float o[16][4];
#pragma unroll
    for (int nf = 0; nf < 16; nf++)
#pragma unroll
        for (int c = 0; c < 4; c++) o[nf][c] = 0.f;
    float m0 = -1e30f, m8 = -1e30f, l0 = 0.f, l8 = 0.f;

    uint32_t qf[8][4];
    const float scl = 0.08838834764831845f;
    int rg = w * 16 + g;                               // [0,64)
    int arow_f = w * 16 + ((lane >> 3) & 1) * 8 + (lane & 7);  // [0,64)
    int acol_f = ((lane >> 4) & 1) * 8;

    for (int i = 0; i < NT; i++) {
        asm volatile("cp.async.wait_group 2;" ::: "memory");
        __syncthreads();

        if (i == 0) {
#pragma unroll
            for (int kk = 0; kk < 8; kk++)
                ldsm4(sb + ATT_P_OFF + sw256o(arow_f, kk * 16 + acol_f),
                      qf[kk][0], qf[kk][1], qf[kk][2], qf[kk][3]);
        }

        uint32_t kbuf = sb + ATT_K_OFF + (i & 1) * 32768;

        // ---- QK: 8 k-chunks x 16 n-frags ----
        float accs[16][4];
#pragma unroll
        for (int nf = 0; nf < 16; nf++)
#pragma unroll
            for (int c = 0; c < 4; c++) accs[nf][c] = 0.f;

#pragma unroll
        for (int kk = 0; kk < 8; kk++) {
#pragma unroll
            for (int hf = 0; hf < 2; hf++) {
                uint32_t b0[8], b1[8];
#pragma unroll
                for (int nb = 0; nb < 4; nb++) {
                    int br = hf * 64 + nb * 16 + ((lane >> 3) & 1) * 8 + (lane & 7);
                    uint32_t r0, r1, r2, r3;
                    ldsm4(kbuf + sw256o(br, kk * 16 + acol_f), r0, r1, r2, r3);
                    b0[2 * nb] = r0; b0[2 * nb + 1] = r1;
                    b1[2 * nb] = r2; b1[2 * nb + 1] = r3;
                }
#pragma unroll
                for (int nf = 0; nf < 8; nf++)
                    MMA_F16(accs[hf * 8 + nf], qf[kk], b0[nf], b1[nf]);
            }
        }

        // ---- register-space online softmax, Ph fp16 ----
        float mx0 = -1e30f, mx8 = -1e30f;
#pragma unroll
        for (int nf = 0; nf < 16; nf++) {
            accs[nf][0] *= scl; accs[nf][1] *= scl;
            accs[nf][2] *= scl; accs[nf][3] *= scl;
            mx0 = fmaxf(mx0, fmaxf(accs[nf][0], accs[nf][1]));
            mx8 = fmaxf(mx8, fmaxf(accs[nf][2], accs[nf][3]));
        }
        mx0 = fmaxf(mx0, __shfl_xor_sync(0xffffffffu, mx0, 1));
        mx0 = fmaxf(mx0, __shfl_xor_sync(0xffffffffu, mx0, 2));
        mx8 = fmaxf(mx8, __shfl_xor_sync(0xffffffffu, mx8, 1));
        mx8 = fmaxf(mx8, __shfl_xor_sync(0xffffffffu, mx8, 2));
        float mn0 = fmaxf(m0, mx0), mn8 = fmaxf(m8, mx8);
        float al0 = __expf(m0 - mn0), al8 = __expf(m8 - mn8);
        m0 = mn0; m8 = mn8;
        float sum0 = 0.f, sum8 = 0.f;
#pragma unroll
        for (int nf = 0; nf < 16; nf++) {
            int c = nf * 8 + 2 * t;
            float p0 = __expf(accs[nf][0] - mn0);
            float p1 = __expf(accs[nf][1] - mn0);
            sum0 += p0 + p1;
            *(__half2*)(smc + ATT_P_OFF + sw256o(rg, c)) = __floats2half2_rn(p0, p1);
            float p2 = __expf(accs[nf][2] - mn8);
            float p3 = __expf(accs[nf][3] - mn8);
            sum8 += p2 + p3;
            *(__half2*)(smc + ATT_P_OFF + sw256o(rg + 8, c)) =
                __floats2half2_rn(p2, p3);
        }
        sum0 += __shfl_xor_sync(0xffffffffu, sum0, 1);
        sum0 += __shfl_xor_sync(0xffffffffu, sum0, 2);
        sum8 += __shfl_xor_sync(0xffffffffu, sum8, 1);
        sum8 += __shfl_xor_sync(0xffffffffu, sum8, 2);
        l0 = l0 * al0 + sum0;
        l8 = l8 * al8 + sum8;
#pragma unroll
        for (int nf = 0; nf < 16; nf++) {
            o[nf][0] *= al0; o[nf][1] *= al0;
            o[nf][2] *= al8; o[nf][3] *= al8;
        }

        asm volatile("cp.async.wait_group 1;" ::: "memory");
        __syncthreads();

        // ---- PV: 8 v-chunks (k-dim 128), Ph only ----
        uint32_t vbuf = sb + ATT_V_OFF;
#pragma unroll
        for (int vv = 0; vv < 8; vv++) {
            uint32_t vb[8][4];
#pragma unroll
            for (int ng = 0; ng < 8; ng++) {
                int vr = vv * 16 + ((lane >> 3) & 1) * 8 + (lane & 7);
                ldsm4t(vbuf + sw256o(vr, ng * 16 + acol_f),
                       vb[ng][0], vb[ng][1], vb[ng][2], vb[ng][3]);
            }
            uint32_t ah[4];
            ldsm4(sb + ATT_P_OFF + sw256o(arow_f, vv * 16 + acol_f),
                  ah[0], ah[1], ah[2], ah[3]);
#pragma unroll
            for (int ng = 0; ng < 8; ng++) {
                MMA_F16(o[2 * ng], ah, vb[ng][0], vb[ng][1]);
                MMA_F16(o[2 * ng + 1], ah, vb[ng][2], vb[ng][3]);
            }
        }
        __syncthreads();

        // ---- issue V(i+1) then K(i+2) ----
        if (i + 1 < NT) {
            int tV = (i + 1) * 128;
#pragma unroll
            for (int it = 0; it < 16; it++) {
                int idx = it * 128 + tid;
                int r = idx >> 4, c = (idx & 15) * 8;
                cpa16g(sb + ATT_V_OFF + sw256o(r, c),
                       Vg + (size_t)(tV + r) * KVROWW + c);
            }
        }
        cp_commitg();
        if (i + 2 < NT) {
            int tK = (i + 2) * 128;
            uint32_t kb2 = sb + ATT_K_OFF + (i & 1) * 32768;
#pragma unroll
            for (int it = 0; it < 16; it++) {
                int idx = it * 128 + tid;
                int r = idx >> 4, c = (idx & 15) * 8;
                cpa16g(kb2 + sw256o(r, c), Kg + (size_t)(tK + r) * KVROWW + c);
            }
        }
        cp_commitg();
    }

    // epilogue
    {
        float li0 = __fdiv_rn(1.f, l0);
        float li8 = __fdiv_rn(1.f, l8);
        size_t grow0 = (size_t)(b * S_DIM + q0 + rg) * E_DIM + h * D_DIM;
        size_t grow8 = grow0 + (size_t)8 * E_DIM;
#pragma unroll
        for (int nf = 0; nf < 16; nf++) {
            int c = nf * 8 + 2 * t;
            *(__half2*)&AO[grow0 + c] =
                __floats2half2_rn(o[nf][0] * li0, o[nf][1] * li0);
            *(__half2*)&AO[grow8 + c] =
                __floats2half2_rn(o[nf][2] * li8, o[nf][3] * li8);
        }
    }
}

// ---------------- launcher ----------------------------------------------------
extern "C" void kernel_launch(void* const* d_in, const int* in_sizes, int n_in,
                              void* d_out, int out_size) {
    const float* x  = (const float*)d_in[0];
    const float* rt = (const float*)d_in[1];
    const float* qw = (const float*)d_in[2];
    const float* kw = (const float*)d_in[3];
    const float* vw = (const float*)d_in[4];
    const float* ow = (const float*)d_in[5];
    const float* ob = (const float*)d_in[6];
    float* out = (float*)d_out;

    __half *p_wb, *p_xb, *p_qs, *p_ks, *p_vs, *p_ao, *p_ow, *p_kwf, *p_vwf, *p_rt;
    float *p_as, *p_part, *p_scales;
    cudaGetSymbolAddress((void**)&p_wb, g_wb);
    cudaGetSymbolAddress((void**)&p_xb, g_xb);
    cudaGetSymbolAddress((void**)&p_as, g_as);
    cudaGetSymbolAddress((void**)&p_qs, g_qs);
    cudaGetSymbolAddress((void**)&p_ks, g_ks);
    cudaGetSymbolAddress((void**)&p_vs, g_vs);
    cudaGetSymbolAddress((void**)&p_ao, g_ao);
    cudaGetSymbolAddress((void**)&p_ow, g_ow);
    cudaGetSymbolAddress((void**)&p_kwf, g_kwf);
    cudaGetSymbolAddress((void**)&p_vwf, g_vwf);
    cudaGetSymbolAddress((void**)&p_rt, g_rt);
    cudaGetSymbolAddress((void**)&p_part, g_part);
    cudaGetSymbolAddress((void**)&p_scales, g_scales);

    const int n = E_DIM * E_DIM;

    // 1. scales + fused weight prep
    absmean3<<<dim3(1024, 3), 256>>>(qw, kw, vw, p_part, n);
    scale_finalize<<<3, 256>>>(p_part, p_scales, 1024, 1.f / (float)n);
    wprep3<<<dim3(n / 8 / 256, 3), 256>>>(qw, kw, vw, ow, p_wb, p_ow, p_kwf,
                                          p_vwf, p_scales, n);

    // 2. activation quant + rt convert
    quant_act_k<<<B_DIM * S_DIM + (B_DIM * R_DIM * E_DIM) / 8 / 256, 256>>>(
        x, rt, p_xb, p_rt, p_as);

    // 3+4. QKV projections + rk/rv in ONE launch
    HJobs j1 = {};
    for (int z = 0; z < 6; z++) {
        int w = z >> 1, batch = z & 1;
        j1.A[z] = p_xb + (size_t)batch * S_DIM * E_DIM;
        j1.W[z] = p_wb + (size_t)w * n;
        if (w == 0)
            j1.C[z] = p_qs + (size_t)batch * S_DIM * KVROWW;
        else if (w == 1)
            j1.C[z] = p_ks + (size_t)batch * T_DIM * KVROWW;
        else
            j1.C[z] = p_vs + (size_t)batch * T_DIM * KVROWW;
        j1.rs[z] = p_as + (size_t)batch * S_DIM;
        j1.ws[z] = p_scales + w;
        j1.mode[z] = 2;
        j1.Mz[z] = S_DIM;
    }
    for (int z = 6; z < 10; z++) {
        int w = (z - 6) >> 1, batch = (z - 6) & 1;
        j1.A[z] = p_rt + (size_t)batch * R_DIM * E_DIM;
        j1.W[z] = (w == 0) ? p_kwf : p_vwf;
        j1.C[z] = ((w == 0) ? p_ks : p_vs) +
                  ((size_t)batch * T_DIM + S_DIM) * KVROWW;
        j1.rs[z] = nullptr;
        j1.ws[z] = nullptr;
        j1.mode[z] = 2;
        j1.Mz[z] = R_DIM;
    }
    j1.bias = nullptr;
    cudaFuncSetAttribute(hgemm_nt, cudaFuncAttributeMaxDynamicSharedMemorySize,
                         65536);
    hgemm_nt<<<dim3(16, 16, 10), 256, 65536>>>(j1, S_DIM, E_DIM, E_DIM);

    // 5. fp16 flash attention (BQ=64, 1024 CTAs, 2/SM) -> AO
    cudaFuncSetAttribute(attn_tc, cudaFuncAttributeMaxDynamicSharedMemorySize,
                         ATT_SMEM);
    attn_tc<<<dim3(S_DIM / 64, H_DIM, B_DIM), 128, ATT_SMEM>>>(p_qs, p_ks, p_vs,
                                                               p_ao);

    // 6. output projection: fp16 GEMM over K=2048 + bias
    HJobs j3 = {};
    j3.A[0] = p_ao;
    j3.W[0] = p_ow;
    j3.C[0] = out;
    j3.rs[0] = nullptr;
    j3.ws[0] = nullptr;
    j3.mode[0] = 0;
    j3.Mz[0] = B_DIM * S_DIM;
    j3.bias = ob;
    hgemm_nt<<<dim3(16, 32, 1), 256, 65536>>>(j3, B_DIM * S_DIM, E_DIM, E_DIM);
}